// round 1
// baseline (speedup 1.0000x reference)
#include <cuda_runtime.h>
#include <cuda_bf16.h>
#include <cstdint>

// Problem constants (fixed by the dataset)
#define NN      50000
#define EE      800000
#define IN_DIM  256
#define HEADS   8
#define C1      64
#define HC1     512          // HEADS*C1
#define C2      32
#define OUT_DIM 40
#define NEG_SLOPE 0.2f

// ---------------- scratch (device globals; no cudaMalloc allowed) ------------
__device__ float g_xl1[(size_t)NN * HC1];     // x @ W1
__device__ float g_h1 [(size_t)NN * HC1];     // layer-1 output (relu)
__device__ float g_as1[NN * HEADS];
__device__ float g_ad1[NN * HEADS];
__device__ float g_em1[NN * HEADS];
__device__ float g_dn1[NN * HEADS];
__device__ float g_alpha1[(size_t)EE * HEADS];
__device__ float g_xl2[(size_t)NN * C2];
__device__ float g_as2[NN], g_ad2[NN], g_em2[NN], g_dn2[NN];
__device__ float g_alpha2[EE];
__device__ int   g_deg[NN];
__device__ int   g_rowptr[NN + 1];
__device__ int   g_cursor[NN];
__device__ int   g_csrc[EE];
__device__ int   g_cdst[EE];

__device__ __forceinline__ float lrelu(float x) { return x > 0.f ? x : NEG_SLOPE * x; }

// ---------------- GEMM1: xl1 = x @ W1  (M=NN, K=256, N=512) ------------------
#define BM 128
#define BN 64
#define BK 8
__global__ void sgemm1_kernel(const float* __restrict__ A, const float* __restrict__ B) {
    const int K = IN_DIM, Ncol = HC1;
    __shared__ float As[BK][BM];
    __shared__ float Bs[BK][BN];
    int tid = threadIdx.x;
    int rowBase = blockIdx.x * BM;
    int colBase = blockIdx.y * BN;
    int ty = tid >> 4, tx = tid & 15;           // 16x16 threads, each 8x4 outputs
    int ar = tid >> 1, ak = (tid & 1) * 4;      // A load: 128 rows x 8 k, float4

    float acc[8][4];
#pragma unroll
    for (int i = 0; i < 8; i++)
#pragma unroll
        for (int j = 0; j < 4; j++) acc[i][j] = 0.f;

    for (int k0 = 0; k0 < K; k0 += BK) {
        int grow = rowBase + ar;
        float4 av = make_float4(0.f, 0.f, 0.f, 0.f);
        if (grow < NN) av = *(const float4*)(A + (size_t)grow * K + k0 + ak);
        As[ak + 0][ar] = av.x; As[ak + 1][ar] = av.y;
        As[ak + 2][ar] = av.z; As[ak + 3][ar] = av.w;
        if (tid < 128) {
            int bk = tid >> 4, bc = (tid & 15) * 4;
            float4 bv = *(const float4*)(B + (size_t)(k0 + bk) * Ncol + colBase + bc);
            *(float4*)(&Bs[bk][bc]) = bv;
        }
        __syncthreads();
#pragma unroll
        for (int k = 0; k < BK; k++) {
            float a[8];
#pragma unroll
            for (int i = 0; i < 8; i++) a[i] = As[k][ty * 8 + i];
            float4 b4 = *(const float4*)(&Bs[k][tx * 4]);
            float b[4] = { b4.x, b4.y, b4.z, b4.w };
#pragma unroll
            for (int i = 0; i < 8; i++)
#pragma unroll
                for (int j = 0; j < 4; j++) acc[i][j] = fmaf(a[i], b[j], acc[i][j]);
        }
        __syncthreads();
    }
#pragma unroll
    for (int i = 0; i < 8; i++) {
        int r = rowBase + ty * 8 + i;
        if (r < NN) {
            float4 v = make_float4(acc[i][0], acc[i][1], acc[i][2], acc[i][3]);
            *(float4*)(&g_xl1[(size_t)r * Ncol + colBase + tx * 4]) = v;
        }
    }
}

// ------------- attention coefficients layer 1: warp per (node, head) ---------
__global__ void attn_coef1_kernel(const float* __restrict__ attS, const float* __restrict__ attD) {
    int w = (blockIdx.x * blockDim.x + threadIdx.x) >> 5;
    int lane = threadIdx.x & 31;
    if (w >= NN * HEADS) return;
    int n = w >> 3, h = w & 7;
    size_t base = (size_t)n * HC1 + h * C1;
    float v0 = g_xl1[base + lane];
    float v1 = g_xl1[base + 32 + lane];
    float s = v0 * attS[h * C1 + lane] + v1 * attS[h * C1 + 32 + lane];
    float d = v0 * attD[h * C1 + lane] + v1 * attD[h * C1 + 32 + lane];
#pragma unroll
    for (int off = 16; off; off >>= 1) {
        s += __shfl_down_sync(0xffffffffu, s, off);
        d += __shfl_down_sync(0xffffffffu, d, off);
    }
    if (lane == 0) { g_as1[w] = s; g_ad1[w] = d; }
}

// ---------------------------- CSR construction -------------------------------
__global__ void zero_deg_kernel() {
    int i = blockIdx.x * blockDim.x + threadIdx.x;
    if (i < NN) g_deg[i] = 0;
}
__global__ void hist_kernel(const int* __restrict__ dst) {
    int e = blockIdx.x * blockDim.x + threadIdx.x;
    if (e < EE) atomicAdd(&g_deg[dst[e]], 1);
}
__global__ void scan_kernel() {  // 1 block, 1024 threads
    __shared__ int sh[1024];
    int running = 0;
    for (int base = 0; base < NN; base += 1024) {
        int i = base + threadIdx.x;
        int v = (i < NN) ? g_deg[i] : 0;
        sh[threadIdx.x] = v;
        __syncthreads();
        for (int off = 1; off < 1024; off <<= 1) {
            int t = (threadIdx.x >= off) ? sh[threadIdx.x - off] : 0;
            __syncthreads();
            sh[threadIdx.x] += t;
            __syncthreads();
        }
        int incl = sh[threadIdx.x];
        if (i < NN) {
            int ex = running + incl - v;
            g_rowptr[i] = ex;
            g_cursor[i] = ex;
        }
        int total = sh[1023];
        __syncthreads();
        running += total;
    }
    if (threadIdx.x == 0) g_rowptr[NN] = running;
}
__global__ void scatter_kernel(const int* __restrict__ src, const int* __restrict__ dst) {
    int e = blockIdx.x * blockDim.x + threadIdx.x;
    if (e >= EE) return;
    int d = dst[e];
    int pos = atomicAdd(&g_cursor[d], 1);
    g_csrc[pos] = src[e];
    g_cdst[pos] = d;
}

// ------------- layer-1 softmax stats: thread per (node, head), online --------
__global__ void stats1_kernel() {
    int t = blockIdx.x * blockDim.x + threadIdx.x;
    if (t >= NN * HEADS) return;
    int n = t >> 3, h = t & 7;
    float ad = g_ad1[t];
    float m = lrelu(g_as1[t] + ad);   // self-loop
    float d = 1.f;
    int beg = g_rowptr[n], end = g_rowptr[n + 1];
    for (int j = beg; j < end; j++) {
        int s = g_csrc[j];
        float e = lrelu(g_as1[s * HEADS + h] + ad);
        if (e <= m) d += __expf(e - m);
        else { d = d * __expf(m - e) + 1.f; m = e; }
    }
    g_em1[t] = m; g_dn1[t] = d;
}

// ------------- layer-1 alpha: thread per (csr-edge, head) --------------------
__global__ void alpha1_kernel() {
    int t = blockIdx.x * blockDim.x + threadIdx.x;
    if (t >= EE * HEADS) return;
    int j = t >> 3, h = t & 7;
    int s = g_csrc[j], d = g_cdst[j];
    float e = lrelu(g_as1[s * HEADS + h] + g_ad1[d * HEADS + h]);
    g_alpha1[t] = __expf(e - g_em1[d * HEADS + h]) / (g_dn1[d * HEADS + h] + 1e-16f);
}

// ------------- layer-1 aggregation: warp per (node, head) --------------------
__global__ void agg1_kernel(const float* __restrict__ b1) {
    int w = (blockIdx.x * blockDim.x + threadIdx.x) >> 5;
    int lane = threadIdx.x & 31;
    if (w >= NN * HEADS) return;
    int n = w >> 3, h = w & 7;
    float em = g_em1[w];
    float den = g_dn1[w] + 1e-16f;
    float aself = __expf(lrelu(g_as1[w] + g_ad1[w]) - em) / den;
    size_t base = (size_t)n * HC1 + h * C1;
    float acc0 = aself * g_xl1[base + lane];
    float acc1 = aself * g_xl1[base + 32 + lane];
    int beg = g_rowptr[n], end = g_rowptr[n + 1];
    int j = beg;
    int   s_next = 0; float a_next = 0.f;
    if (j < end) { s_next = g_csrc[j]; a_next = g_alpha1[(size_t)j * HEADS + h]; }
    while (j < end) {
        int s = s_next; float a = a_next;
        int jn = j + 1;
        if (jn < end) { s_next = g_csrc[jn]; a_next = g_alpha1[(size_t)jn * HEADS + h]; }
        size_t sb = (size_t)s * HC1 + h * C1;
        acc0 = fmaf(a, g_xl1[sb + lane], acc0);
        acc1 = fmaf(a, g_xl1[sb + 32 + lane], acc1);
        j = jn;
    }
    g_h1[base + lane]      = fmaxf(acc0 + b1[h * C1 + lane], 0.f);
    g_h1[base + 32 + lane] = fmaxf(acc1 + b1[h * C1 + 32 + lane], 0.f);
}

// ------------- GEMM2: xl2 = h1 @ W2  (K=512, N=32), warp per row -------------
__global__ void gemm2_kernel(const float* __restrict__ W2) {
    int w = (blockIdx.x * blockDim.x + threadIdx.x) >> 5;
    int lane = threadIdx.x & 31;
    if (w >= NN) return;
    const float* hrow = g_h1 + (size_t)w * HC1;
    float a0 = 0.f, a1 = 0.f, a2 = 0.f, a3 = 0.f;
#pragma unroll 8
    for (int k = 0; k < HC1; k += 4) {
        a0 = fmaf(hrow[k + 0], W2[(k + 0) * C2 + lane], a0);
        a1 = fmaf(hrow[k + 1], W2[(k + 1) * C2 + lane], a1);
        a2 = fmaf(hrow[k + 2], W2[(k + 2) * C2 + lane], a2);
        a3 = fmaf(hrow[k + 3], W2[(k + 3) * C2 + lane], a3);
    }
    g_xl2[(size_t)w * C2 + lane] = (a0 + a1) + (a2 + a3);
}

// ------------- layer-2 attention coefficients: warp per node -----------------
__global__ void attn_coef2_kernel(const float* __restrict__ attS, const float* __restrict__ attD) {
    int w = (blockIdx.x * blockDim.x + threadIdx.x) >> 5;
    int lane = threadIdx.x & 31;
    if (w >= NN) return;
    float v = g_xl2[(size_t)w * C2 + lane];
    float s = v * attS[lane];
    float d = v * attD[lane];
#pragma unroll
    for (int off = 16; off; off >>= 1) {
        s += __shfl_down_sync(0xffffffffu, s, off);
        d += __shfl_down_sync(0xffffffffu, d, off);
    }
    if (lane == 0) { g_as2[w] = s; g_ad2[w] = d; }
}

__global__ void stats2_kernel() {
    int n = blockIdx.x * blockDim.x + threadIdx.x;
    if (n >= NN) return;
    float ad = g_ad2[n];
    float m = lrelu(g_as2[n] + ad);
    float d = 1.f;
    int beg = g_rowptr[n], end = g_rowptr[n + 1];
    for (int j = beg; j < end; j++) {
        int s = g_csrc[j];
        float e = lrelu(g_as2[s] + ad);
        if (e <= m) d += __expf(e - m);
        else { d = d * __expf(m - e) + 1.f; m = e; }
    }
    g_em2[n] = m; g_dn2[n] = d;
}

__global__ void alpha2_kernel() {
    int j = blockIdx.x * blockDim.x + threadIdx.x;
    if (j >= EE) return;
    int s = g_csrc[j], d = g_cdst[j];
    float e = lrelu(g_as2[s] + g_ad2[d]);
    g_alpha2[j] = __expf(e - g_em2[d]) / (g_dn2[d] + 1e-16f);
}

// agg2 writes the embedding (relu) straight into d_out[0 : NN*C2]
__global__ void agg2_kernel(const float* __restrict__ b2, float* __restrict__ out) {
    int w = (blockIdx.x * blockDim.x + threadIdx.x) >> 5;
    int lane = threadIdx.x & 31;
    if (w >= NN) return;
    float em = g_em2[w];
    float den = g_dn2[w] + 1e-16f;
    float aself = __expf(lrelu(g_as2[w] + g_ad2[w]) - em) / den;
    float acc = aself * g_xl2[(size_t)w * C2 + lane];
    int beg = g_rowptr[w], end = g_rowptr[w + 1];
    int j = beg;
    int s_next = 0; float a_next = 0.f;
    if (j < end) { s_next = g_csrc[j]; a_next = g_alpha2[j]; }
    while (j < end) {
        int s = s_next; float a = a_next;
        int jn = j + 1;
        if (jn < end) { s_next = g_csrc[jn]; a_next = g_alpha2[jn]; }
        acc = fmaf(a, g_xl2[(size_t)s * C2 + lane], acc);
        j = jn;
    }
    out[(size_t)w * C2 + lane] = fmaxf(acc + b2[lane], 0.f);
}

// final linear head: logits[n,j] = emb[n,:] @ fcW[:,j] + fcb[j]
__global__ void fc_kernel(const float* __restrict__ fcW, const float* __restrict__ fcb,
                          float* __restrict__ out) {
    int idx = blockIdx.x * blockDim.x + threadIdx.x;
    if (idx >= NN * OUT_DIM) return;
    int n = idx / OUT_DIM;
    int j = idx - n * OUT_DIM;
    const float* e = out + (size_t)n * C2;
    float s = fcb[j];
#pragma unroll
    for (int c = 0; c < C2; c++) s = fmaf(e[c], fcW[c * OUT_DIM + j], s);
    out[(size_t)NN * C2 + idx] = s;
}

// ------------------------------------------------------------------------------
extern "C" void kernel_launch(void* const* d_in, const int* in_sizes, int n_in,
                              void* d_out, int out_size) {
    const float* x     = (const float*)d_in[0];
    const int*   ei    = (const int*)  d_in[1];
    const float* W1    = (const float*)d_in[2];
    const float* attS1 = (const float*)d_in[3];
    const float* attD1 = (const float*)d_in[4];
    const float* b1    = (const float*)d_in[5];
    const float* W2    = (const float*)d_in[6];
    const float* attS2 = (const float*)d_in[7];
    const float* attD2 = (const float*)d_in[8];
    const float* b2    = (const float*)d_in[9];
    const float* fcW   = (const float*)d_in[10];
    const float* fcb   = (const float*)d_in[11];
    float* out = (float*)d_out;

    const int* src = ei;
    const int* dst = ei + EE;

    // CSR build (independent of GEMM1)
    zero_deg_kernel<<<(NN + 255) / 256, 256>>>();
    hist_kernel<<<(EE + 255) / 256, 256>>>(dst);
    scan_kernel<<<1, 1024>>>();
    scatter_kernel<<<(EE + 255) / 256, 256>>>(src, dst);

    // layer 1
    {
        dim3 grid((NN + BM - 1) / BM, HC1 / BN);
        sgemm1_kernel<<<grid, 256>>>(x, W1);
    }
    attn_coef1_kernel<<<(NN * HEADS * 32 + 255) / 256, 256>>>(attS1, attD1);
    stats1_kernel<<<(NN * HEADS + 255) / 256, 256>>>();
    alpha1_kernel<<<(EE * HEADS + 255) / 256, 256>>>();
    agg1_kernel<<<(NN * HEADS * 32 + 255) / 256, 256>>>(b1);

    // layer 2
    gemm2_kernel<<<(NN * 32 + 255) / 256, 256>>>(W2);
    attn_coef2_kernel<<<(NN * 32 + 255) / 256, 256>>>(attS2, attD2);
    stats2_kernel<<<(NN + 255) / 256, 256>>>();
    alpha2_kernel<<<(EE + 255) / 256, 256>>>();
    agg2_kernel<<<(NN * 32 + 255) / 256, 256>>>(b2, out);

    // head
    fc_kernel<<<(NN * OUT_DIM + 255) / 256, 256>>>(fcW, fcb, out);
}

// round 3
// speedup vs baseline: 1.1532x; 1.1532x over previous
#include <cuda_runtime.h>
#include <cuda_bf16.h>
#include <cstdint>

// Problem constants (fixed by the dataset)
#define NN      50000
#define EE      800000
#define IN_DIM  256
#define HEADS   8
#define C1      64
#define HC1     512          // HEADS*C1
#define C2      32
#define OUT_DIM 40
#define NEG_SLOPE 0.2f

// ---------------- scratch (device globals; no cudaMalloc allowed) ------------
__device__ float g_xl1[(size_t)NN * HC1];     // x @ W1
__device__ float g_h1 [(size_t)NN * HC1];     // layer-1 output (relu)
__device__ float g_as1[NN * HEADS];
__device__ float g_ad1[NN * HEADS];
__device__ float g_em1[NN * HEADS];
__device__ float g_dn1[NN * HEADS];
__device__ float g_alpha1[(size_t)EE * HEADS];
__device__ float g_xl2[(size_t)NN * C2];
__device__ float g_as2[NN], g_ad2[NN], g_em2[NN], g_dn2[NN];
__device__ float g_alpha2[EE];
__device__ int   g_deg[NN];
__device__ int   g_rowptr[NN + 1];
__device__ int   g_cursor[NN];
__device__ int   g_csrc[EE];
__device__ int   g_cdst[EE];

__device__ __forceinline__ float lrelu(float x) { return x > 0.f ? x : NEG_SLOPE * x; }

// ========================= PTX helpers (legacy path only) =====================
__device__ __forceinline__ uint32_t smem_u32(const void* p) {
    uint32_t a;
    asm("{ .reg .u64 t; cvta.to.shared.u64 t, %1; cvt.u32.u64 %0, t; }" : "=r"(a) : "l"(p));
    return a;
}
__device__ __forceinline__ void ldsm_x4(uint32_t addr, uint32_t& r0, uint32_t& r1,
                                        uint32_t& r2, uint32_t& r3) {
    asm volatile("ldmatrix.sync.aligned.m8n8.x4.shared.b16 {%0,%1,%2,%3}, [%4];"
                 : "=r"(r0), "=r"(r1), "=r"(r2), "=r"(r3) : "r"(addr));
}
__device__ __forceinline__ void ldsm_x4_trans(uint32_t addr, uint32_t& r0, uint32_t& r1,
                                              uint32_t& r2, uint32_t& r3) {
    asm volatile("ldmatrix.sync.aligned.m8n8.x4.trans.shared.b16 {%0,%1,%2,%3}, [%4];"
                 : "=r"(r0), "=r"(r1), "=r"(r2), "=r"(r3) : "r"(addr));
}
__device__ __forceinline__ void mma16816(float* d, const uint32_t* a, const uint32_t* b) {
    asm volatile(
        "mma.sync.aligned.m16n8k16.row.col.f32.bf16.bf16.f32 "
        "{%0,%1,%2,%3},{%4,%5,%6,%7},{%8,%9},{%0,%1,%2,%3};"
        : "+f"(d[0]), "+f"(d[1]), "+f"(d[2]), "+f"(d[3])
        : "r"(a[0]), "r"(a[1]), "r"(a[2]), "r"(a[3]), "r"(b[0]), "r"(b[1]));
}
__device__ __forceinline__ uint32_t pack2(__nv_bfloat16 x, __nv_bfloat16 y) {
    uint32_t lo = __bfloat16_as_ushort(x);
    uint32_t hi = __bfloat16_as_ushort(y);
    return lo | (hi << 16);
}

// ============ GEMM1: xl1 = x @ W1, bf16 mma.sync 3-split =====================
// CTA tile 128x128, 512 threads (16 warps, warp tile 32x32), K chunk 32.
#define AP 40    // padded halves per A smem row (32 + 8)
#define BP 136   // padded halves per B smem row (128 + 8)

__global__ void __launch_bounds__(512) gemm1_mma_kernel(const float* __restrict__ A,
                                                        const float* __restrict__ B) {
    __shared__ __align__(16) __nv_bfloat16 sAhi[128 * AP];
    __shared__ __align__(16) __nv_bfloat16 sAlo[128 * AP];
    __shared__ __align__(16) __nv_bfloat16 sBhi[32 * BP];
    __shared__ __align__(16) __nv_bfloat16 sBlo[32 * BP];

    const int tid = threadIdx.x;
    const int wid = tid >> 5;
    const int lane = tid & 31;
    const int warpM = (wid >> 2) * 32;   // 4 warp rows
    const int warpN = (wid & 3) * 32;    // 4 warp cols
    const int mBase = blockIdx.x * 128;
    const int nBase = blockIdx.y * 128;

    uint32_t* pAhi = (uint32_t*)sAhi;
    uint32_t* pAlo = (uint32_t*)sAlo;
    uint32_t* pBhi = (uint32_t*)sBhi;
    uint32_t* pBlo = (uint32_t*)sBlo;

    float acc[2][4][4];
#pragma unroll
    for (int mi = 0; mi < 2; mi++)
#pragma unroll
        for (int ni = 0; ni < 4; ni++)
#pragma unroll
            for (int q = 0; q < 4; q++) acc[mi][ni][q] = 0.f;

    for (int ch = 0; ch < 8; ch++) {
        const int k0 = ch * 32;
        // ---- load A tile [128 rows x 32 k], split hi/lo ----
#pragma unroll
        for (int it = 0; it < 2; it++) {
            int i = it * 512 + tid;           // 0..1023
            int r = i >> 3, c4 = (i & 7) * 4;
            float4 v = make_float4(0.f, 0.f, 0.f, 0.f);
            int gr = mBase + r;
            if (gr < NN) v = *(const float4*)(A + (size_t)gr * IN_DIM + k0 + c4);
            __nv_bfloat16 h0 = __float2bfloat16_rn(v.x);
            __nv_bfloat16 h1 = __float2bfloat16_rn(v.y);
            __nv_bfloat16 h2 = __float2bfloat16_rn(v.z);
            __nv_bfloat16 h3 = __float2bfloat16_rn(v.w);
            __nv_bfloat16 l0 = __float2bfloat16_rn(v.x - __bfloat162float(h0));
            __nv_bfloat16 l1 = __float2bfloat16_rn(v.y - __bfloat162float(h1));
            __nv_bfloat16 l2 = __float2bfloat16_rn(v.z - __bfloat162float(h2));
            __nv_bfloat16 l3 = __float2bfloat16_rn(v.w - __bfloat162float(h3));
            int si = (r * AP + c4) >> 1;
            pAhi[si]     = pack2(h0, h1);
            pAhi[si + 1] = pack2(h2, h3);
            pAlo[si]     = pack2(l0, l1);
            pAlo[si + 1] = pack2(l2, l3);
        }
        // ---- load B tile [32 k-rows x 128 n] from W1 (natural [K][N]) ----
#pragma unroll
        for (int it = 0; it < 2; it++) {
            int i = it * 512 + tid;
            int r = i >> 5, c4 = (i & 31) * 4;
            float4 v = *(const float4*)(B + (size_t)(k0 + r) * HC1 + nBase + c4);
            __nv_bfloat16 h0 = __float2bfloat16_rn(v.x);
            __nv_bfloat16 h1 = __float2bfloat16_rn(v.y);
            __nv_bfloat16 h2 = __float2bfloat16_rn(v.z);
            __nv_bfloat16 h3 = __float2bfloat16_rn(v.w);
            __nv_bfloat16 l0 = __float2bfloat16_rn(v.x - __bfloat162float(h0));
            __nv_bfloat16 l1 = __float2bfloat16_rn(v.y - __bfloat162float(h1));
            __nv_bfloat16 l2 = __float2bfloat16_rn(v.z - __bfloat162float(h2));
            __nv_bfloat16 l3 = __float2bfloat16_rn(v.w - __bfloat162float(h3));
            int si = (r * BP + c4) >> 1;
            pBhi[si]     = pack2(h0, h1);
            pBhi[si + 1] = pack2(h2, h3);
            pBlo[si]     = pack2(l0, l1);
            pBlo[si + 1] = pack2(l2, l3);
        }
        __syncthreads();

#pragma unroll
        for (int ks = 0; ks < 2; ks++) {
            // A fragments: per mi, ldmatrix.x4 covers m16 x k16
            uint32_t ah[2][4], al[2][4];
#pragma unroll
            for (int mi = 0; mi < 2; mi++) {
                int row = warpM + mi * 16 + (lane & 15);
                int col = ks * 16 + (lane >> 4) * 8;
                uint32_t ad = smem_u32(&sAhi[row * AP + col]);
                ldsm_x4(ad, ah[mi][0], ah[mi][1], ah[mi][2], ah[mi][3]);
                uint32_t ad2 = smem_u32(&sAlo[row * AP + col]);
                ldsm_x4(ad2, al[mi][0], al[mi][1], al[mi][2], al[mi][3]);
            }
            // B fragments: per n16-pair, ldmatrix.x4.trans covers k16 x n16
            uint32_t bh[4][2], bl[4][2];
#pragma unroll
            for (int np = 0; np < 2; np++) {
                int krow = ks * 16 + (lane & 15);
                int col = warpN + np * 16 + (lane >> 4) * 8;
                uint32_t ad = smem_u32(&sBhi[krow * BP + col]);
                ldsm_x4_trans(ad, bh[np * 2][0], bh[np * 2][1], bh[np * 2 + 1][0], bh[np * 2 + 1][1]);
                uint32_t ad2 = smem_u32(&sBlo[krow * BP + col]);
                ldsm_x4_trans(ad2, bl[np * 2][0], bl[np * 2][1], bl[np * 2 + 1][0], bl[np * 2 + 1][1]);
            }
            // 3-split MMAs: hi*hi + hi*lo + lo*hi
#pragma unroll
            for (int mi = 0; mi < 2; mi++)
#pragma unroll
                for (int ni = 0; ni < 4; ni++) {
                    mma16816(acc[mi][ni], ah[mi], bh[ni]);
                    mma16816(acc[mi][ni], ah[mi], bl[ni]);
                    mma16816(acc[mi][ni], al[mi], bh[ni]);
                }
        }
        __syncthreads();
    }

    // epilogue: c0,c1 -> row=lane/4, cols=(lane%4)*2..+1 ; c2,c3 -> row+8
#pragma unroll
    for (int mi = 0; mi < 2; mi++) {
#pragma unroll
        for (int ni = 0; ni < 4; ni++) {
            int row0 = mBase + warpM + mi * 16 + (lane >> 2);
            int col = nBase + warpN + ni * 8 + (lane & 3) * 2;
            if (row0 < NN) {
                float2 v0 = make_float2(acc[mi][ni][0], acc[mi][ni][1]);
                *(float2*)(&g_xl1[(size_t)row0 * HC1 + col]) = v0;
            }
            int row1 = row0 + 8;
            if (row1 < NN) {
                float2 v1 = make_float2(acc[mi][ni][2], acc[mi][ni][3]);
                *(float2*)(&g_xl1[(size_t)row1 * HC1 + col]) = v1;
            }
        }
    }
}

// ------------- attention coefficients layer 1: warp per (node, head) ---------
__global__ void attn_coef1_kernel(const float* __restrict__ attS, const float* __restrict__ attD) {
    int w = (blockIdx.x * blockDim.x + threadIdx.x) >> 5;
    int lane = threadIdx.x & 31;
    if (w >= NN * HEADS) return;
    int n = w >> 3, h = w & 7;
    size_t base = (size_t)n * HC1 + h * C1;
    float v0 = g_xl1[base + lane];
    float v1 = g_xl1[base + 32 + lane];
    float s = v0 * attS[h * C1 + lane] + v1 * attS[h * C1 + 32 + lane];
    float d = v0 * attD[h * C1 + lane] + v1 * attD[h * C1 + 32 + lane];
#pragma unroll
    for (int off = 16; off; off >>= 1) {
        s += __shfl_down_sync(0xffffffffu, s, off);
        d += __shfl_down_sync(0xffffffffu, d, off);
    }
    if (lane == 0) { g_as1[w] = s; g_ad1[w] = d; }
}

// ---------------------------- CSR construction -------------------------------
__global__ void zero_deg_kernel() {
    int i = blockIdx.x * blockDim.x + threadIdx.x;
    if (i < NN) g_deg[i] = 0;
}
__global__ void hist_kernel(const int* __restrict__ dst) {
    int e = blockIdx.x * blockDim.x + threadIdx.x;
    if (e < EE) atomicAdd(&g_deg[dst[e]], 1);
}
__global__ void scan_kernel() {  // 1 block, 1024 threads
    __shared__ int sh[1024];
    int running = 0;
    for (int base = 0; base < NN; base += 1024) {
        int i = base + threadIdx.x;
        int v = (i < NN) ? g_deg[i] : 0;
        sh[threadIdx.x] = v;
        __syncthreads();
        for (int off = 1; off < 1024; off <<= 1) {
            int t = (threadIdx.x >= off) ? sh[threadIdx.x - off] : 0;
            __syncthreads();
            sh[threadIdx.x] += t;
            __syncthreads();
        }
        int incl = sh[threadIdx.x];
        if (i < NN) {
            int ex = running + incl - v;
            g_rowptr[i] = ex;
            g_cursor[i] = ex;
        }
        int total = sh[1023];
        __syncthreads();
        running += total;
    }
    if (threadIdx.x == 0) g_rowptr[NN] = running;
}
__global__ void scatter_kernel(const int* __restrict__ src, const int* __restrict__ dst) {
    int e = blockIdx.x * blockDim.x + threadIdx.x;
    if (e >= EE) return;
    int d = dst[e];
    int pos = atomicAdd(&g_cursor[d], 1);
    g_csrc[pos] = src[e];
    g_cdst[pos] = d;
}

// ------------- layer-1 softmax stats: thread per (node, head), online --------
__global__ void stats1_kernel() {
    int t = blockIdx.x * blockDim.x + threadIdx.x;
    if (t >= NN * HEADS) return;
    int n = t >> 3, h = t & 7;
    float ad = g_ad1[t];
    float m = lrelu(g_as1[t] + ad);   // self-loop
    float d = 1.f;
    int beg = g_rowptr[n], end = g_rowptr[n + 1];
    for (int j = beg; j < end; j++) {
        int s = g_csrc[j];
        float e = lrelu(g_as1[s * HEADS + h] + ad);
        if (e <= m) d += __expf(e - m);
        else { d = d * __expf(m - e) + 1.f; m = e; }
    }
    g_em1[t] = m; g_dn1[t] = d;
}

// ------------- layer-1 alpha: thread per (csr-edge, head) --------------------
__global__ void alpha1_kernel() {
    int t = blockIdx.x * blockDim.x + threadIdx.x;
    if (t >= EE * HEADS) return;
    int j = t >> 3, h = t & 7;
    int s = g_csrc[j], d = g_cdst[j];
    float e = lrelu(g_as1[s * HEADS + h] + g_ad1[d * HEADS + h]);
    g_alpha1[t] = __expf(e - g_em1[d * HEADS + h]) / (g_dn1[d * HEADS + h] + 1e-16f);
}

// ------------- layer-1 aggregation: warp per (node, head) --------------------
__global__ void agg1_kernel(const float* __restrict__ b1) {
    int w = (blockIdx.x * blockDim.x + threadIdx.x) >> 5;
    int lane = threadIdx.x & 31;
    if (w >= NN * HEADS) return;
    int n = w >> 3, h = w & 7;
    float em = g_em1[w];
    float den = g_dn1[w] + 1e-16f;
    float aself = __expf(lrelu(g_as1[w] + g_ad1[w]) - em) / den;
    size_t base = (size_t)n * HC1 + h * C1;
    float acc0 = aself * g_xl1[base + lane];
    float acc1 = aself * g_xl1[base + 32 + lane];
    int beg = g_rowptr[n], end = g_rowptr[n + 1];
    int j = beg;
    int   s_next = 0; float a_next = 0.f;
    if (j < end) { s_next = g_csrc[j]; a_next = g_alpha1[(size_t)j * HEADS + h]; }
    while (j < end) {
        int s = s_next; float a = a_next;
        int jn = j + 1;
        if (jn < end) { s_next = g_csrc[jn]; a_next = g_alpha1[(size_t)jn * HEADS + h]; }
        size_t sb = (size_t)s * HC1 + h * C1;
        acc0 = fmaf(a, g_xl1[sb + lane], acc0);
        acc1 = fmaf(a, g_xl1[sb + 32 + lane], acc1);
        j = jn;
    }
    g_h1[base + lane]      = fmaxf(acc0 + b1[h * C1 + lane], 0.f);
    g_h1[base + 32 + lane] = fmaxf(acc1 + b1[h * C1 + 32 + lane], 0.f);
}

// ------------- GEMM2: xl2 = h1 @ W2  (K=512, N=32), warp per row -------------
__global__ void gemm2_kernel(const float* __restrict__ W2) {
    int w = (blockIdx.x * blockDim.x + threadIdx.x) >> 5;
    int lane = threadIdx.x & 31;
    if (w >= NN) return;
    const float* hrow = g_h1 + (size_t)w * HC1;
    float a0 = 0.f, a1 = 0.f, a2 = 0.f, a3 = 0.f;
#pragma unroll 8
    for (int k = 0; k < HC1; k += 4) {
        a0 = fmaf(hrow[k + 0], W2[(k + 0) * C2 + lane], a0);
        a1 = fmaf(hrow[k + 1], W2[(k + 1) * C2 + lane], a1);
        a2 = fmaf(hrow[k + 2], W2[(k + 2) * C2 + lane], a2);
        a3 = fmaf(hrow[k + 3], W2[(k + 3) * C2 + lane], a3);
    }
    g_xl2[(size_t)w * C2 + lane] = (a0 + a1) + (a2 + a3);
}

// ------------- layer-2 attention coefficients: warp per node -----------------
__global__ void attn_coef2_kernel(const float* __restrict__ attS, const float* __restrict__ attD) {
    int w = (blockIdx.x * blockDim.x + threadIdx.x) >> 5;
    int lane = threadIdx.x & 31;
    if (w >= NN) return;
    float v = g_xl2[(size_t)w * C2 + lane];
    float s = v * attS[lane];
    float d = v * attD[lane];
#pragma unroll
    for (int off = 16; off; off >>= 1) {
        s += __shfl_down_sync(0xffffffffu, s, off);
        d += __shfl_down_sync(0xffffffffu, d, off);
    }
    if (lane == 0) { g_as2[w] = s; g_ad2[w] = d; }
}

__global__ void stats2_kernel() {
    int n = blockIdx.x * blockDim.x + threadIdx.x;
    if (n >= NN) return;
    float ad = g_ad2[n];
    float m = lrelu(g_as2[n] + ad);
    float d = 1.f;
    int beg = g_rowptr[n], end = g_rowptr[n + 1];
    for (int j = beg; j < end; j++) {
        int s = g_csrc[j];
        float e = lrelu(g_as2[s] + ad);
        if (e <= m) d += __expf(e - m);
        else { d = d * __expf(m - e) + 1.f; m = e; }
    }
    g_em2[n] = m; g_dn2[n] = d;
}

__global__ void alpha2_kernel() {
    int j = blockIdx.x * blockDim.x + threadIdx.x;
    if (j >= EE) return;
    int s = g_csrc[j], d = g_cdst[j];
    float e = lrelu(g_as2[s] + g_ad2[d]);
    g_alpha2[j] = __expf(e - g_em2[d]) / (g_dn2[d] + 1e-16f);
}

// agg2 writes the embedding (relu) straight into d_out[0 : NN*C2]
__global__ void agg2_kernel(const float* __restrict__ b2, float* __restrict__ out) {
    int w = (blockIdx.x * blockDim.x + threadIdx.x) >> 5;
    int lane = threadIdx.x & 31;
    if (w >= NN) return;
    float em = g_em2[w];
    float den = g_dn2[w] + 1e-16f;
    float aself = __expf(lrelu(g_as2[w] + g_ad2[w]) - em) / den;
    float acc = aself * g_xl2[(size_t)w * C2 + lane];
    int beg = g_rowptr[w], end = g_rowptr[w + 1];
    int j = beg;
    int s_next = 0; float a_next = 0.f;
    if (j < end) { s_next = g_csrc[j]; a_next = g_alpha2[j]; }
    while (j < end) {
        int s = s_next; float a = a_next;
        int jn = j + 1;
        if (jn < end) { s_next = g_csrc[jn]; a_next = g_alpha2[jn]; }
        acc = fmaf(a, g_xl2[(size_t)s * C2 + lane], acc);
        j = jn;
    }
    out[(size_t)w * C2 + lane] = fmaxf(acc + b2[lane], 0.f);
}

// final linear head: logits[n,j] = emb[n,:] @ fcW[:,j] + fcb[j]
__global__ void fc_kernel(const float* __restrict__ fcW, const float* __restrict__ fcb,
                          float* __restrict__ out) {
    int idx = blockIdx.x * blockDim.x + threadIdx.x;
    if (idx >= NN * OUT_DIM) return;
    int n = idx / OUT_DIM;
    int j = idx - n * OUT_DIM;
    const float* e = out + (size_t)n * C2;
    float s = fcb[j];
#pragma unroll
    for (int c = 0; c < C2; c++) s = fmaf(e[c], fcW[c * OUT_DIM + j], s);
    out[(size_t)NN * C2 + idx] = s;
}

// ------------------------------------------------------------------------------
extern "C" void kernel_launch(void* const* d_in, const int* in_sizes, int n_in,
                              void* d_out, int out_size) {
    const float* x     = (const float*)d_in[0];
    const int*   ei    = (const int*)  d_in[1];
    const float* W1    = (const float*)d_in[2];
    const float* attS1 = (const float*)d_in[3];
    const float* attD1 = (const float*)d_in[4];
    const float* b1    = (const float*)d_in[5];
    const float* W2    = (const float*)d_in[6];
    const float* attS2 = (const float*)d_in[7];
    const float* attD2 = (const float*)d_in[8];
    const float* b2    = (const float*)d_in[9];
    const float* fcW   = (const float*)d_in[10];
    const float* fcb   = (const float*)d_in[11];
    float* out = (float*)d_out;

    const int* src = ei;
    const int* dst = ei + EE;

    // CSR build (independent of GEMM1)
    zero_deg_kernel<<<(NN + 255) / 256, 256>>>();
    hist_kernel<<<(EE + 255) / 256, 256>>>(dst);
    scan_kernel<<<1, 1024>>>();
    scatter_kernel<<<(EE + 255) / 256, 256>>>(src, dst);

    // layer 1 GEMM on tensor cores (bf16 mma.sync, 3-way split)
    {
        dim3 grid((NN + 127) / 128, HC1 / 128);
        gemm1_mma_kernel<<<grid, 512>>>(x, W1);
    }
    attn_coef1_kernel<<<(NN * HEADS * 32 + 255) / 256, 256>>>(attS1, attD1);
    stats1_kernel<<<(NN * HEADS + 255) / 256, 256>>>();
    alpha1_kernel<<<(EE * HEADS + 255) / 256, 256>>>();
    agg1_kernel<<<(NN * HEADS * 32 + 255) / 256, 256>>>(b1);

    // layer 2
    gemm2_kernel<<<(NN * 32 + 255) / 256, 256>>>(W2);
    attn_coef2_kernel<<<(NN * 32 + 255) / 256, 256>>>(attS2, attD2);
    stats2_kernel<<<(NN + 255) / 256, 256>>>();
    alpha2_kernel<<<(EE + 255) / 256, 256>>>();
    agg2_kernel<<<(NN * 32 + 255) / 256, 256>>>(b2, out);

    // head
    fc_kernel<<<(NN * OUT_DIM + 255) / 256, 256>>>(fcW, fcb, out);
}

// round 4
// speedup vs baseline: 1.3044x; 1.1311x over previous
#include <cuda_runtime.h>
#include <cuda_bf16.h>
#include <cstdint>

// Problem constants (fixed by the dataset)
#define NN      50000
#define EE      800000
#define IN_DIM  256
#define HEADS   8
#define C1      64
#define HC1     512          // HEADS*C1
#define C2      32
#define OUT_DIM 40
#define NEG_SLOPE 0.2f

// ---------------- scratch (device globals; no cudaMalloc allowed) ------------
__device__ float g_xl1[(size_t)NN * HC1];     // x @ W1
__device__ float g_h1 [(size_t)NN * HC1];     // layer-1 output (relu)
__device__ __nv_bfloat16 g_xhi[(size_t)NN * IN_DIM];
__device__ __nv_bfloat16 g_xlo[(size_t)NN * IN_DIM];
__device__ __nv_bfloat16 g_whi[(size_t)IN_DIM * HC1];
__device__ __nv_bfloat16 g_wlo[(size_t)IN_DIM * HC1];
__device__ float g_as1[NN * HEADS];
__device__ float g_ad1[NN * HEADS];
__device__ float g_dn1[NN * HEADS];
__device__ float g_p1[(size_t)EE * HEADS];    // exp(e) per (csr-edge, head)
__device__ float g_xl2[(size_t)NN * C2];
__device__ float g_as2[NN], g_ad2[NN], g_dn2[NN];
__device__ float g_p2[EE];
__device__ int   g_deg[NN];
__device__ int   g_rowptr[NN + 1];
__device__ int   g_cursor[NN];
__device__ int   g_csrc[EE];

__device__ __forceinline__ float lrelu(float x) { return x > 0.f ? x : NEG_SLOPE * x; }

// ========================= PTX helpers =========================
__device__ __forceinline__ uint32_t smem_u32(const void* p) {
    uint32_t a;
    asm("{ .reg .u64 t; cvta.to.shared.u64 t, %1; cvt.u32.u64 %0, t; }" : "=r"(a) : "l"(p));
    return a;
}
__device__ __forceinline__ void ldsm_x4(uint32_t addr, uint32_t& r0, uint32_t& r1,
                                        uint32_t& r2, uint32_t& r3) {
    asm volatile("ldmatrix.sync.aligned.m8n8.x4.shared.b16 {%0,%1,%2,%3}, [%4];"
                 : "=r"(r0), "=r"(r1), "=r"(r2), "=r"(r3) : "r"(addr));
}
__device__ __forceinline__ void ldsm_x4_trans(uint32_t addr, uint32_t& r0, uint32_t& r1,
                                              uint32_t& r2, uint32_t& r3) {
    asm volatile("ldmatrix.sync.aligned.m8n8.x4.trans.shared.b16 {%0,%1,%2,%3}, [%4];"
                 : "=r"(r0), "=r"(r1), "=r"(r2), "=r"(r3) : "r"(addr));
}
__device__ __forceinline__ void mma16816(float* d, const uint32_t* a, const uint32_t* b) {
    asm volatile(
        "mma.sync.aligned.m16n8k16.row.col.f32.bf16.bf16.f32 "
        "{%0,%1,%2,%3},{%4,%5,%6,%7},{%8,%9},{%0,%1,%2,%3};"
        : "+f"(d[0]), "+f"(d[1]), "+f"(d[2]), "+f"(d[3])
        : "r"(a[0]), "r"(a[1]), "r"(a[2]), "r"(a[3]), "r"(b[0]), "r"(b[1]));
}
__device__ __forceinline__ uint32_t pack2(__nv_bfloat16 x, __nv_bfloat16 y) {
    uint32_t lo = __bfloat16_as_ushort(x);
    uint32_t hi = __bfloat16_as_ushort(y);
    return lo | (hi << 16);
}
__device__ __forceinline__ void cp16(uint32_t dst, const void* src, uint32_t sz) {
    asm volatile("cp.async.cg.shared.global [%0], [%1], 16, %2;"
                 :: "r"(dst), "l"(src), "r"(sz) : "memory");
}

// ===================== split: fp32 -> bf16 hi/lo ==============================
__global__ void split_x_kernel(const float* __restrict__ x) {
    int i = blockIdx.x * blockDim.x + threadIdx.x;
    if (i >= NN * IN_DIM / 4) return;
    float4 v = ((const float4*)x)[i];
    __nv_bfloat16 h0 = __float2bfloat16_rn(v.x);
    __nv_bfloat16 h1 = __float2bfloat16_rn(v.y);
    __nv_bfloat16 h2 = __float2bfloat16_rn(v.z);
    __nv_bfloat16 h3 = __float2bfloat16_rn(v.w);
    uint2 hv, lv;
    hv.x = pack2(h0, h1); hv.y = pack2(h2, h3);
    lv.x = pack2(__float2bfloat16_rn(v.x - __bfloat162float(h0)),
                 __float2bfloat16_rn(v.y - __bfloat162float(h1)));
    lv.y = pack2(__float2bfloat16_rn(v.z - __bfloat162float(h2)),
                 __float2bfloat16_rn(v.w - __bfloat162float(h3)));
    ((uint2*)g_xhi)[i] = hv;
    ((uint2*)g_xlo)[i] = lv;
}
__global__ void split_w_kernel(const float* __restrict__ w) {
    int i = blockIdx.x * blockDim.x + threadIdx.x;
    if (i >= IN_DIM * HC1 / 4) return;
    float4 v = ((const float4*)w)[i];
    __nv_bfloat16 h0 = __float2bfloat16_rn(v.x);
    __nv_bfloat16 h1 = __float2bfloat16_rn(v.y);
    __nv_bfloat16 h2 = __float2bfloat16_rn(v.z);
    __nv_bfloat16 h3 = __float2bfloat16_rn(v.w);
    uint2 hv, lv;
    hv.x = pack2(h0, h1); hv.y = pack2(h2, h3);
    lv.x = pack2(__float2bfloat16_rn(v.x - __bfloat162float(h0)),
                 __float2bfloat16_rn(v.y - __bfloat162float(h1)));
    lv.y = pack2(__float2bfloat16_rn(v.z - __bfloat162float(h2)),
                 __float2bfloat16_rn(v.w - __bfloat162float(h3)));
    ((uint2*)g_whi)[i] = hv;
    ((uint2*)g_wlo)[i] = lv;
}

// ======== GEMM1: xl1 = x @ W1, bf16 3-split, cp.async double-buffered ========
// CTA 128x128, 256 threads = 8 warps, warp tile 32x64; fused a_src/a_dst epilogue.
#define ASTR 40     // bf16 per A smem row (32 + 8 pad) -> 80B rows (16B-aligned)
#define BSTR 136    // bf16 per B smem row (128 + 8 pad) -> 272B rows
#define OFF_AHI 0
#define OFF_ALO 10240
#define OFF_BHI 20480
#define OFF_BLO 29184
#define STAGE   37888
#define GEMM1_SMEM (2 * STAGE)

__global__ void __launch_bounds__(256) gemm1_mma_kernel(const float* __restrict__ attS1,
                                                        const float* __restrict__ attD1) {
    extern __shared__ __align__(16) char smem[];
    const uint32_t sbase = smem_u32(smem);
    const int tid = threadIdx.x, wid = tid >> 5, lane = tid & 31;
    const int warpM = (wid & 3) * 32;
    const int warpN = (wid >> 2) * 64;
    const int mBase = blockIdx.x * 128;
    const int nBase = blockIdx.y * 128;

    float acc[2][8][4];
#pragma unroll
    for (int mi = 0; mi < 2; mi++)
#pragma unroll
        for (int ni = 0; ni < 8; ni++)
#pragma unroll
            for (int q = 0; q < 4; q++) acc[mi][ni][q] = 0.f;

    // ---- stage loader ----
    auto load_stage = [&](int ch, int buf) {
        const int k0 = ch * 32;
        const uint32_t sb = sbase + buf * STAGE;
#pragma unroll
        for (int it = 0; it < 2; it++) {
            int chunk = it * 256 + tid;          // 512 chunks of 16B for A
            int r = chunk >> 2, c = (chunk & 3) * 8;
            int gr = mBase + r;
            uint32_t sz = (gr < NN) ? 16u : 0u;
            int grc = gr < NN ? gr : NN - 1;
            uint32_t so = (uint32_t)(r * ASTR + c) * 2;
            cp16(sb + OFF_AHI + so, &g_xhi[(size_t)grc * IN_DIM + k0 + c], sz);
            cp16(sb + OFF_ALO + so, &g_xlo[(size_t)grc * IN_DIM + k0 + c], sz);
        }
#pragma unroll
        for (int it = 0; it < 2; it++) {
            int chunk = it * 256 + tid;          // 512 chunks of 16B for B
            int r = chunk >> 4, c = (chunk & 15) * 8;
            uint32_t so = (uint32_t)(r * BSTR + c) * 2;
            cp16(sb + OFF_BHI + so, &g_whi[(size_t)(k0 + r) * HC1 + nBase + c], 16);
            cp16(sb + OFF_BLO + so, &g_wlo[(size_t)(k0 + r) * HC1 + nBase + c], 16);
        }
        asm volatile("cp.async.commit_group;" ::: "memory");
    };

    load_stage(0, 0);
    for (int ch = 0; ch < 8; ch++) {
        const int buf = ch & 1;
        if (ch + 1 < 8) {
            load_stage(ch + 1, buf ^ 1);
            asm volatile("cp.async.wait_group 1;" ::: "memory");
        } else {
            asm volatile("cp.async.wait_group 0;" ::: "memory");
        }
        __syncthreads();
        const uint32_t sb = sbase + buf * STAGE;
#pragma unroll
        for (int ks = 0; ks < 2; ks++) {
            uint32_t ah[2][4], al[2][4];
#pragma unroll
            for (int mi = 0; mi < 2; mi++) {
                int row = warpM + mi * 16 + (lane & 15);
                int col = ks * 16 + (lane >> 4) * 8;
                uint32_t off = (uint32_t)(row * ASTR + col) * 2;
                ldsm_x4(sb + OFF_AHI + off, ah[mi][0], ah[mi][1], ah[mi][2], ah[mi][3]);
                ldsm_x4(sb + OFF_ALO + off, al[mi][0], al[mi][1], al[mi][2], al[mi][3]);
            }
            uint32_t bh[8][2], bl[8][2];
#pragma unroll
            for (int np = 0; np < 4; np++) {
                int krow = ks * 16 + (lane & 15);
                int col = warpN + np * 16 + (lane >> 4) * 8;
                uint32_t off = (uint32_t)(krow * BSTR + col) * 2;
                ldsm_x4_trans(sb + OFF_BHI + off, bh[np * 2][0], bh[np * 2][1],
                              bh[np * 2 + 1][0], bh[np * 2 + 1][1]);
                ldsm_x4_trans(sb + OFF_BLO + off, bl[np * 2][0], bl[np * 2][1],
                              bl[np * 2 + 1][0], bl[np * 2 + 1][1]);
            }
#pragma unroll
            for (int mi = 0; mi < 2; mi++)
#pragma unroll
                for (int ni = 0; ni < 8; ni++) {
                    mma16816(acc[mi][ni], ah[mi], bh[ni]);
                    mma16816(acc[mi][ni], ah[mi], bl[ni]);
                    mma16816(acc[mi][ni], al[mi], bh[ni]);
                }
        }
        __syncthreads();
    }

    // ---- epilogue 1: store xl1 ----
#pragma unroll
    for (int mi = 0; mi < 2; mi++) {
#pragma unroll
        for (int ni = 0; ni < 8; ni++) {
            int row0 = mBase + warpM + mi * 16 + (lane >> 2);
            int col = nBase + warpN + ni * 8 + (lane & 3) * 2;
            if (row0 < NN)
                *(float2*)(&g_xl1[(size_t)row0 * HC1 + col]) =
                    make_float2(acc[mi][ni][0], acc[mi][ni][1]);
            int row1 = row0 + 8;
            if (row1 < NN)
                *(float2*)(&g_xl1[(size_t)row1 * HC1 + col]) =
                    make_float2(acc[mi][ni][2], acc[mi][ni][3]);
        }
    }

    // ---- epilogue 2: fused a_src / a_dst (warp owns one complete head) ----
    {
        const int h = blockIdx.y * 2 + (wid >> 2);
        float sS[8][2], sD[8][2];
        int cb = h * C1 + (lane & 3) * 2;
#pragma unroll
        for (int ni = 0; ni < 8; ni++) {
            sS[ni][0] = __ldg(&attS1[cb + ni * 8]);
            sS[ni][1] = __ldg(&attS1[cb + ni * 8 + 1]);
            sD[ni][0] = __ldg(&attD1[cb + ni * 8]);
            sD[ni][1] = __ldg(&attD1[cb + ni * 8 + 1]);
        }
#pragma unroll
        for (int mi = 0; mi < 2; mi++) {
            float rs0 = 0.f, rs1 = 0.f, rd0 = 0.f, rd1 = 0.f;
#pragma unroll
            for (int ni = 0; ni < 8; ni++) {
                rs0 = fmaf(acc[mi][ni][0], sS[ni][0], fmaf(acc[mi][ni][1], sS[ni][1], rs0));
                rd0 = fmaf(acc[mi][ni][0], sD[ni][0], fmaf(acc[mi][ni][1], sD[ni][1], rd0));
                rs1 = fmaf(acc[mi][ni][2], sS[ni][0], fmaf(acc[mi][ni][3], sS[ni][1], rs1));
                rd1 = fmaf(acc[mi][ni][2], sD[ni][0], fmaf(acc[mi][ni][3], sD[ni][1], rd1));
            }
#pragma unroll
            for (int off = 1; off <= 2; off <<= 1) {
                rs0 += __shfl_xor_sync(0xffffffffu, rs0, off);
                rd0 += __shfl_xor_sync(0xffffffffu, rd0, off);
                rs1 += __shfl_xor_sync(0xffffffffu, rs1, off);
                rd1 += __shfl_xor_sync(0xffffffffu, rd1, off);
            }
            if ((lane & 3) == 0) {
                int row0 = mBase + warpM + mi * 16 + (lane >> 2);
                if (row0 < NN) { g_as1[row0 * 8 + h] = rs0; g_ad1[row0 * 8 + h] = rd0; }
                int row1 = row0 + 8;
                if (row1 < NN) { g_as1[row1 * 8 + h] = rs1; g_ad1[row1 * 8 + h] = rd1; }
            }
        }
    }
}

// ---------------------------- CSR construction -------------------------------
__global__ void zero_deg_kernel() {
    int i = blockIdx.x * blockDim.x + threadIdx.x;
    if (i < NN) g_deg[i] = 0;
}
__global__ void hist_kernel(const int* __restrict__ dst) {
    int e = blockIdx.x * blockDim.x + threadIdx.x;
    if (e < EE) atomicAdd(&g_deg[dst[e]], 1);
}
__global__ void scan_kernel() {  // 1 block, 1024 threads
    __shared__ int sh[1024];
    int running = 0;
    for (int base = 0; base < NN; base += 1024) {
        int i = base + threadIdx.x;
        int v = (i < NN) ? g_deg[i] : 0;
        sh[threadIdx.x] = v;
        __syncthreads();
        for (int off = 1; off < 1024; off <<= 1) {
            int t = (threadIdx.x >= off) ? sh[threadIdx.x - off] : 0;
            __syncthreads();
            sh[threadIdx.x] += t;
            __syncthreads();
        }
        int incl = sh[threadIdx.x];
        if (i < NN) {
            int ex = running + incl - v;
            g_rowptr[i] = ex;
            g_cursor[i] = ex;
        }
        int total = sh[1023];
        __syncthreads();
        running += total;
    }
    if (threadIdx.x == 0) g_rowptr[NN] = running;
}
__global__ void scatter_kernel(const int* __restrict__ src, const int* __restrict__ dst) {
    int e = blockIdx.x * blockDim.x + threadIdx.x;
    if (e >= EE) return;
    int d = dst[e];
    int pos = atomicAdd(&g_cursor[d], 1);
    g_csrc[pos] = src[e];
}

// ---- layer-1 softmax: p = exp(e) per (edge, head) + denominator, warp/node ---
__global__ void pexp1_kernel() {
    int w = (blockIdx.x * blockDim.x + threadIdx.x) >> 5;
    int lane = threadIdx.x & 31;
    if (w >= NN) return;
    int h = lane >> 2, e4 = lane & 3;
    float ad = g_ad1[w * 8 + h];
    int beg = g_rowptr[w], end = g_rowptr[w + 1];
    float dacc = 0.f;
    for (int j0 = beg; j0 < end; j0 += 4) {
        int j = j0 + e4;
        bool valid = j < end;
        int s = valid ? g_csrc[j] : 0;
        float e = lrelu(__ldg(&g_as1[s * 8 + h]) + ad);
        float p = valid ? __expf(e) : 0.f;
        if (valid) g_p1[(size_t)j * 8 + h] = p;
        dacc += p;
    }
    dacc += __shfl_xor_sync(0xffffffffu, dacc, 1);
    dacc += __shfl_xor_sync(0xffffffffu, dacc, 2);
    if (e4 == 0) {
        float pself = __expf(lrelu(g_as1[w * 8 + h] + ad));
        g_dn1[w * 8 + h] = dacc + pself;
    }
}

// ---- layer-1 aggregation: warp per node, all heads (16 cols/lane) -----------
__global__ void agg1_kernel(const float* __restrict__ b1) {
    int w = (blockIdx.x * blockDim.x + threadIdx.x) >> 5;
    int lane = threadIdx.x & 31;
    if (w >= NN) return;
    int h = lane >> 2;
    int idx8 = w * 8 + h;
    float ad = g_ad1[idx8], as = g_as1[idx8];
    float inv = 1.f / (g_dn1[idx8] + 1e-16f);
    float pself = __expf(lrelu(as + ad));
    const float4* xr = (const float4*)(g_xl1 + (size_t)w * HC1 + lane * 16);
    float4 a0 = xr[0], a1 = xr[1], a2 = xr[2], a3 = xr[3];
    a0.x *= pself; a0.y *= pself; a0.z *= pself; a0.w *= pself;
    a1.x *= pself; a1.y *= pself; a1.z *= pself; a1.w *= pself;
    a2.x *= pself; a2.y *= pself; a2.z *= pself; a2.w *= pself;
    a3.x *= pself; a3.y *= pself; a3.z *= pself; a3.w *= pself;

    int beg = g_rowptr[w], end = g_rowptr[w + 1];
    int j = beg;
    float4 v0, v1, v2, v3;
    float pc = 0.f;
    if (j < end) {
        int s = g_csrc[j];
        pc = g_p1[(size_t)j * 8 + h];
        const float4* sr = (const float4*)(g_xl1 + (size_t)s * HC1 + lane * 16);
        v0 = sr[0]; v1 = sr[1]; v2 = sr[2]; v3 = sr[3];
    }
    while (j < end) {
        float4 u0 = v0, u1 = v1, u2 = v2, u3 = v3;
        float pp = pc;
        int jn = j + 1;
        if (jn < end) {
            int s = g_csrc[jn];
            pc = g_p1[(size_t)jn * 8 + h];
            const float4* sr = (const float4*)(g_xl1 + (size_t)s * HC1 + lane * 16);
            v0 = sr[0]; v1 = sr[1]; v2 = sr[2]; v3 = sr[3];
        }
        a0.x = fmaf(pp, u0.x, a0.x); a0.y = fmaf(pp, u0.y, a0.y);
        a0.z = fmaf(pp, u0.z, a0.z); a0.w = fmaf(pp, u0.w, a0.w);
        a1.x = fmaf(pp, u1.x, a1.x); a1.y = fmaf(pp, u1.y, a1.y);
        a1.z = fmaf(pp, u1.z, a1.z); a1.w = fmaf(pp, u1.w, a1.w);
        a2.x = fmaf(pp, u2.x, a2.x); a2.y = fmaf(pp, u2.y, a2.y);
        a2.z = fmaf(pp, u2.z, a2.z); a2.w = fmaf(pp, u2.w, a2.w);
        a3.x = fmaf(pp, u3.x, a3.x); a3.y = fmaf(pp, u3.y, a3.y);
        a3.z = fmaf(pp, u3.z, a3.z); a3.w = fmaf(pp, u3.w, a3.w);
        j = jn;
    }
    const float4* bb = (const float4*)(b1 + lane * 16);
    float4 b0 = bb[0], b1v = bb[1], b2v = bb[2], b3v = bb[3];
    float4* hw = (float4*)(g_h1 + (size_t)w * HC1 + lane * 16);
    float4 o;
    o.x = fmaxf(fmaf(a0.x, inv, b0.x), 0.f); o.y = fmaxf(fmaf(a0.y, inv, b0.y), 0.f);
    o.z = fmaxf(fmaf(a0.z, inv, b0.z), 0.f); o.w = fmaxf(fmaf(a0.w, inv, b0.w), 0.f);
    hw[0] = o;
    o.x = fmaxf(fmaf(a1.x, inv, b1v.x), 0.f); o.y = fmaxf(fmaf(a1.y, inv, b1v.y), 0.f);
    o.z = fmaxf(fmaf(a1.z, inv, b1v.z), 0.f); o.w = fmaxf(fmaf(a1.w, inv, b1v.w), 0.f);
    hw[1] = o;
    o.x = fmaxf(fmaf(a2.x, inv, b2v.x), 0.f); o.y = fmaxf(fmaf(a2.y, inv, b2v.y), 0.f);
    o.z = fmaxf(fmaf(a2.z, inv, b2v.z), 0.f); o.w = fmaxf(fmaf(a2.w, inv, b2v.w), 0.f);
    hw[2] = o;
    o.x = fmaxf(fmaf(a3.x, inv, b3v.x), 0.f); o.y = fmaxf(fmaf(a3.y, inv, b3v.y), 0.f);
    o.z = fmaxf(fmaf(a3.z, inv, b3v.z), 0.f); o.w = fmaxf(fmaf(a3.w, inv, b3v.w), 0.f);
    hw[3] = o;
}

// ------------- GEMM2: xl2 = h1 @ W2  (K=512, N=32), warp per row -------------
__global__ void gemm2_kernel(const float* __restrict__ W2) {
    int w = (blockIdx.x * blockDim.x + threadIdx.x) >> 5;
    int lane = threadIdx.x & 31;
    if (w >= NN) return;
    const float* hrow = g_h1 + (size_t)w * HC1;
    float a0 = 0.f, a1 = 0.f, a2 = 0.f, a3 = 0.f;
#pragma unroll 8
    for (int k = 0; k < HC1; k += 4) {
        a0 = fmaf(hrow[k + 0], W2[(k + 0) * C2 + lane], a0);
        a1 = fmaf(hrow[k + 1], W2[(k + 1) * C2 + lane], a1);
        a2 = fmaf(hrow[k + 2], W2[(k + 2) * C2 + lane], a2);
        a3 = fmaf(hrow[k + 3], W2[(k + 3) * C2 + lane], a3);
    }
    g_xl2[(size_t)w * C2 + lane] = (a0 + a1) + (a2 + a3);
}

// ------------- layer-2 attention coefficients: warp per node -----------------
__global__ void attn_coef2_kernel(const float* __restrict__ attS, const float* __restrict__ attD) {
    int w = (blockIdx.x * blockDim.x + threadIdx.x) >> 5;
    int lane = threadIdx.x & 31;
    if (w >= NN) return;
    float v = g_xl2[(size_t)w * C2 + lane];
    float s = v * attS[lane];
    float d = v * attD[lane];
#pragma unroll
    for (int off = 16; off; off >>= 1) {
        s += __shfl_down_sync(0xffffffffu, s, off);
        d += __shfl_down_sync(0xffffffffu, d, off);
    }
    if (lane == 0) { g_as2[w] = s; g_ad2[w] = d; }
}

// ---- layer-2 softmax p + denominator: warp per node --------------------------
__global__ void pexp2_kernel() {
    int w = (blockIdx.x * blockDim.x + threadIdx.x) >> 5;
    int lane = threadIdx.x & 31;
    if (w >= NN) return;
    float ad = g_ad2[w];
    int beg = g_rowptr[w], end = g_rowptr[w + 1];
    float dacc = 0.f;
    for (int j0 = beg; j0 < end; j0 += 32) {
        int j = j0 + lane;
        bool valid = j < end;
        int s = valid ? g_csrc[j] : 0;
        float e = lrelu(__ldg(&g_as2[s]) + ad);
        float p = valid ? __expf(e) : 0.f;
        if (valid) g_p2[j] = p;
        dacc += p;
    }
#pragma unroll
    for (int off = 16; off; off >>= 1) dacc += __shfl_down_sync(0xffffffffu, dacc, off);
    if (lane == 0) g_dn2[w] = dacc + __expf(lrelu(g_as2[w] + ad));
}

// agg2 writes the embedding (relu) straight into d_out[0 : NN*C2]
__global__ void agg2_kernel(const float* __restrict__ b2, float* __restrict__ out) {
    int w = (blockIdx.x * blockDim.x + threadIdx.x) >> 5;
    int lane = threadIdx.x & 31;
    if (w >= NN) return;
    float inv = 1.f / (g_dn2[w] + 1e-16f);
    float pself = __expf(lrelu(g_as2[w] + g_ad2[w]));
    float acc = pself * g_xl2[(size_t)w * C2 + lane];
    int beg = g_rowptr[w], end = g_rowptr[w + 1];
    int j = beg;
    float vc = 0.f, pc = 0.f;
    if (j < end) {
        int s = g_csrc[j];
        pc = g_p2[j];
        vc = g_xl2[(size_t)s * C2 + lane];
    }
    while (j < end) {
        float vv = vc, pp = pc;
        int jn = j + 1;
        if (jn < end) {
            int s = g_csrc[jn];
            pc = g_p2[jn];
            vc = g_xl2[(size_t)s * C2 + lane];
        }
        acc = fmaf(pp, vv, acc);
        j = jn;
    }
    out[(size_t)w * C2 + lane] = fmaxf(fmaf(acc, inv, b2[lane]), 0.f);
}

// final linear head: logits[n,j] = emb[n,:] @ fcW[:,j] + fcb[j]
__global__ void fc_kernel(const float* __restrict__ fcW, const float* __restrict__ fcb,
                          float* __restrict__ out) {
    int idx = blockIdx.x * blockDim.x + threadIdx.x;
    if (idx >= NN * OUT_DIM) return;
    int n = idx / OUT_DIM;
    int j = idx - n * OUT_DIM;
    const float* e = out + (size_t)n * C2;
    float s = fcb[j];
#pragma unroll
    for (int c = 0; c < C2; c++) s = fmaf(e[c], fcW[c * OUT_DIM + j], s);
    out[(size_t)NN * C2 + idx] = s;
}

// ------------------------------------------------------------------------------
extern "C" void kernel_launch(void* const* d_in, const int* in_sizes, int n_in,
                              void* d_out, int out_size) {
    const float* x     = (const float*)d_in[0];
    const int*   ei    = (const int*)  d_in[1];
    const float* W1    = (const float*)d_in[2];
    const float* attS1 = (const float*)d_in[3];
    const float* attD1 = (const float*)d_in[4];
    const float* b1    = (const float*)d_in[5];
    const float* W2    = (const float*)d_in[6];
    const float* attS2 = (const float*)d_in[7];
    const float* attD2 = (const float*)d_in[8];
    const float* b2    = (const float*)d_in[9];
    const float* fcW   = (const float*)d_in[10];
    const float* fcb   = (const float*)d_in[11];
    float* out = (float*)d_out;

    const int* src = ei;
    const int* dst = ei + EE;

    cudaFuncSetAttribute(gemm1_mma_kernel, cudaFuncAttributeMaxDynamicSharedMemorySize,
                         GEMM1_SMEM);

    // split inputs to bf16 hi/lo (feeds GEMM1)
    split_x_kernel<<<(NN * IN_DIM / 4 + 255) / 256, 256>>>(x);
    split_w_kernel<<<(IN_DIM * HC1 / 4 + 255) / 256, 256>>>(W1);

    // CSR build
    zero_deg_kernel<<<(NN + 255) / 256, 256>>>();
    hist_kernel<<<(EE + 255) / 256, 256>>>(dst);
    scan_kernel<<<1, 1024>>>();
    scatter_kernel<<<(EE + 255) / 256, 256>>>(src, dst);

    // layer 1
    {
        dim3 grid((NN + 127) / 128, HC1 / 128);
        gemm1_mma_kernel<<<grid, 256, GEMM1_SMEM>>>(attS1, attD1);
    }
    pexp1_kernel<<<(NN * 32 + 255) / 256, 256>>>();
    agg1_kernel<<<(NN * 32 + 255) / 256, 256>>>(b1);

    // layer 2
    gemm2_kernel<<<(NN * 32 + 255) / 256, 256>>>(W2);
    attn_coef2_kernel<<<(NN * 32 + 255) / 256, 256>>>(attS2, attD2);
    pexp2_kernel<<<(NN * 32 + 255) / 256, 256>>>();
    agg2_kernel<<<(NN * 32 + 255) / 256, 256>>>(b2, out);

    // head
    fc_kernel<<<(NN * OUT_DIM + 255) / 256, 256>>>(fcW, fcb, out);
}

// round 5
// speedup vs baseline: 1.5662x; 1.2007x over previous
#include <cuda_runtime.h>
#include <cuda_bf16.h>
#include <cstdint>

// Problem constants (fixed by the dataset)
#define NN      50000
#define EE      800000
#define IN_DIM  256
#define HEADS   8
#define C1      64
#define HC1     512          // HEADS*C1
#define C2      32
#define OUT_DIM 40
#define NEG_SLOPE 0.2f

#define SCAN_BLOCKS 49       // 49 * 1024 >= NN

// ---------------- scratch (device globals; no cudaMalloc allowed) ------------
__device__ float g_xl1[(size_t)NN * HC1];     // x @ W1
__device__ float g_h1 [(size_t)NN * HC1];     // layer-1 output (relu)
__device__ __nv_bfloat16 g_xhi[(size_t)NN * IN_DIM];
__device__ __nv_bfloat16 g_xlo[(size_t)NN * IN_DIM];
__device__ __nv_bfloat16 g_whi[(size_t)IN_DIM * HC1];
__device__ __nv_bfloat16 g_wlo[(size_t)IN_DIM * HC1];
__device__ float g_as1[NN * HEADS];
__device__ float g_ad1[NN * HEADS];
__device__ float g_xl2[(size_t)NN * C2];
__device__ float g_as2[NN], g_ad2[NN];
__device__ int   g_deg[NN];
__device__ int   g_incl[SCAN_BLOCKS * 1024];
__device__ int   g_bsum[SCAN_BLOCKS];
__device__ int   g_boff[SCAN_BLOCKS];
__device__ int   g_rowptr[NN + 1];
__device__ int   g_cursor[NN];
__device__ int   g_csrc[EE];

__device__ __forceinline__ float lrelu(float x) { return x > 0.f ? x : NEG_SLOPE * x; }

// ========================= PTX helpers =========================
__device__ __forceinline__ uint32_t smem_u32(const void* p) {
    uint32_t a;
    asm("{ .reg .u64 t; cvta.to.shared.u64 t, %1; cvt.u32.u64 %0, t; }" : "=r"(a) : "l"(p));
    return a;
}
__device__ __forceinline__ void ldsm_x4(uint32_t addr, uint32_t& r0, uint32_t& r1,
                                        uint32_t& r2, uint32_t& r3) {
    asm volatile("ldmatrix.sync.aligned.m8n8.x4.shared.b16 {%0,%1,%2,%3}, [%4];"
                 : "=r"(r0), "=r"(r1), "=r"(r2), "=r"(r3) : "r"(addr));
}
__device__ __forceinline__ void ldsm_x4_trans(uint32_t addr, uint32_t& r0, uint32_t& r1,
                                              uint32_t& r2, uint32_t& r3) {
    asm volatile("ldmatrix.sync.aligned.m8n8.x4.trans.shared.b16 {%0,%1,%2,%3}, [%4];"
                 : "=r"(r0), "=r"(r1), "=r"(r2), "=r"(r3) : "r"(addr));
}
__device__ __forceinline__ void mma16816(float* d, const uint32_t* a, const uint32_t* b) {
    asm volatile(
        "mma.sync.aligned.m16n8k16.row.col.f32.bf16.bf16.f32 "
        "{%0,%1,%2,%3},{%4,%5,%6,%7},{%8,%9},{%0,%1,%2,%3};"
        : "+f"(d[0]), "+f"(d[1]), "+f"(d[2]), "+f"(d[3])
        : "r"(a[0]), "r"(a[1]), "r"(a[2]), "r"(a[3]), "r"(b[0]), "r"(b[1]));
}
__device__ __forceinline__ uint32_t pack2(__nv_bfloat16 x, __nv_bfloat16 y) {
    uint32_t lo = __bfloat16_as_ushort(x);
    uint32_t hi = __bfloat16_as_ushort(y);
    return lo | (hi << 16);
}
__device__ __forceinline__ void cp16(uint32_t dst, const void* src, uint32_t sz) {
    asm volatile("cp.async.cg.shared.global [%0], [%1], 16, %2;"
                 :: "r"(dst), "l"(src), "r"(sz) : "memory");
}

// ===================== split: fp32 -> bf16 hi/lo ==============================
__global__ void split_x_kernel(const float* __restrict__ x) {
    int i = blockIdx.x * blockDim.x + threadIdx.x;
    if (i >= NN * IN_DIM / 4) return;
    float4 v = ((const float4*)x)[i];
    __nv_bfloat16 h0 = __float2bfloat16_rn(v.x);
    __nv_bfloat16 h1 = __float2bfloat16_rn(v.y);
    __nv_bfloat16 h2 = __float2bfloat16_rn(v.z);
    __nv_bfloat16 h3 = __float2bfloat16_rn(v.w);
    uint2 hv, lv;
    hv.x = pack2(h0, h1); hv.y = pack2(h2, h3);
    lv.x = pack2(__float2bfloat16_rn(v.x - __bfloat162float(h0)),
                 __float2bfloat16_rn(v.y - __bfloat162float(h1)));
    lv.y = pack2(__float2bfloat16_rn(v.z - __bfloat162float(h2)),
                 __float2bfloat16_rn(v.w - __bfloat162float(h3)));
    ((uint2*)g_xhi)[i] = hv;
    ((uint2*)g_xlo)[i] = lv;
}
__global__ void split_w_kernel(const float* __restrict__ w) {
    int i = blockIdx.x * blockDim.x + threadIdx.x;
    if (i >= IN_DIM * HC1 / 4) return;
    float4 v = ((const float4*)w)[i];
    __nv_bfloat16 h0 = __float2bfloat16_rn(v.x);
    __nv_bfloat16 h1 = __float2bfloat16_rn(v.y);
    __nv_bfloat16 h2 = __float2bfloat16_rn(v.z);
    __nv_bfloat16 h3 = __float2bfloat16_rn(v.w);
    uint2 hv, lv;
    hv.x = pack2(h0, h1); hv.y = pack2(h2, h3);
    lv.x = pack2(__float2bfloat16_rn(v.x - __bfloat162float(h0)),
                 __float2bfloat16_rn(v.y - __bfloat162float(h1)));
    lv.y = pack2(__float2bfloat16_rn(v.z - __bfloat162float(h2)),
                 __float2bfloat16_rn(v.w - __bfloat162float(h3)));
    ((uint2*)g_whi)[i] = hv;
    ((uint2*)g_wlo)[i] = lv;
}

// ======== GEMM1: xl1 = x @ W1, bf16 3-split, cp.async double-buffered ========
#define ASTR 40     // bf16 per A smem row (32 + 8 pad)
#define BSTR 136    // bf16 per B smem row (128 + 8 pad)
#define OFF_AHI 0
#define OFF_ALO 10240
#define OFF_BHI 20480
#define OFF_BLO 29184
#define STAGE   37888
#define GEMM1_SMEM (2 * STAGE)

__global__ void __launch_bounds__(256) gemm1_mma_kernel(const float* __restrict__ attS1,
                                                        const float* __restrict__ attD1) {
    extern __shared__ __align__(16) char smem[];
    const uint32_t sbase = smem_u32(smem);
    const int tid = threadIdx.x, wid = tid >> 5, lane = tid & 31;
    const int warpM = (wid & 3) * 32;
    const int warpN = (wid >> 2) * 64;
    const int mBase = blockIdx.x * 128;
    const int nBase = blockIdx.y * 128;

    float acc[2][8][4];
#pragma unroll
    for (int mi = 0; mi < 2; mi++)
#pragma unroll
        for (int ni = 0; ni < 8; ni++)
#pragma unroll
            for (int q = 0; q < 4; q++) acc[mi][ni][q] = 0.f;

    auto load_stage = [&](int ch, int buf) {
        const int k0 = ch * 32;
        const uint32_t sb = sbase + buf * STAGE;
#pragma unroll
        for (int it = 0; it < 2; it++) {
            int chunk = it * 256 + tid;
            int r = chunk >> 2, c = (chunk & 3) * 8;
            int gr = mBase + r;
            uint32_t sz = (gr < NN) ? 16u : 0u;
            int grc = gr < NN ? gr : NN - 1;
            uint32_t so = (uint32_t)(r * ASTR + c) * 2;
            cp16(sb + OFF_AHI + so, &g_xhi[(size_t)grc * IN_DIM + k0 + c], sz);
            cp16(sb + OFF_ALO + so, &g_xlo[(size_t)grc * IN_DIM + k0 + c], sz);
        }
#pragma unroll
        for (int it = 0; it < 2; it++) {
            int chunk = it * 256 + tid;
            int r = chunk >> 4, c = (chunk & 15) * 8;
            uint32_t so = (uint32_t)(r * BSTR + c) * 2;
            cp16(sb + OFF_BHI + so, &g_whi[(size_t)(k0 + r) * HC1 + nBase + c], 16);
            cp16(sb + OFF_BLO + so, &g_wlo[(size_t)(k0 + r) * HC1 + nBase + c], 16);
        }
        asm volatile("cp.async.commit_group;" ::: "memory");
    };

    load_stage(0, 0);
    for (int ch = 0; ch < 8; ch++) {
        const int buf = ch & 1;
        if (ch + 1 < 8) {
            load_stage(ch + 1, buf ^ 1);
            asm volatile("cp.async.wait_group 1;" ::: "memory");
        } else {
            asm volatile("cp.async.wait_group 0;" ::: "memory");
        }
        __syncthreads();
        const uint32_t sb = sbase + buf * STAGE;
#pragma unroll
        for (int ks = 0; ks < 2; ks++) {
            uint32_t ah[2][4], al[2][4];
#pragma unroll
            for (int mi = 0; mi < 2; mi++) {
                int row = warpM + mi * 16 + (lane & 15);
                int col = ks * 16 + (lane >> 4) * 8;
                uint32_t off = (uint32_t)(row * ASTR + col) * 2;
                ldsm_x4(sb + OFF_AHI + off, ah[mi][0], ah[mi][1], ah[mi][2], ah[mi][3]);
                ldsm_x4(sb + OFF_ALO + off, al[mi][0], al[mi][1], al[mi][2], al[mi][3]);
            }
            uint32_t bh[8][2], bl[8][2];
#pragma unroll
            for (int np = 0; np < 4; np++) {
                int krow = ks * 16 + (lane & 15);
                int col = warpN + np * 16 + (lane >> 4) * 8;
                uint32_t off = (uint32_t)(krow * BSTR + col) * 2;
                ldsm_x4_trans(sb + OFF_BHI + off, bh[np * 2][0], bh[np * 2][1],
                              bh[np * 2 + 1][0], bh[np * 2 + 1][1]);
                ldsm_x4_trans(sb + OFF_BLO + off, bl[np * 2][0], bl[np * 2][1],
                              bl[np * 2 + 1][0], bl[np * 2 + 1][1]);
            }
#pragma unroll
            for (int mi = 0; mi < 2; mi++)
#pragma unroll
                for (int ni = 0; ni < 8; ni++) {
                    mma16816(acc[mi][ni], ah[mi], bh[ni]);
                    mma16816(acc[mi][ni], ah[mi], bl[ni]);
                    mma16816(acc[mi][ni], al[mi], bh[ni]);
                }
        }
        __syncthreads();
    }

    // ---- epilogue 1: store xl1 ----
#pragma unroll
    for (int mi = 0; mi < 2; mi++) {
#pragma unroll
        for (int ni = 0; ni < 8; ni++) {
            int row0 = mBase + warpM + mi * 16 + (lane >> 2);
            int col = nBase + warpN + ni * 8 + (lane & 3) * 2;
            if (row0 < NN)
                *(float2*)(&g_xl1[(size_t)row0 * HC1 + col]) =
                    make_float2(acc[mi][ni][0], acc[mi][ni][1]);
            int row1 = row0 + 8;
            if (row1 < NN)
                *(float2*)(&g_xl1[(size_t)row1 * HC1 + col]) =
                    make_float2(acc[mi][ni][2], acc[mi][ni][3]);
        }
    }

    // ---- epilogue 2: fused a_src / a_dst (warp owns one complete head) ----
    {
        const int h = blockIdx.y * 2 + (wid >> 2);
        float sS[8][2], sD[8][2];
        int cb = h * C1 + (lane & 3) * 2;
#pragma unroll
        for (int ni = 0; ni < 8; ni++) {
            sS[ni][0] = __ldg(&attS1[cb + ni * 8]);
            sS[ni][1] = __ldg(&attS1[cb + ni * 8 + 1]);
            sD[ni][0] = __ldg(&attD1[cb + ni * 8]);
            sD[ni][1] = __ldg(&attD1[cb + ni * 8 + 1]);
        }
#pragma unroll
        for (int mi = 0; mi < 2; mi++) {
            float rs0 = 0.f, rs1 = 0.f, rd0 = 0.f, rd1 = 0.f;
#pragma unroll
            for (int ni = 0; ni < 8; ni++) {
                rs0 = fmaf(acc[mi][ni][0], sS[ni][0], fmaf(acc[mi][ni][1], sS[ni][1], rs0));
                rd0 = fmaf(acc[mi][ni][0], sD[ni][0], fmaf(acc[mi][ni][1], sD[ni][1], rd0));
                rs1 = fmaf(acc[mi][ni][2], sS[ni][0], fmaf(acc[mi][ni][3], sS[ni][1], rs1));
                rd1 = fmaf(acc[mi][ni][2], sD[ni][0], fmaf(acc[mi][ni][3], sD[ni][1], rd1));
            }
#pragma unroll
            for (int off = 1; off <= 2; off <<= 1) {
                rs0 += __shfl_xor_sync(0xffffffffu, rs0, off);
                rd0 += __shfl_xor_sync(0xffffffffu, rd0, off);
                rs1 += __shfl_xor_sync(0xffffffffu, rs1, off);
                rd1 += __shfl_xor_sync(0xffffffffu, rd1, off);
            }
            if ((lane & 3) == 0) {
                int row0 = mBase + warpM + mi * 16 + (lane >> 2);
                if (row0 < NN) { g_as1[row0 * 8 + h] = rs0; g_ad1[row0 * 8 + h] = rd0; }
                int row1 = row0 + 8;
                if (row1 < NN) { g_as1[row1 * 8 + h] = rs1; g_ad1[row1 * 8 + h] = rd1; }
            }
        }
    }
}

// ---------------------------- CSR construction -------------------------------
__global__ void hist_kernel(const int* __restrict__ dst) {
    int e = blockIdx.x * blockDim.x + threadIdx.x;
    if (e < EE) atomicAdd(&g_deg[dst[e]], 1);
}
// parallel scan: blocks of 1024
__global__ void scanA_kernel() {
    __shared__ int sh[1024];
    int i = blockIdx.x * 1024 + threadIdx.x;
    int v = (i < NN) ? g_deg[i] : 0;
    sh[threadIdx.x] = v;
    __syncthreads();
#pragma unroll
    for (int off = 1; off < 1024; off <<= 1) {
        int t = (threadIdx.x >= off) ? sh[threadIdx.x - off] : 0;
        __syncthreads();
        sh[threadIdx.x] += t;
        __syncthreads();
    }
    g_incl[i] = sh[threadIdx.x];
    if (threadIdx.x == 1023) g_bsum[blockIdx.x] = sh[1023];
}
__global__ void scanB_kernel() {   // 1 block, 64 threads
    __shared__ int sh[64];
    int t = threadIdx.x;
    int v = (t < SCAN_BLOCKS) ? g_bsum[t] : 0;
    sh[t] = v;
    __syncthreads();
#pragma unroll
    for (int off = 1; off < 64; off <<= 1) {
        int u = (t >= off) ? sh[t - off] : 0;
        __syncthreads();
        sh[t] += u;
        __syncthreads();
    }
    if (t < SCAN_BLOCKS) g_boff[t] = sh[t] - v;   // exclusive
}
__global__ void scanC_kernel() {
    int i = blockIdx.x * 1024 + threadIdx.x;
    if (i < NN) {
        int ex = g_boff[blockIdx.x] + g_incl[i] - g_deg[i];
        g_rowptr[i] = ex;
        g_cursor[i] = ex;
    }
    if (i == 0) g_rowptr[NN] = EE;
}
__global__ void scatter_kernel(const int* __restrict__ src, const int* __restrict__ dst) {
    int e = blockIdx.x * blockDim.x + threadIdx.x;
    if (e >= EE) return;
    int d = dst[e];
    int pos = atomicAdd(&g_cursor[d], 1);
    g_csrc[pos] = src[e];
}

// ---- layer-1 fused softmax+aggregation: warp per node, all heads ------------
__global__ void agg1_kernel(const float* __restrict__ b1) {
    int w = (blockIdx.x * blockDim.x + threadIdx.x) >> 5;
    int lane = threadIdx.x & 31;
    if (w >= NN) return;
    const int h = lane >> 2;       // head owned by this lane's column slice
    const int e4 = lane & 3;
    const int idx8 = w * 8 + h;
    const float ad = g_ad1[idx8];
    const float pself = __expf(lrelu(g_as1[idx8] + ad));

    const float4* xr = (const float4*)(g_xl1 + (size_t)w * HC1 + lane * 16);
    float4 a0 = xr[0], a1 = xr[1], a2 = xr[2], a3 = xr[3];
    a0.x *= pself; a0.y *= pself; a0.z *= pself; a0.w *= pself;
    a1.x *= pself; a1.y *= pself; a1.z *= pself; a1.w *= pself;
    a2.x *= pself; a2.y *= pself; a2.z *= pself; a2.w *= pself;
    a3.x *= pself; a3.y *= pself; a3.z *= pself; a3.w *= pself;
    float dacc = 0.f;

    const int beg = g_rowptr[w], end = g_rowptr[w + 1];
    for (int j0 = beg; j0 < end; j0 += 4) {
        int j = j0 + e4;
        bool valid = j < end;
        int s_l = valid ? g_csrc[j] : 0;
        float p_l = 0.f;
        if (valid) p_l = __expf(lrelu(__ldg(&g_as1[s_l * 8 + h]) + ad));
        dacc += p_l;
        int cnt = end - j0;
        int qb = lane & 28;
#pragma unroll
        for (int t = 0; t < 4; t++) {
            if (t < cnt) {
                float p = __shfl_sync(0xffffffffu, p_l, qb | t);
                int   s = __shfl_sync(0xffffffffu, s_l, qb | t);
                const float4* sr = (const float4*)(g_xl1 + (size_t)s * HC1 + lane * 16);
                float4 u0 = sr[0], u1 = sr[1], u2 = sr[2], u3 = sr[3];
                a0.x = fmaf(p, u0.x, a0.x); a0.y = fmaf(p, u0.y, a0.y);
                a0.z = fmaf(p, u0.z, a0.z); a0.w = fmaf(p, u0.w, a0.w);
                a1.x = fmaf(p, u1.x, a1.x); a1.y = fmaf(p, u1.y, a1.y);
                a1.z = fmaf(p, u1.z, a1.z); a1.w = fmaf(p, u1.w, a1.w);
                a2.x = fmaf(p, u2.x, a2.x); a2.y = fmaf(p, u2.y, a2.y);
                a2.z = fmaf(p, u2.z, a2.z); a2.w = fmaf(p, u2.w, a2.w);
                a3.x = fmaf(p, u3.x, a3.x); a3.y = fmaf(p, u3.y, a3.y);
                a3.z = fmaf(p, u3.z, a3.z); a3.w = fmaf(p, u3.w, a3.w);
            }
        }
    }
    // denominator: quad-reduce + self
    dacc += __shfl_xor_sync(0xffffffffu, dacc, 1);
    dacc += __shfl_xor_sync(0xffffffffu, dacc, 2);
    float inv = 1.f / (dacc + pself + 1e-16f);

    const float4* bb = (const float4*)(b1 + lane * 16);
    float4 b0 = bb[0], b1v = bb[1], b2v = bb[2], b3v = bb[3];
    float4* hw = (float4*)(g_h1 + (size_t)w * HC1 + lane * 16);
    float4 o;
    o.x = fmaxf(fmaf(a0.x, inv, b0.x), 0.f); o.y = fmaxf(fmaf(a0.y, inv, b0.y), 0.f);
    o.z = fmaxf(fmaf(a0.z, inv, b0.z), 0.f); o.w = fmaxf(fmaf(a0.w, inv, b0.w), 0.f);
    hw[0] = o;
    o.x = fmaxf(fmaf(a1.x, inv, b1v.x), 0.f); o.y = fmaxf(fmaf(a1.y, inv, b1v.y), 0.f);
    o.z = fmaxf(fmaf(a1.z, inv, b1v.z), 0.f); o.w = fmaxf(fmaf(a1.w, inv, b1v.w), 0.f);
    hw[1] = o;
    o.x = fmaxf(fmaf(a2.x, inv, b2v.x), 0.f); o.y = fmaxf(fmaf(a2.y, inv, b2v.y), 0.f);
    o.z = fmaxf(fmaf(a2.z, inv, b2v.z), 0.f); o.w = fmaxf(fmaf(a2.w, inv, b2v.w), 0.f);
    hw[2] = o;
    o.x = fmaxf(fmaf(a3.x, inv, b3v.x), 0.f); o.y = fmaxf(fmaf(a3.y, inv, b3v.y), 0.f);
    o.z = fmaxf(fmaf(a3.z, inv, b3v.z), 0.f); o.w = fmaxf(fmaf(a3.w, inv, b3v.w), 0.f);
    hw[3] = o;
}

// ---- GEMM2 + fused layer-2 attention coefficients: warp per row -------------
__global__ void gemm2_kernel(const float* __restrict__ W2,
                             const float* __restrict__ attS2,
                             const float* __restrict__ attD2) {
    int w = (blockIdx.x * blockDim.x + threadIdx.x) >> 5;
    int lane = threadIdx.x & 31;
    if (w >= NN) return;
    const float* hrow = g_h1 + (size_t)w * HC1;
    float a0 = 0.f, a1 = 0.f, a2 = 0.f, a3 = 0.f;
#pragma unroll 8
    for (int k = 0; k < HC1; k += 4) {
        a0 = fmaf(hrow[k + 0], W2[(k + 0) * C2 + lane], a0);
        a1 = fmaf(hrow[k + 1], W2[(k + 1) * C2 + lane], a1);
        a2 = fmaf(hrow[k + 2], W2[(k + 2) * C2 + lane], a2);
        a3 = fmaf(hrow[k + 3], W2[(k + 3) * C2 + lane], a3);
    }
    float val = (a0 + a1) + (a2 + a3);
    g_xl2[(size_t)w * C2 + lane] = val;
    float s = val * __ldg(&attS2[lane]);
    float d = val * __ldg(&attD2[lane]);
#pragma unroll
    for (int off = 16; off; off >>= 1) {
        s += __shfl_down_sync(0xffffffffu, s, off);
        d += __shfl_down_sync(0xffffffffu, d, off);
    }
    if (lane == 0) { g_as2[w] = s; g_ad2[w] = d; }
}

// ---- layer-2 fused softmax+aggregation: warp per node ------------------------
__global__ void agg2_kernel(const float* __restrict__ b2, float* __restrict__ out) {
    int w = (blockIdx.x * blockDim.x + threadIdx.x) >> 5;
    int lane = threadIdx.x & 31;
    if (w >= NN) return;
    float ad = g_ad2[w];
    float pself = __expf(lrelu(g_as2[w] + ad));
    float acc = pself * g_xl2[(size_t)w * C2 + lane];
    float dacc = 0.f;
    int beg = g_rowptr[w], end = g_rowptr[w + 1];
    for (int j0 = beg; j0 < end; j0 += 32) {
        int j = j0 + lane;
        bool valid = j < end;
        int s_l = valid ? g_csrc[j] : 0;
        float p_l = 0.f;
        if (valid) p_l = __expf(lrelu(__ldg(&g_as2[s_l]) + ad));
        dacc += p_l;
        int cnt = end - j0;
        if (cnt > 32) cnt = 32;
        for (int t = 0; t < cnt; t++) {
            float p = __shfl_sync(0xffffffffu, p_l, t);
            int   s = __shfl_sync(0xffffffffu, s_l, t);
            acc = fmaf(p, g_xl2[(size_t)s * C2 + lane], acc);
        }
    }
#pragma unroll
    for (int off = 16; off; off >>= 1) dacc += __shfl_xor_sync(0xffffffffu, dacc, off);
    float inv = 1.f / (dacc + pself + 1e-16f);
    out[(size_t)w * C2 + lane] = fmaxf(fmaf(acc, inv, b2[lane]), 0.f);
}

// final linear head: logits[n,j] = emb[n,:] @ fcW[:,j] + fcb[j]
__global__ void fc_kernel(const float* __restrict__ fcW, const float* __restrict__ fcb,
                          float* __restrict__ out) {
    int idx = blockIdx.x * blockDim.x + threadIdx.x;
    if (idx >= NN * OUT_DIM) return;
    int n = idx / OUT_DIM;
    int j = idx - n * OUT_DIM;
    const float* e = out + (size_t)n * C2;
    float s = fcb[j];
#pragma unroll
    for (int c = 0; c < C2; c++) s = fmaf(e[c], fcW[c * OUT_DIM + j], s);
    out[(size_t)NN * C2 + idx] = s;
}

// ------------------------------------------------------------------------------
extern "C" void kernel_launch(void* const* d_in, const int* in_sizes, int n_in,
                              void* d_out, int out_size) {
    const float* x     = (const float*)d_in[0];
    const int*   ei    = (const int*)  d_in[1];
    const float* W1    = (const float*)d_in[2];
    const float* attS1 = (const float*)d_in[3];
    const float* attD1 = (const float*)d_in[4];
    const float* b1    = (const float*)d_in[5];
    const float* W2    = (const float*)d_in[6];
    const float* attS2 = (const float*)d_in[7];
    const float* attD2 = (const float*)d_in[8];
    const float* b2    = (const float*)d_in[9];
    const float* fcW   = (const float*)d_in[10];
    const float* fcb   = (const float*)d_in[11];
    float* out = (float*)d_out;

    const int* src = ei;
    const int* dst = ei + EE;

    cudaFuncSetAttribute(gemm1_mma_kernel, cudaFuncAttributeMaxDynamicSharedMemorySize,
                         GEMM1_SMEM);

    // split inputs to bf16 hi/lo (feeds GEMM1)
    split_x_kernel<<<(NN * IN_DIM / 4 + 255) / 256, 256>>>(x);
    split_w_kernel<<<(IN_DIM * HC1 / 4 + 255) / 256, 256>>>(W1);

    // CSR build
    void* degp = nullptr;
    cudaGetSymbolAddress(&degp, g_deg);
    cudaMemsetAsync(degp, 0, NN * sizeof(int));
    hist_kernel<<<(EE + 255) / 256, 256>>>(dst);
    scanA_kernel<<<SCAN_BLOCKS, 1024>>>();
    scanB_kernel<<<1, 64>>>();
    scanC_kernel<<<SCAN_BLOCKS, 1024>>>();
    scatter_kernel<<<(EE + 255) / 256, 256>>>(src, dst);

    // layer 1
    {
        dim3 grid((NN + 127) / 128, HC1 / 128);
        gemm1_mma_kernel<<<grid, 256, GEMM1_SMEM>>>(attS1, attD1);
    }
    agg1_kernel<<<(NN * 32 + 255) / 256, 256>>>(b1);

    // layer 2
    gemm2_kernel<<<(NN * 32 + 255) / 256, 256>>>(W2, attS2, attD2);
    agg2_kernel<<<(NN * 32 + 255) / 256, 256>>>(b2, out);

    // head
    fc_kernel<<<(NN * OUT_DIM + 255) / 256, 256>>>(fcW, fcb, out);
}

// round 6
// speedup vs baseline: 2.0957x; 1.3381x over previous
#include <cuda_runtime.h>
#include <cuda_bf16.h>
#include <cstdint>

// Problem constants (fixed by the dataset)
#define NN      50000
#define EE      800000
#define IN_DIM  256
#define HEADS   8
#define C1      64
#define HC1     512          // HEADS*C1
#define C2      32
#define OUT_DIM 40
#define NEG_SLOPE 0.2f

#define SCAN_BLOCKS 49       // 49 * 1024 >= NN

// ---------------- scratch (device globals; no cudaMalloc allowed) ------------
__device__ float g_xl1[(size_t)NN * HC1];     // x @ W1
__device__ float g_h1 [(size_t)NN * HC1];     // layer-1 output (relu)
__device__ __nv_bfloat16 g_xhi[(size_t)NN * IN_DIM];
__device__ __nv_bfloat16 g_xlo[(size_t)NN * IN_DIM];
__device__ __nv_bfloat16 g_whi[(size_t)IN_DIM * HC1];
__device__ __nv_bfloat16 g_wlo[(size_t)IN_DIM * HC1];
__device__ __nv_bfloat16 g_w2hi[HC1 * C2];
__device__ __nv_bfloat16 g_w2lo[HC1 * C2];
__device__ float g_as1[NN * HEADS];
__device__ float g_ad1[NN * HEADS];
__device__ float g_xl2[(size_t)NN * C2];
__device__ float g_as2[NN], g_ad2[NN];
__device__ int   g_deg[NN];
__device__ int   g_incl[SCAN_BLOCKS * 1024];
__device__ int   g_bsum[SCAN_BLOCKS];
__device__ int   g_boff[SCAN_BLOCKS];
__device__ int   g_rowptr[NN + 1];
__device__ int   g_cursor[NN];
__device__ int   g_csrc[EE];

__device__ __forceinline__ float lrelu(float x) { return x > 0.f ? x : NEG_SLOPE * x; }

// ========================= PTX helpers =========================
__device__ __forceinline__ uint32_t smem_u32(const void* p) {
    uint32_t a;
    asm("{ .reg .u64 t; cvta.to.shared.u64 t, %1; cvt.u32.u64 %0, t; }" : "=r"(a) : "l"(p));
    return a;
}
__device__ __forceinline__ void ldsm_x4(uint32_t addr, uint32_t& r0, uint32_t& r1,
                                        uint32_t& r2, uint32_t& r3) {
    asm volatile("ldmatrix.sync.aligned.m8n8.x4.shared.b16 {%0,%1,%2,%3}, [%4];"
                 : "=r"(r0), "=r"(r1), "=r"(r2), "=r"(r3) : "r"(addr));
}
__device__ __forceinline__ void ldsm_x4_trans(uint32_t addr, uint32_t& r0, uint32_t& r1,
                                              uint32_t& r2, uint32_t& r3) {
    asm volatile("ldmatrix.sync.aligned.m8n8.x4.trans.shared.b16 {%0,%1,%2,%3}, [%4];"
                 : "=r"(r0), "=r"(r1), "=r"(r2), "=r"(r3) : "r"(addr));
}
__device__ __forceinline__ void mma16816(float* d, const uint32_t* a, const uint32_t* b) {
    asm volatile(
        "mma.sync.aligned.m16n8k16.row.col.f32.bf16.bf16.f32 "
        "{%0,%1,%2,%3},{%4,%5,%6,%7},{%8,%9},{%0,%1,%2,%3};"
        : "+f"(d[0]), "+f"(d[1]), "+f"(d[2]), "+f"(d[3])
        : "r"(a[0]), "r"(a[1]), "r"(a[2]), "r"(a[3]), "r"(b[0]), "r"(b[1]));
}
__device__ __forceinline__ uint32_t pack2(__nv_bfloat16 x, __nv_bfloat16 y) {
    uint32_t lo = __bfloat16_as_ushort(x);
    uint32_t hi = __bfloat16_as_ushort(y);
    return lo | (hi << 16);
}
__device__ __forceinline__ void cp16(uint32_t dst, const void* src, uint32_t sz) {
    asm volatile("cp.async.cg.shared.global [%0], [%1], 16, %2;"
                 :: "r"(dst), "l"(src), "r"(sz) : "memory");
}
__device__ __forceinline__ void cvt_store(float4 v, __nv_bfloat16* hi, __nv_bfloat16* lo) {
    __nv_bfloat16 h0 = __float2bfloat16_rn(v.x), h1 = __float2bfloat16_rn(v.y);
    __nv_bfloat16 h2 = __float2bfloat16_rn(v.z), h3 = __float2bfloat16_rn(v.w);
    uint2 hv, lv;
    hv.x = pack2(h0, h1); hv.y = pack2(h2, h3);
    lv.x = pack2(__float2bfloat16_rn(v.x - __bfloat162float(h0)),
                 __float2bfloat16_rn(v.y - __bfloat162float(h1)));
    lv.y = pack2(__float2bfloat16_rn(v.z - __bfloat162float(h2)),
                 __float2bfloat16_rn(v.w - __bfloat162float(h3)));
    *(uint2*)hi = hv; *(uint2*)lo = lv;
}

// ===================== split: fp32 -> bf16 hi/lo ==============================
__global__ void split_x_kernel(const float* __restrict__ x) {
    int i = blockIdx.x * blockDim.x + threadIdx.x;
    if (i >= NN * IN_DIM / 4) return;
    cvt_store(((const float4*)x)[i], g_xhi + i * 4, g_xlo + i * 4);
}
__global__ void split_w_kernel(const float* __restrict__ w) {
    int i = blockIdx.x * blockDim.x + threadIdx.x;
    if (i >= IN_DIM * HC1 / 4) return;
    cvt_store(((const float4*)w)[i], g_whi + i * 4, g_wlo + i * 4);
}
__global__ void split_w2_kernel(const float* __restrict__ w) {
    int i = blockIdx.x * blockDim.x + threadIdx.x;
    if (i >= HC1 * C2 / 4) return;
    cvt_store(((const float4*)w)[i], g_w2hi + i * 4, g_w2lo + i * 4);
}

// ======== GEMM1: xl1 = x @ W1, bf16 3-split, cp.async double-buffered ========
#define ASTR 40     // bf16 per A smem row (32 + 8 pad)
#define BSTR 136    // bf16 per B smem row (128 + 8 pad)
#define OFF_AHI 0
#define OFF_ALO 10240
#define OFF_BHI 20480
#define OFF_BLO 29184
#define STAGE   37888
#define GEMM1_SMEM (2 * STAGE)

__global__ void __launch_bounds__(256) gemm1_mma_kernel(const float* __restrict__ attS1,
                                                        const float* __restrict__ attD1) {
    extern __shared__ __align__(16) char smem[];
    const uint32_t sbase = smem_u32(smem);
    const int tid = threadIdx.x, wid = tid >> 5, lane = tid & 31;
    const int warpM = (wid & 3) * 32;
    const int warpN = (wid >> 2) * 64;
    const int mBase = blockIdx.x * 128;
    const int nBase = blockIdx.y * 128;

    float acc[2][8][4];
#pragma unroll
    for (int mi = 0; mi < 2; mi++)
#pragma unroll
        for (int ni = 0; ni < 8; ni++)
#pragma unroll
            for (int q = 0; q < 4; q++) acc[mi][ni][q] = 0.f;

    auto load_stage = [&](int ch, int buf) {
        const int k0 = ch * 32;
        const uint32_t sb = sbase + buf * STAGE;
#pragma unroll
        for (int it = 0; it < 2; it++) {
            int chunk = it * 256 + tid;
            int r = chunk >> 2, c = (chunk & 3) * 8;
            int gr = mBase + r;
            uint32_t sz = (gr < NN) ? 16u : 0u;
            int grc = gr < NN ? gr : NN - 1;
            uint32_t so = (uint32_t)(r * ASTR + c) * 2;
            cp16(sb + OFF_AHI + so, &g_xhi[(size_t)grc * IN_DIM + k0 + c], sz);
            cp16(sb + OFF_ALO + so, &g_xlo[(size_t)grc * IN_DIM + k0 + c], sz);
        }
#pragma unroll
        for (int it = 0; it < 2; it++) {
            int chunk = it * 256 + tid;
            int r = chunk >> 4, c = (chunk & 15) * 8;
            uint32_t so = (uint32_t)(r * BSTR + c) * 2;
            cp16(sb + OFF_BHI + so, &g_whi[(size_t)(k0 + r) * HC1 + nBase + c], 16);
            cp16(sb + OFF_BLO + so, &g_wlo[(size_t)(k0 + r) * HC1 + nBase + c], 16);
        }
        asm volatile("cp.async.commit_group;" ::: "memory");
    };

    load_stage(0, 0);
    for (int ch = 0; ch < 8; ch++) {
        const int buf = ch & 1;
        if (ch + 1 < 8) {
            load_stage(ch + 1, buf ^ 1);
            asm volatile("cp.async.wait_group 1;" ::: "memory");
        } else {
            asm volatile("cp.async.wait_group 0;" ::: "memory");
        }
        __syncthreads();
        const uint32_t sb = sbase + buf * STAGE;
#pragma unroll
        for (int ks = 0; ks < 2; ks++) {
            uint32_t ah[2][4], al[2][4];
#pragma unroll
            for (int mi = 0; mi < 2; mi++) {
                int row = warpM + mi * 16 + (lane & 15);
                int col = ks * 16 + (lane >> 4) * 8;
                uint32_t off = (uint32_t)(row * ASTR + col) * 2;
                ldsm_x4(sb + OFF_AHI + off, ah[mi][0], ah[mi][1], ah[mi][2], ah[mi][3]);
                ldsm_x4(sb + OFF_ALO + off, al[mi][0], al[mi][1], al[mi][2], al[mi][3]);
            }
            uint32_t bh[8][2], bl[8][2];
#pragma unroll
            for (int np = 0; np < 4; np++) {
                int krow = ks * 16 + (lane & 15);
                int col = warpN + np * 16 + (lane >> 4) * 8;
                uint32_t off = (uint32_t)(krow * BSTR + col) * 2;
                ldsm_x4_trans(sb + OFF_BHI + off, bh[np * 2][0], bh[np * 2][1],
                              bh[np * 2 + 1][0], bh[np * 2 + 1][1]);
                ldsm_x4_trans(sb + OFF_BLO + off, bl[np * 2][0], bl[np * 2][1],
                              bl[np * 2 + 1][0], bl[np * 2 + 1][1]);
            }
#pragma unroll
            for (int mi = 0; mi < 2; mi++)
#pragma unroll
                for (int ni = 0; ni < 8; ni++) {
                    mma16816(acc[mi][ni], ah[mi], bh[ni]);
                    mma16816(acc[mi][ni], ah[mi], bl[ni]);
                    mma16816(acc[mi][ni], al[mi], bh[ni]);
                }
        }
        __syncthreads();
    }

    // ---- epilogue 1: store xl1 ----
#pragma unroll
    for (int mi = 0; mi < 2; mi++) {
#pragma unroll
        for (int ni = 0; ni < 8; ni++) {
            int row0 = mBase + warpM + mi * 16 + (lane >> 2);
            int col = nBase + warpN + ni * 8 + (lane & 3) * 2;
            if (row0 < NN)
                *(float2*)(&g_xl1[(size_t)row0 * HC1 + col]) =
                    make_float2(acc[mi][ni][0], acc[mi][ni][1]);
            int row1 = row0 + 8;
            if (row1 < NN)
                *(float2*)(&g_xl1[(size_t)row1 * HC1 + col]) =
                    make_float2(acc[mi][ni][2], acc[mi][ni][3]);
        }
    }

    // ---- epilogue 2: fused a_src / a_dst (warp owns one complete head) ----
    {
        const int h = blockIdx.y * 2 + (wid >> 2);
        float sS[8][2], sD[8][2];
        int cb = h * C1 + (lane & 3) * 2;
#pragma unroll
        for (int ni = 0; ni < 8; ni++) {
            sS[ni][0] = __ldg(&attS1[cb + ni * 8]);
            sS[ni][1] = __ldg(&attS1[cb + ni * 8 + 1]);
            sD[ni][0] = __ldg(&attD1[cb + ni * 8]);
            sD[ni][1] = __ldg(&attD1[cb + ni * 8 + 1]);
        }
#pragma unroll
        for (int mi = 0; mi < 2; mi++) {
            float rs0 = 0.f, rs1 = 0.f, rd0 = 0.f, rd1 = 0.f;
#pragma unroll
            for (int ni = 0; ni < 8; ni++) {
                rs0 = fmaf(acc[mi][ni][0], sS[ni][0], fmaf(acc[mi][ni][1], sS[ni][1], rs0));
                rd0 = fmaf(acc[mi][ni][0], sD[ni][0], fmaf(acc[mi][ni][1], sD[ni][1], rd0));
                rs1 = fmaf(acc[mi][ni][2], sS[ni][0], fmaf(acc[mi][ni][3], sS[ni][1], rs1));
                rd1 = fmaf(acc[mi][ni][2], sD[ni][0], fmaf(acc[mi][ni][3], sD[ni][1], rd1));
            }
#pragma unroll
            for (int off = 1; off <= 2; off <<= 1) {
                rs0 += __shfl_xor_sync(0xffffffffu, rs0, off);
                rd0 += __shfl_xor_sync(0xffffffffu, rd0, off);
                rs1 += __shfl_xor_sync(0xffffffffu, rs1, off);
                rd1 += __shfl_xor_sync(0xffffffffu, rd1, off);
            }
            if ((lane & 3) == 0) {
                int row0 = mBase + warpM + mi * 16 + (lane >> 2);
                if (row0 < NN) { g_as1[row0 * 8 + h] = rs0; g_ad1[row0 * 8 + h] = rd0; }
                int row1 = row0 + 8;
                if (row1 < NN) { g_as1[row1 * 8 + h] = rs1; g_ad1[row1 * 8 + h] = rd1; }
            }
        }
    }
}

// ---------------------------- CSR construction -------------------------------
__global__ void hist_kernel(const int* __restrict__ dst) {
    int e = blockIdx.x * blockDim.x + threadIdx.x;
    if (e < EE) atomicAdd(&g_deg[dst[e]], 1);
}
__global__ void scanA_kernel() {
    __shared__ int sh[1024];
    int i = blockIdx.x * 1024 + threadIdx.x;
    int v = (i < NN) ? g_deg[i] : 0;
    sh[threadIdx.x] = v;
    __syncthreads();
#pragma unroll
    for (int off = 1; off < 1024; off <<= 1) {
        int t = (threadIdx.x >= off) ? sh[threadIdx.x - off] : 0;
        __syncthreads();
        sh[threadIdx.x] += t;
        __syncthreads();
    }
    g_incl[i] = sh[threadIdx.x];
    if (threadIdx.x == 1023) g_bsum[blockIdx.x] = sh[1023];
}
__global__ void scanB_kernel() {   // 1 block, 64 threads
    __shared__ int sh[64];
    int t = threadIdx.x;
    int v = (t < SCAN_BLOCKS) ? g_bsum[t] : 0;
    sh[t] = v;
    __syncthreads();
#pragma unroll
    for (int off = 1; off < 64; off <<= 1) {
        int u = (t >= off) ? sh[t - off] : 0;
        __syncthreads();
        sh[t] += u;
        __syncthreads();
    }
    if (t < SCAN_BLOCKS) g_boff[t] = sh[t] - v;   // exclusive
}
__global__ void scanC_kernel() {
    int i = blockIdx.x * 1024 + threadIdx.x;
    if (i < NN) {
        int ex = g_boff[blockIdx.x] + g_incl[i] - g_deg[i];
        g_rowptr[i] = ex;
        g_cursor[i] = ex;
    }
    if (i == 0) g_rowptr[NN] = EE;
}
__global__ void scatter_kernel(const int* __restrict__ src, const int* __restrict__ dst) {
    int e = blockIdx.x * blockDim.x + threadIdx.x;
    if (e >= EE) return;
    int d = dst[e];
    int pos = atomicAdd(&g_cursor[d], 1);
    g_csrc[pos] = src[e];
}

// ---- layer-1 fused softmax+aggregation: warp per node, all heads ------------
__global__ void agg1_kernel(const float* __restrict__ b1) {
    int w = (blockIdx.x * blockDim.x + threadIdx.x) >> 5;
    int lane = threadIdx.x & 31;
    if (w >= NN) return;
    const int h = lane >> 2;
    const int e4 = lane & 3;
    const int idx8 = w * 8 + h;
    const float ad = g_ad1[idx8];
    const float pself = __expf(lrelu(g_as1[idx8] + ad));

    const float4* xr = (const float4*)(g_xl1 + (size_t)w * HC1 + lane * 16);
    float4 a0 = xr[0], a1 = xr[1], a2 = xr[2], a3 = xr[3];
    a0.x *= pself; a0.y *= pself; a0.z *= pself; a0.w *= pself;
    a1.x *= pself; a1.y *= pself; a1.z *= pself; a1.w *= pself;
    a2.x *= pself; a2.y *= pself; a2.z *= pself; a2.w *= pself;
    a3.x *= pself; a3.y *= pself; a3.z *= pself; a3.w *= pself;
    float dacc = 0.f;

    const int beg = g_rowptr[w], end = g_rowptr[w + 1];
    for (int j0 = beg; j0 < end; j0 += 4) {
        int j = j0 + e4;
        bool valid = j < end;
        int s_l = valid ? g_csrc[j] : 0;
        float p_l = 0.f;
        if (valid) p_l = __expf(lrelu(__ldg(&g_as1[s_l * 8 + h]) + ad));
        dacc += p_l;
        int cnt = end - j0;
        int qb = lane & 28;
#pragma unroll
        for (int t = 0; t < 4; t++) {
            if (t < cnt) {
                float p = __shfl_sync(0xffffffffu, p_l, qb | t);
                int   s = __shfl_sync(0xffffffffu, s_l, qb | t);
                const float4* sr = (const float4*)(g_xl1 + (size_t)s * HC1 + lane * 16);
                float4 u0 = sr[0], u1 = sr[1], u2 = sr[2], u3 = sr[3];
                a0.x = fmaf(p, u0.x, a0.x); a0.y = fmaf(p, u0.y, a0.y);
                a0.z = fmaf(p, u0.z, a0.z); a0.w = fmaf(p, u0.w, a0.w);
                a1.x = fmaf(p, u1.x, a1.x); a1.y = fmaf(p, u1.y, a1.y);
                a1.z = fmaf(p, u1.z, a1.z); a1.w = fmaf(p, u1.w, a1.w);
                a2.x = fmaf(p, u2.x, a2.x); a2.y = fmaf(p, u2.y, a2.y);
                a2.z = fmaf(p, u2.z, a2.z); a2.w = fmaf(p, u2.w, a2.w);
                a3.x = fmaf(p, u3.x, a3.x); a3.y = fmaf(p, u3.y, a3.y);
                a3.z = fmaf(p, u3.z, a3.z); a3.w = fmaf(p, u3.w, a3.w);
            }
        }
    }
    dacc += __shfl_xor_sync(0xffffffffu, dacc, 1);
    dacc += __shfl_xor_sync(0xffffffffu, dacc, 2);
    float inv = 1.f / (dacc + pself + 1e-16f);

    const float4* bb = (const float4*)(b1 + lane * 16);
    float4 b0 = bb[0], b1v = bb[1], b2v = bb[2], b3v = bb[3];
    float4* hw = (float4*)(g_h1 + (size_t)w * HC1 + lane * 16);
    float4 o;
    o.x = fmaxf(fmaf(a0.x, inv, b0.x), 0.f); o.y = fmaxf(fmaf(a0.y, inv, b0.y), 0.f);
    o.z = fmaxf(fmaf(a0.z, inv, b0.z), 0.f); o.w = fmaxf(fmaf(a0.w, inv, b0.w), 0.f);
    hw[0] = o;
    o.x = fmaxf(fmaf(a1.x, inv, b1v.x), 0.f); o.y = fmaxf(fmaf(a1.y, inv, b1v.y), 0.f);
    o.z = fmaxf(fmaf(a1.z, inv, b1v.z), 0.f); o.w = fmaxf(fmaf(a1.w, inv, b1v.w), 0.f);
    hw[1] = o;
    o.x = fmaxf(fmaf(a2.x, inv, b2v.x), 0.f); o.y = fmaxf(fmaf(a2.y, inv, b2v.y), 0.f);
    o.z = fmaxf(fmaf(a2.z, inv, b2v.z), 0.f); o.w = fmaxf(fmaf(a2.w, inv, b2v.w), 0.f);
    hw[2] = o;
    o.x = fmaxf(fmaf(a3.x, inv, b3v.x), 0.f); o.y = fmaxf(fmaf(a3.y, inv, b3v.y), 0.f);
    o.z = fmaxf(fmaf(a3.z, inv, b3v.z), 0.f); o.w = fmaxf(fmaf(a3.w, inv, b3v.w), 0.f);
    hw[3] = o;
}

// ==== GEMM2 on tensor cores: xl2 = h1 @ W2 (M=NN, K=512, N=32), 3-split ======
// CTA 128 rows, 256 threads = 8 warps (warp tile 16x32), K chunks of 32,
// inline fp32->bf16 hi/lo conversion with register prefetch; fused coef2 epi.
#define A2STR 40
#define B2STR 40
__global__ void __launch_bounds__(256) gemm2_mma_kernel(const float* __restrict__ attS2,
                                                        const float* __restrict__ attD2) {
    __shared__ __align__(16) __nv_bfloat16 sAhi[128 * A2STR], sAlo[128 * A2STR];
    __shared__ __align__(16) __nv_bfloat16 sBhi[32 * B2STR],  sBlo[32 * B2STR];
    const int tid = threadIdx.x, wid = tid >> 5, lane = tid & 31;
    const int mBase = blockIdx.x * 128;
    const int warpM = wid * 16;

    // A: thread owns (row = tid>>1, 16 k at ak)
    const int ar = tid >> 1, ak = (tid & 1) * 16;
    int grow = mBase + ar; if (grow >= NN) grow = NN - 1;
    const float* abase = g_h1 + (size_t)grow * HC1 + ak;
    // B: threads 0..127 load hi, 128..255 load lo; 16B each
    const bool bhi_role = tid < 128;
    const int bk = (tid & 127) >> 2, bseg = (tid & 3) * 8;
    const __nv_bfloat16* bsrc = (bhi_role ? g_w2hi : g_w2lo) + bk * C2 + bseg;

    float acc[4][4];
#pragma unroll
    for (int ni = 0; ni < 4; ni++)
#pragma unroll
        for (int q = 0; q < 4; q++) acc[ni][q] = 0.f;

    float4 ra0 = *(const float4*)(abase + 0);
    float4 ra1 = *(const float4*)(abase + 4);
    float4 ra2 = *(const float4*)(abase + 8);
    float4 ra3 = *(const float4*)(abase + 12);
    uint4 rb = *(const uint4*)bsrc;

    const uint32_t sAhiB = smem_u32(sAhi), sAloB = smem_u32(sAlo);
    const uint32_t sBhiB = smem_u32(sBhi), sBloB = smem_u32(sBlo);

    for (int ch = 0; ch < 16; ch++) {
        __nv_bfloat16* ah = &sAhi[ar * A2STR + ak];
        __nv_bfloat16* al = &sAlo[ar * A2STR + ak];
        cvt_store(ra0, ah + 0,  al + 0);
        cvt_store(ra1, ah + 4,  al + 4);
        cvt_store(ra2, ah + 8,  al + 8);
        cvt_store(ra3, ah + 12, al + 12);
        __nv_bfloat16* bdst = (bhi_role ? sBhi : sBlo) + bk * B2STR + bseg;
        *(uint4*)bdst = rb;
        __syncthreads();
        if (ch < 15) {
            const float* an = abase + (ch + 1) * 32;
            ra0 = *(const float4*)(an + 0);
            ra1 = *(const float4*)(an + 4);
            ra2 = *(const float4*)(an + 8);
            ra3 = *(const float4*)(an + 12);
            rb = *(const uint4*)(bsrc + (size_t)(ch + 1) * 32 * C2);
        }
#pragma unroll
        for (int ks = 0; ks < 2; ks++) {
            uint32_t ah4[4], al4[4];
            int row = warpM + (lane & 15);
            int col = ks * 16 + (lane >> 4) * 8;
            uint32_t offA = (uint32_t)(row * A2STR + col) * 2;
            ldsm_x4(sAhiB + offA, ah4[0], ah4[1], ah4[2], ah4[3]);
            ldsm_x4(sAloB + offA, al4[0], al4[1], al4[2], al4[3]);
            uint32_t bh[4][2], bl[4][2];
            int krow = ks * 16 + (lane & 15);
#pragma unroll
            for (int np = 0; np < 2; np++) {
                int bcol = np * 16 + (lane >> 4) * 8;
                uint32_t offB = (uint32_t)(krow * B2STR + bcol) * 2;
                ldsm_x4_trans(sBhiB + offB, bh[np * 2][0], bh[np * 2][1],
                              bh[np * 2 + 1][0], bh[np * 2 + 1][1]);
                ldsm_x4_trans(sBloB + offB, bl[np * 2][0], bl[np * 2][1],
                              bl[np * 2 + 1][0], bl[np * 2 + 1][1]);
            }
#pragma unroll
            for (int ni = 0; ni < 4; ni++) {
                mma16816(acc[ni], ah4, bh[ni]);
                mma16816(acc[ni], ah4, bl[ni]);
                mma16816(acc[ni], al4, bh[ni]);
            }
        }
        __syncthreads();
    }

    // epilogue: store xl2 + fused layer-2 attention coefficients
    int row0 = mBase + warpM + (lane >> 2);
    int row1 = row0 + 8;
    float rs0 = 0.f, rd0 = 0.f, rs1 = 0.f, rd1 = 0.f;
#pragma unroll
    for (int ni = 0; ni < 4; ni++) {
        int col = ni * 8 + (lane & 3) * 2;
        if (row0 < NN)
            *(float2*)(&g_xl2[(size_t)row0 * C2 + col]) = make_float2(acc[ni][0], acc[ni][1]);
        if (row1 < NN)
            *(float2*)(&g_xl2[(size_t)row1 * C2 + col]) = make_float2(acc[ni][2], acc[ni][3]);
        float s0 = __ldg(&attS2[col]), s1 = __ldg(&attS2[col + 1]);
        float d0 = __ldg(&attD2[col]), d1 = __ldg(&attD2[col + 1]);
        rs0 = fmaf(acc[ni][0], s0, fmaf(acc[ni][1], s1, rs0));
        rd0 = fmaf(acc[ni][0], d0, fmaf(acc[ni][1], d1, rd0));
        rs1 = fmaf(acc[ni][2], s0, fmaf(acc[ni][3], s1, rs1));
        rd1 = fmaf(acc[ni][2], d0, fmaf(acc[ni][3], d1, rd1));
    }
#pragma unroll
    for (int off = 1; off <= 2; off <<= 1) {
        rs0 += __shfl_xor_sync(0xffffffffu, rs0, off);
        rd0 += __shfl_xor_sync(0xffffffffu, rd0, off);
        rs1 += __shfl_xor_sync(0xffffffffu, rs1, off);
        rd1 += __shfl_xor_sync(0xffffffffu, rd1, off);
    }
    if ((lane & 3) == 0) {
        if (row0 < NN) { g_as2[row0] = rs0; g_ad2[row0] = rd0; }
        if (row1 < NN) { g_as2[row1] = rs1; g_ad2[row1] = rd1; }
    }
}

// ---- layer-2 fused softmax+aggregation + fc head: warp per node --------------
__global__ void __launch_bounds__(256) agg2_kernel(const float* __restrict__ b2,
                                                   const float* __restrict__ fcW,
                                                   const float* __restrict__ fcb,
                                                   float* __restrict__ out) {
    __shared__ float fs[C2 * OUT_DIM];
    __shared__ float fb[OUT_DIM];
    for (int i = threadIdx.x; i < C2 * OUT_DIM; i += 256) fs[i] = fcW[i];
    if (threadIdx.x < OUT_DIM) fb[threadIdx.x] = fcb[threadIdx.x];
    __syncthreads();

    int w = (blockIdx.x * blockDim.x + threadIdx.x) >> 5;
    int lane = threadIdx.x & 31;
    if (w >= NN) return;
    float ad = g_ad2[w];
    float pself = __expf(lrelu(g_as2[w] + ad));
    float acc = pself * g_xl2[(size_t)w * C2 + lane];
    float dacc = 0.f;
    int beg = g_rowptr[w], end = g_rowptr[w + 1];
    for (int j0 = beg; j0 < end; j0 += 32) {
        int j = j0 + lane;
        bool valid = j < end;
        int s_l = valid ? g_csrc[j] : 0;
        float p_l = 0.f;
        if (valid) p_l = __expf(lrelu(__ldg(&g_as2[s_l]) + ad));
        dacc += p_l;
        int cnt = end - j0;
        if (cnt > 32) cnt = 32;
        for (int t = 0; t < cnt; t++) {
            float p = __shfl_sync(0xffffffffu, p_l, t);
            int   s = __shfl_sync(0xffffffffu, s_l, t);
            acc = fmaf(p, g_xl2[(size_t)s * C2 + lane], acc);
        }
    }
#pragma unroll
    for (int off = 16; off; off >>= 1) dacc += __shfl_xor_sync(0xffffffffu, dacc, off);
    float inv = 1.f / (dacc + pself + 1e-16f);
    float emb = fmaxf(fmaf(acc, inv, b2[lane]), 0.f);
    out[(size_t)w * C2 + lane] = emb;

    // fused fc head: logits[w][j] = fcb[j] + sum_c emb_c fcW[c][j]
    float l1 = fb[lane];
    float l2 = (lane < OUT_DIM - 32) ? fb[32 + lane] : 0.f;
#pragma unroll
    for (int c = 0; c < C2; c++) {
        float e = __shfl_sync(0xffffffffu, emb, c);
        l1 = fmaf(e, fs[c * OUT_DIM + lane], l1);
        if (lane < OUT_DIM - 32) l2 = fmaf(e, fs[c * OUT_DIM + 32 + lane], l2);
    }
    float* lg = out + (size_t)NN * C2 + (size_t)w * OUT_DIM;
    lg[lane] = l1;
    if (lane < OUT_DIM - 32) lg[32 + lane] = l2;
}

// ------------------------------------------------------------------------------
extern "C" void kernel_launch(void* const* d_in, const int* in_sizes, int n_in,
                              void* d_out, int out_size) {
    const float* x     = (const float*)d_in[0];
    const int*   ei    = (const int*)  d_in[1];
    const float* W1    = (const float*)d_in[2];
    const float* attS1 = (const float*)d_in[3];
    const float* attD1 = (const float*)d_in[4];
    const float* b1    = (const float*)d_in[5];
    const float* W2    = (const float*)d_in[6];
    const float* attS2 = (const float*)d_in[7];
    const float* attD2 = (const float*)d_in[8];
    const float* b2    = (const float*)d_in[9];
    const float* fcW   = (const float*)d_in[10];
    const float* fcb   = (const float*)d_in[11];
    float* out = (float*)d_out;

    const int* src = ei;
    const int* dst = ei + EE;

    cudaFuncSetAttribute(gemm1_mma_kernel, cudaFuncAttributeMaxDynamicSharedMemorySize,
                         GEMM1_SMEM);

    // split inputs to bf16 hi/lo
    split_x_kernel<<<(NN * IN_DIM / 4 + 255) / 256, 256>>>(x);
    split_w_kernel<<<(IN_DIM * HC1 / 4 + 255) / 256, 256>>>(W1);
    split_w2_kernel<<<(HC1 * C2 / 4 + 255) / 256, 256>>>(W2);

    // CSR build
    void* degp = nullptr;
    cudaGetSymbolAddress(&degp, g_deg);
    cudaMemsetAsync(degp, 0, NN * sizeof(int));
    hist_kernel<<<(EE + 255) / 256, 256>>>(dst);
    scanA_kernel<<<SCAN_BLOCKS, 1024>>>();
    scanB_kernel<<<1, 64>>>();
    scanC_kernel<<<SCAN_BLOCKS, 1024>>>();
    scatter_kernel<<<(EE + 255) / 256, 256>>>(src, dst);

    // layer 1
    {
        dim3 grid((NN + 127) / 128, HC1 / 128);
        gemm1_mma_kernel<<<grid, 256, GEMM1_SMEM>>>(attS1, attD1);
    }
    agg1_kernel<<<(NN * 32 + 255) / 256, 256>>>(b1);

    // layer 2
    gemm2_mma_kernel<<<(NN + 127) / 128, 256>>>(attS2, attD2);
    agg2_kernel<<<(NN * 32 + 255) / 256, 256>>>(b2, fcW, fcb, out);
}

// round 7
// speedup vs baseline: 2.2205x; 1.0595x over previous
#include <cuda_runtime.h>
#include <cuda_bf16.h>
#include <cstdint>

// Problem constants (fixed by the dataset)
#define NN      50000
#define EE      800000
#define IN_DIM  256
#define HEADS   8
#define C1      64
#define HC1     512          // HEADS*C1
#define C2      32
#define OUT_DIM 40
#define NEG_SLOPE 0.2f

#define SCAN_BLOCKS 49       // 49 * 1024 >= NN
#define NHALF 25088          // 196 * 128, split point for layer pipelining

// ---------------- scratch (device globals; no cudaMalloc allowed) ------------
__device__ float g_xl1[(size_t)NN * HC1];     // x @ W1
__device__ float g_h1 [(size_t)NN * HC1];     // layer-1 output (relu)
__device__ __nv_bfloat16 g_xhi[(size_t)NN * IN_DIM];
__device__ __nv_bfloat16 g_xlo[(size_t)NN * IN_DIM];
__device__ __nv_bfloat16 g_whi[(size_t)IN_DIM * HC1];
__device__ __nv_bfloat16 g_wlo[(size_t)IN_DIM * HC1];
__device__ __nv_bfloat16 g_w2hi[HC1 * C2];
__device__ __nv_bfloat16 g_w2lo[HC1 * C2];
__device__ float g_as1[NN * HEADS];
__device__ float g_ad1[NN * HEADS];
__device__ float g_xl2[(size_t)NN * C2];
__device__ float g_as2[NN], g_ad2[NN];
__device__ int   g_deg[NN];
__device__ int   g_incl[SCAN_BLOCKS * 1024];
__device__ int   g_bsum[SCAN_BLOCKS];
__device__ int   g_boff[SCAN_BLOCKS];
__device__ int   g_rowptr[NN + 1];
__device__ int   g_cursor[NN];
__device__ int   g_csrc[EE];

__device__ __forceinline__ float lrelu(float x) { return x > 0.f ? x : NEG_SLOPE * x; }

// ========================= PTX helpers =========================
__device__ __forceinline__ uint32_t smem_u32(const void* p) {
    uint32_t a;
    asm("{ .reg .u64 t; cvta.to.shared.u64 t, %1; cvt.u32.u64 %0, t; }" : "=r"(a) : "l"(p));
    return a;
}
__device__ __forceinline__ void ldsm_x4(uint32_t addr, uint32_t& r0, uint32_t& r1,
                                        uint32_t& r2, uint32_t& r3) {
    asm volatile("ldmatrix.sync.aligned.m8n8.x4.shared.b16 {%0,%1,%2,%3}, [%4];"
                 : "=r"(r0), "=r"(r1), "=r"(r2), "=r"(r3) : "r"(addr));
}
__device__ __forceinline__ void ldsm_x4_trans(uint32_t addr, uint32_t& r0, uint32_t& r1,
                                              uint32_t& r2, uint32_t& r3) {
    asm volatile("ldmatrix.sync.aligned.m8n8.x4.trans.shared.b16 {%0,%1,%2,%3}, [%4];"
                 : "=r"(r0), "=r"(r1), "=r"(r2), "=r"(r3) : "r"(addr));
}
__device__ __forceinline__ void mma16816(float* d, const uint32_t* a, const uint32_t* b) {
    asm volatile(
        "mma.sync.aligned.m16n8k16.row.col.f32.bf16.bf16.f32 "
        "{%0,%1,%2,%3},{%4,%5,%6,%7},{%8,%9},{%0,%1,%2,%3};"
        : "+f"(d[0]), "+f"(d[1]), "+f"(d[2]), "+f"(d[3])
        : "r"(a[0]), "r"(a[1]), "r"(a[2]), "r"(a[3]), "r"(b[0]), "r"(b[1]));
}
__device__ __forceinline__ uint32_t pack2(__nv_bfloat16 x, __nv_bfloat16 y) {
    uint32_t lo = __bfloat16_as_ushort(x);
    uint32_t hi = __bfloat16_as_ushort(y);
    return lo | (hi << 16);
}
__device__ __forceinline__ void cp16(uint32_t dst, const void* src, uint32_t sz) {
    asm volatile("cp.async.cg.shared.global [%0], [%1], 16, %2;"
                 :: "r"(dst), "l"(src), "r"(sz) : "memory");
}
__device__ __forceinline__ void cvt_store(float4 v, __nv_bfloat16* hi, __nv_bfloat16* lo) {
    __nv_bfloat16 h0 = __float2bfloat16_rn(v.x), h1 = __float2bfloat16_rn(v.y);
    __nv_bfloat16 h2 = __float2bfloat16_rn(v.z), h3 = __float2bfloat16_rn(v.w);
    uint2 hv, lv;
    hv.x = pack2(h0, h1); hv.y = pack2(h2, h3);
    lv.x = pack2(__float2bfloat16_rn(v.x - __bfloat162float(h0)),
                 __float2bfloat16_rn(v.y - __bfloat162float(h1)));
    lv.y = pack2(__float2bfloat16_rn(v.z - __bfloat162float(h2)),
                 __float2bfloat16_rn(v.w - __bfloat162float(h3)));
    *(uint2*)hi = hv; *(uint2*)lo = lv;
}

// ===================== split: fp32 -> bf16 hi/lo ==============================
__global__ void split_x_kernel(const float* __restrict__ x) {
    int i = blockIdx.x * blockDim.x + threadIdx.x;
    if (i >= NN * IN_DIM / 4) return;
    cvt_store(((const float4*)x)[i], g_xhi + i * 4, g_xlo + i * 4);
}
__global__ void split_w_kernel(const float* __restrict__ w) {
    int i = blockIdx.x * blockDim.x + threadIdx.x;
    if (i >= IN_DIM * HC1 / 4) return;
    cvt_store(((const float4*)w)[i], g_whi + i * 4, g_wlo + i * 4);
}
__global__ void split_w2_kernel(const float* __restrict__ w) {
    int i = blockIdx.x * blockDim.x + threadIdx.x;
    if (i >= HC1 * C2 / 4) return;
    cvt_store(((const float4*)w)[i], g_w2hi + i * 4, g_w2lo + i * 4);
}

// ======== GEMM1: xl1 = x @ W1, bf16 3-split, cp.async double-buffered ========
#define ASTR 40     // bf16 per A smem row (32 + 8 pad)
#define BSTR 136    // bf16 per B smem row (128 + 8 pad)
#define OFF_AHI 0
#define OFF_ALO 10240
#define OFF_BHI 20480
#define OFF_BLO 29184
#define STAGE   37888
#define GEMM1_SMEM (2 * STAGE)

__global__ void __launch_bounds__(256, 2) gemm1_mma_kernel(const float* __restrict__ attS1,
                                                           const float* __restrict__ attD1) {
    extern __shared__ __align__(16) char smem[];
    const uint32_t sbase = smem_u32(smem);
    const int tid = threadIdx.x, wid = tid >> 5, lane = tid & 31;
    const int warpM = (wid & 3) * 32;
    const int warpN = (wid >> 2) * 64;
    const int mBase = blockIdx.x * 128;
    const int nBase = blockIdx.y * 128;

    float acc[2][8][4];
#pragma unroll
    for (int mi = 0; mi < 2; mi++)
#pragma unroll
        for (int ni = 0; ni < 8; ni++)
#pragma unroll
            for (int q = 0; q < 4; q++) acc[mi][ni][q] = 0.f;

    auto load_stage = [&](int ch, int buf) {
        const int k0 = ch * 32;
        const uint32_t sb = sbase + buf * STAGE;
#pragma unroll
        for (int it = 0; it < 2; it++) {
            int chunk = it * 256 + tid;
            int r = chunk >> 2, c = (chunk & 3) * 8;
            int gr = mBase + r;
            uint32_t sz = (gr < NN) ? 16u : 0u;
            int grc = gr < NN ? gr : NN - 1;
            uint32_t so = (uint32_t)(r * ASTR + c) * 2;
            cp16(sb + OFF_AHI + so, &g_xhi[(size_t)grc * IN_DIM + k0 + c], sz);
            cp16(sb + OFF_ALO + so, &g_xlo[(size_t)grc * IN_DIM + k0 + c], sz);
        }
#pragma unroll
        for (int it = 0; it < 2; it++) {
            int chunk = it * 256 + tid;
            int r = chunk >> 4, c = (chunk & 15) * 8;
            uint32_t so = (uint32_t)(r * BSTR + c) * 2;
            cp16(sb + OFF_BHI + so, &g_whi[(size_t)(k0 + r) * HC1 + nBase + c], 16);
            cp16(sb + OFF_BLO + so, &g_wlo[(size_t)(k0 + r) * HC1 + nBase + c], 16);
        }
        asm volatile("cp.async.commit_group;" ::: "memory");
    };

    load_stage(0, 0);
    for (int ch = 0; ch < 8; ch++) {
        const int buf = ch & 1;
        if (ch + 1 < 8) {
            load_stage(ch + 1, buf ^ 1);
            asm volatile("cp.async.wait_group 1;" ::: "memory");
        } else {
            asm volatile("cp.async.wait_group 0;" ::: "memory");
        }
        __syncthreads();
        const uint32_t sb = sbase + buf * STAGE;
#pragma unroll
        for (int ks = 0; ks < 2; ks++) {
            uint32_t ah[2][4], al[2][4];
#pragma unroll
            for (int mi = 0; mi < 2; mi++) {
                int row = warpM + mi * 16 + (lane & 15);
                int col = ks * 16 + (lane >> 4) * 8;
                uint32_t off = (uint32_t)(row * ASTR + col) * 2;
                ldsm_x4(sb + OFF_AHI + off, ah[mi][0], ah[mi][1], ah[mi][2], ah[mi][3]);
                ldsm_x4(sb + OFF_ALO + off, al[mi][0], al[mi][1], al[mi][2], al[mi][3]);
            }
            uint32_t bh[8][2], bl[8][2];
#pragma unroll
            for (int np = 0; np < 4; np++) {
                int krow = ks * 16 + (lane & 15);
                int col = warpN + np * 16 + (lane >> 4) * 8;
                uint32_t off = (uint32_t)(krow * BSTR + col) * 2;
                ldsm_x4_trans(sb + OFF_BHI + off, bh[np * 2][0], bh[np * 2][1],
                              bh[np * 2 + 1][0], bh[np * 2 + 1][1]);
                ldsm_x4_trans(sb + OFF_BLO + off, bl[np * 2][0], bl[np * 2][1],
                              bl[np * 2 + 1][0], bl[np * 2 + 1][1]);
            }
#pragma unroll
            for (int mi = 0; mi < 2; mi++)
#pragma unroll
                for (int ni = 0; ni < 8; ni++) {
                    mma16816(acc[mi][ni], ah[mi], bh[ni]);
                    mma16816(acc[mi][ni], ah[mi], bl[ni]);
                    mma16816(acc[mi][ni], al[mi], bh[ni]);
                }
        }
        __syncthreads();
    }

    // ---- epilogue 1: store xl1 ----
#pragma unroll
    for (int mi = 0; mi < 2; mi++) {
#pragma unroll
        for (int ni = 0; ni < 8; ni++) {
            int row0 = mBase + warpM + mi * 16 + (lane >> 2);
            int col = nBase + warpN + ni * 8 + (lane & 3) * 2;
            if (row0 < NN)
                *(float2*)(&g_xl1[(size_t)row0 * HC1 + col]) =
                    make_float2(acc[mi][ni][0], acc[mi][ni][1]);
            int row1 = row0 + 8;
            if (row1 < NN)
                *(float2*)(&g_xl1[(size_t)row1 * HC1 + col]) =
                    make_float2(acc[mi][ni][2], acc[mi][ni][3]);
        }
    }

    // ---- epilogue 2: fused a_src / a_dst (warp owns one complete head) ----
    {
        const int h = blockIdx.y * 2 + (wid >> 2);
        float sS[8][2], sD[8][2];
        int cb = h * C1 + (lane & 3) * 2;
#pragma unroll
        for (int ni = 0; ni < 8; ni++) {
            sS[ni][0] = __ldg(&attS1[cb + ni * 8]);
            sS[ni][1] = __ldg(&attS1[cb + ni * 8 + 1]);
            sD[ni][0] = __ldg(&attD1[cb + ni * 8]);
            sD[ni][1] = __ldg(&attD1[cb + ni * 8 + 1]);
        }
#pragma unroll
        for (int mi = 0; mi < 2; mi++) {
            float rs0 = 0.f, rs1 = 0.f, rd0 = 0.f, rd1 = 0.f;
#pragma unroll
            for (int ni = 0; ni < 8; ni++) {
                rs0 = fmaf(acc[mi][ni][0], sS[ni][0], fmaf(acc[mi][ni][1], sS[ni][1], rs0));
                rd0 = fmaf(acc[mi][ni][0], sD[ni][0], fmaf(acc[mi][ni][1], sD[ni][1], rd0));
                rs1 = fmaf(acc[mi][ni][2], sS[ni][0], fmaf(acc[mi][ni][3], sS[ni][1], rs1));
                rd1 = fmaf(acc[mi][ni][2], sD[ni][0], fmaf(acc[mi][ni][3], sD[ni][1], rd1));
            }
#pragma unroll
            for (int off = 1; off <= 2; off <<= 1) {
                rs0 += __shfl_xor_sync(0xffffffffu, rs0, off);
                rd0 += __shfl_xor_sync(0xffffffffu, rd0, off);
                rs1 += __shfl_xor_sync(0xffffffffu, rs1, off);
                rd1 += __shfl_xor_sync(0xffffffffu, rd1, off);
            }
            if ((lane & 3) == 0) {
                int row0 = mBase + warpM + mi * 16 + (lane >> 2);
                if (row0 < NN) { g_as1[row0 * 8 + h] = rs0; g_ad1[row0 * 8 + h] = rd0; }
                int row1 = row0 + 8;
                if (row1 < NN) { g_as1[row1 * 8 + h] = rs1; g_ad1[row1 * 8 + h] = rd1; }
            }
        }
    }
}

// ---------------------------- CSR construction -------------------------------
__global__ void hist_kernel(const int* __restrict__ dst) {
    int e = blockIdx.x * blockDim.x + threadIdx.x;
    if (e < EE) atomicAdd(&g_deg[dst[e]], 1);
}
__global__ void scanA_kernel() {
    __shared__ int sh[1024];
    int i = blockIdx.x * 1024 + threadIdx.x;
    int v = (i < NN) ? g_deg[i] : 0;
    sh[threadIdx.x] = v;
    __syncthreads();
#pragma unroll
    for (int off = 1; off < 1024; off <<= 1) {
        int t = (threadIdx.x >= off) ? sh[threadIdx.x - off] : 0;
        __syncthreads();
        sh[threadIdx.x] += t;
        __syncthreads();
    }
    g_incl[i] = sh[threadIdx.x];
    if (threadIdx.x == 1023) g_bsum[blockIdx.x] = sh[1023];
}
__global__ void scanB_kernel() {   // 1 block, 64 threads
    __shared__ int sh[64];
    int t = threadIdx.x;
    int v = (t < SCAN_BLOCKS) ? g_bsum[t] : 0;
    sh[t] = v;
    __syncthreads();
#pragma unroll
    for (int off = 1; off < 64; off <<= 1) {
        int u = (t >= off) ? sh[t - off] : 0;
        __syncthreads();
        sh[t] += u;
        __syncthreads();
    }
    if (t < SCAN_BLOCKS) g_boff[t] = sh[t] - v;   // exclusive
}
__global__ void scanC_kernel() {
    int i = blockIdx.x * 1024 + threadIdx.x;
    if (i < NN) {
        int ex = g_boff[blockIdx.x] + g_incl[i] - g_deg[i];
        g_rowptr[i] = ex;
        g_cursor[i] = ex;
    }
    if (i == 0) g_rowptr[NN] = EE;
}
__global__ void scatter_kernel(const int* __restrict__ src, const int* __restrict__ dst) {
    int e = blockIdx.x * blockDim.x + threadIdx.x;
    if (e >= EE) return;
    int d = dst[e];
    int pos = atomicAdd(&g_cursor[d], 1);
    g_csrc[pos] = src[e];
}

// ---- layer-1 fused softmax+aggregation: warp per node, all heads ------------
__global__ void agg1_kernel(const float* __restrict__ b1, int nodeBeg, int nodeEnd) {
    int w = nodeBeg + ((blockIdx.x * blockDim.x + threadIdx.x) >> 5);
    int lane = threadIdx.x & 31;
    if (w >= nodeEnd) return;
    const int h = lane >> 2;
    const int e4 = lane & 3;
    const int idx8 = w * 8 + h;
    const float ad = g_ad1[idx8];
    const float pself = __expf(lrelu(g_as1[idx8] + ad));

    const float4* xr = (const float4*)(g_xl1 + (size_t)w * HC1 + lane * 16);
    float4 a0 = xr[0], a1 = xr[1], a2 = xr[2], a3 = xr[3];
    a0.x *= pself; a0.y *= pself; a0.z *= pself; a0.w *= pself;
    a1.x *= pself; a1.y *= pself; a1.z *= pself; a1.w *= pself;
    a2.x *= pself; a2.y *= pself; a2.z *= pself; a2.w *= pself;
    a3.x *= pself; a3.y *= pself; a3.z *= pself; a3.w *= pself;
    float dacc = 0.f;

    const int beg = g_rowptr[w], end = g_rowptr[w + 1];
    for (int j0 = beg; j0 < end; j0 += 4) {
        int j = j0 + e4;
        bool valid = j < end;
        int s_l = valid ? g_csrc[j] : 0;
        float p_l = 0.f;
        if (valid) p_l = __expf(lrelu(__ldg(&g_as1[s_l * 8 + h]) + ad));
        dacc += p_l;
        int cnt = end - j0;
        int qb = lane & 28;
#pragma unroll
        for (int t = 0; t < 4; t++) {
            if (t < cnt) {
                float p = __shfl_sync(0xffffffffu, p_l, qb | t);
                int   s = __shfl_sync(0xffffffffu, s_l, qb | t);
                const float4* sr = (const float4*)(g_xl1 + (size_t)s * HC1 + lane * 16);
                float4 u0 = sr[0], u1 = sr[1], u2 = sr[2], u3 = sr[3];
                a0.x = fmaf(p, u0.x, a0.x); a0.y = fmaf(p, u0.y, a0.y);
                a0.z = fmaf(p, u0.z, a0.z); a0.w = fmaf(p, u0.w, a0.w);
                a1.x = fmaf(p, u1.x, a1.x); a1.y = fmaf(p, u1.y, a1.y);
                a1.z = fmaf(p, u1.z, a1.z); a1.w = fmaf(p, u1.w, a1.w);
                a2.x = fmaf(p, u2.x, a2.x); a2.y = fmaf(p, u2.y, a2.y);
                a2.z = fmaf(p, u2.z, a2.z); a2.w = fmaf(p, u2.w, a2.w);
                a3.x = fmaf(p, u3.x, a3.x); a3.y = fmaf(p, u3.y, a3.y);
                a3.z = fmaf(p, u3.z, a3.z); a3.w = fmaf(p, u3.w, a3.w);
            }
        }
    }
    dacc += __shfl_xor_sync(0xffffffffu, dacc, 1);
    dacc += __shfl_xor_sync(0xffffffffu, dacc, 2);
    float inv = 1.f / (dacc + pself + 1e-16f);

    const float4* bb = (const float4*)(b1 + lane * 16);
    float4 b0 = bb[0], b1v = bb[1], b2v = bb[2], b3v = bb[3];
    float4* hw = (float4*)(g_h1 + (size_t)w * HC1 + lane * 16);
    float4 o;
    o.x = fmaxf(fmaf(a0.x, inv, b0.x), 0.f); o.y = fmaxf(fmaf(a0.y, inv, b0.y), 0.f);
    o.z = fmaxf(fmaf(a0.z, inv, b0.z), 0.f); o.w = fmaxf(fmaf(a0.w, inv, b0.w), 0.f);
    hw[0] = o;
    o.x = fmaxf(fmaf(a1.x, inv, b1v.x), 0.f); o.y = fmaxf(fmaf(a1.y, inv, b1v.y), 0.f);
    o.z = fmaxf(fmaf(a1.z, inv, b1v.z), 0.f); o.w = fmaxf(fmaf(a1.w, inv, b1v.w), 0.f);
    hw[1] = o;
    o.x = fmaxf(fmaf(a2.x, inv, b2v.x), 0.f); o.y = fmaxf(fmaf(a2.y, inv, b2v.y), 0.f);
    o.z = fmaxf(fmaf(a2.z, inv, b2v.z), 0.f); o.w = fmaxf(fmaf(a2.w, inv, b2v.w), 0.f);
    hw[2] = o;
    o.x = fmaxf(fmaf(a3.x, inv, b3v.x), 0.f); o.y = fmaxf(fmaf(a3.y, inv, b3v.y), 0.f);
    o.z = fmaxf(fmaf(a3.w, inv, b3v.w), 0.f); o.w = fmaxf(fmaf(a3.w, inv, b3v.w), 0.f);
    // NOTE: fix z-component (see corrected line below)
    o.z = fmaxf(fmaf(a3.z, inv, b3v.z), 0.f);
    hw[3] = o;
}

// ==== GEMM2 on tensor cores: xl2 = h1 @ W2 (rows [nodeBeg,nodeEnd)) ==========
#define A2STR 40
#define B2STR 40
__global__ void __launch_bounds__(256) gemm2_mma_kernel(const float* __restrict__ attS2,
                                                        const float* __restrict__ attD2,
                                                        int nodeBeg, int nodeEnd) {
    __shared__ __align__(16) __nv_bfloat16 sAhi[128 * A2STR], sAlo[128 * A2STR];
    __shared__ __align__(16) __nv_bfloat16 sBhi[32 * B2STR],  sBlo[32 * B2STR];
    const int tid = threadIdx.x, wid = tid >> 5, lane = tid & 31;
    const int mBase = nodeBeg + blockIdx.x * 128;
    const int warpM = wid * 16;

    const int ar = tid >> 1, ak = (tid & 1) * 16;
    int grow = mBase + ar; if (grow >= nodeEnd) grow = nodeEnd - 1;
    const float* abase = g_h1 + (size_t)grow * HC1 + ak;
    const bool bhi_role = tid < 128;
    const int bk = (tid & 127) >> 2, bseg = (tid & 3) * 8;
    const __nv_bfloat16* bsrc = (bhi_role ? g_w2hi : g_w2lo) + bk * C2 + bseg;

    float acc[4][4];
#pragma unroll
    for (int ni = 0; ni < 4; ni++)
#pragma unroll
        for (int q = 0; q < 4; q++) acc[ni][q] = 0.f;

    float4 ra0 = *(const float4*)(abase + 0);
    float4 ra1 = *(const float4*)(abase + 4);
    float4 ra2 = *(const float4*)(abase + 8);
    float4 ra3 = *(const float4*)(abase + 12);
    uint4 rb = *(const uint4*)bsrc;

    const uint32_t sAhiB = smem_u32(sAhi), sAloB = smem_u32(sAlo);
    const uint32_t sBhiB = smem_u32(sBhi), sBloB = smem_u32(sBlo);

    for (int ch = 0; ch < 16; ch++) {
        __nv_bfloat16* ah = &sAhi[ar * A2STR + ak];
        __nv_bfloat16* al = &sAlo[ar * A2STR + ak];
        cvt_store(ra0, ah + 0,  al + 0);
        cvt_store(ra1, ah + 4,  al + 4);
        cvt_store(ra2, ah + 8,  al + 8);
        cvt_store(ra3, ah + 12, al + 12);
        __nv_bfloat16* bdst = (bhi_role ? sBhi : sBlo) + bk * B2STR + bseg;
        *(uint4*)bdst = rb;
        __syncthreads();
        if (ch < 15) {
            const float* an = abase + (ch + 1) * 32;
            ra0 = *(const float4*)(an + 0);
            ra1 = *(const float4*)(an + 4);
            ra2 = *(const float4*)(an + 8);
            ra3 = *(const float4*)(an + 12);
            rb = *(const uint4*)(bsrc + (size_t)(ch + 1) * 32 * C2);
        }
#pragma unroll
        for (int ks = 0; ks < 2; ks++) {
            uint32_t ah4[4], al4[4];
            int row = warpM + (lane & 15);
            int col = ks * 16 + (lane >> 4) * 8;
            uint32_t offA = (uint32_t)(row * A2STR + col) * 2;
            ldsm_x4(sAhiB + offA, ah4[0], ah4[1], ah4[2], ah4[3]);
            ldsm_x4(sAloB + offA, al4[0], al4[1], al4[2], al4[3]);
            uint32_t bh[4][2], bl[4][2];
            int krow = ks * 16 + (lane & 15);
#pragma unroll
            for (int np = 0; np < 2; np++) {
                int bcol = np * 16 + (lane >> 4) * 8;
                uint32_t offB = (uint32_t)(krow * B2STR + bcol) * 2;
                ldsm_x4_trans(sBhiB + offB, bh[np * 2][0], bh[np * 2][1],
                              bh[np * 2 + 1][0], bh[np * 2 + 1][1]);
                ldsm_x4_trans(sBloB + offB, bl[np * 2][0], bl[np * 2][1],
                              bl[np * 2 + 1][0], bl[np * 2 + 1][1]);
            }
#pragma unroll
            for (int ni = 0; ni < 4; ni++) {
                mma16816(acc[ni], ah4, bh[ni]);
                mma16816(acc[ni], ah4, bl[ni]);
                mma16816(acc[ni], al4, bh[ni]);
            }
        }
        __syncthreads();
    }

    int row0 = mBase + warpM + (lane >> 2);
    int row1 = row0 + 8;
    float rs0 = 0.f, rd0 = 0.f, rs1 = 0.f, rd1 = 0.f;
#pragma unroll
    for (int ni = 0; ni < 4; ni++) {
        int col = ni * 8 + (lane & 3) * 2;
        if (row0 < nodeEnd)
            *(float2*)(&g_xl2[(size_t)row0 * C2 + col]) = make_float2(acc[ni][0], acc[ni][1]);
        if (row1 < nodeEnd)
            *(float2*)(&g_xl2[(size_t)row1 * C2 + col]) = make_float2(acc[ni][2], acc[ni][3]);
        float s0 = __ldg(&attS2[col]), s1 = __ldg(&attS2[col + 1]);
        float d0 = __ldg(&attD2[col]), d1 = __ldg(&attD2[col + 1]);
        rs0 = fmaf(acc[ni][0], s0, fmaf(acc[ni][1], s1, rs0));
        rd0 = fmaf(acc[ni][0], d0, fmaf(acc[ni][1], d1, rd0));
        rs1 = fmaf(acc[ni][2], s0, fmaf(acc[ni][3], s1, rs1));
        rd1 = fmaf(acc[ni][2], d0, fmaf(acc[ni][3], d1, rd1));
    }
#pragma unroll
    for (int off = 1; off <= 2; off <<= 1) {
        rs0 += __shfl_xor_sync(0xffffffffu, rs0, off);
        rd0 += __shfl_xor_sync(0xffffffffu, rd0, off);
        rs1 += __shfl_xor_sync(0xffffffffu, rs1, off);
        rd1 += __shfl_xor_sync(0xffffffffu, rd1, off);
    }
    if ((lane & 3) == 0) {
        if (row0 < nodeEnd) { g_as2[row0] = rs0; g_ad2[row0] = rd0; }
        if (row1 < nodeEnd) { g_as2[row1] = rs1; g_ad2[row1] = rd1; }
    }
}

// ---- layer-2 fused softmax+aggregation + fc head: warp per node --------------
__global__ void __launch_bounds__(256) agg2_kernel(const float* __restrict__ b2,
                                                   const float* __restrict__ fcW,
                                                   const float* __restrict__ fcb,
                                                   float* __restrict__ out) {
    __shared__ float fs[C2 * OUT_DIM];
    __shared__ float fb[OUT_DIM];
    for (int i = threadIdx.x; i < C2 * OUT_DIM; i += 256) fs[i] = fcW[i];
    if (threadIdx.x < OUT_DIM) fb[threadIdx.x] = fcb[threadIdx.x];
    __syncthreads();

    int w = (blockIdx.x * blockDim.x + threadIdx.x) >> 5;
    int lane = threadIdx.x & 31;
    if (w >= NN) return;
    float ad = g_ad2[w];
    float pself = __expf(lrelu(g_as2[w] + ad));
    float acc = pself * g_xl2[(size_t)w * C2 + lane];
    float dacc = 0.f;
    int beg = g_rowptr[w], end = g_rowptr[w + 1];
    for (int j0 = beg; j0 < end; j0 += 32) {
        int j = j0 + lane;
        bool valid = j < end;
        int s_l = valid ? g_csrc[j] : 0;
        float p_l = 0.f;
        if (valid) p_l = __expf(lrelu(__ldg(&g_as2[s_l]) + ad));
        dacc += p_l;
        int cnt = end - j0;
        if (cnt > 32) cnt = 32;
        for (int t = 0; t < cnt; t++) {
            float p = __shfl_sync(0xffffffffu, p_l, t);
            int   s = __shfl_sync(0xffffffffu, s_l, t);
            acc = fmaf(p, g_xl2[(size_t)s * C2 + lane], acc);
        }
    }
#pragma unroll
    for (int off = 16; off; off >>= 1) dacc += __shfl_xor_sync(0xffffffffu, dacc, off);
    float inv = 1.f / (dacc + pself + 1e-16f);
    float emb = fmaxf(fmaf(acc, inv, b2[lane]), 0.f);
    out[(size_t)w * C2 + lane] = emb;

    float l1 = fb[lane];
    float l2 = (lane < OUT_DIM - 32) ? fb[32 + lane] : 0.f;
#pragma unroll
    for (int c = 0; c < C2; c++) {
        float e = __shfl_sync(0xffffffffu, emb, c);
        l1 = fmaf(e, fs[c * OUT_DIM + lane], l1);
        if (lane < OUT_DIM - 32) l2 = fmaf(e, fs[c * OUT_DIM + 32 + lane], l2);
    }
    float* lg = out + (size_t)NN * C2 + (size_t)w * OUT_DIM;
    lg[lane] = l1;
    if (lane < OUT_DIM - 32) lg[32 + lane] = l2;
}

// ------------------------------------------------------------------------------
extern "C" void kernel_launch(void* const* d_in, const int* in_sizes, int n_in,
                              void* d_out, int out_size) {
    const float* x     = (const float*)d_in[0];
    const int*   ei    = (const int*)  d_in[1];
    const float* W1    = (const float*)d_in[2];
    const float* attS1 = (const float*)d_in[3];
    const float* attD1 = (const float*)d_in[4];
    const float* b1    = (const float*)d_in[5];
    const float* W2    = (const float*)d_in[6];
    const float* attS2 = (const float*)d_in[7];
    const float* attD2 = (const float*)d_in[8];
    const float* b2    = (const float*)d_in[9];
    const float* fcW   = (const float*)d_in[10];
    const float* fcb   = (const float*)d_in[11];
    float* out = (float*)d_out;

    const int* src = ei;
    const int* dst = ei + EE;

    // fixed auxiliary stream + events (created once; same captured DAG each call)
    static cudaStream_t sB = [] { cudaStream_t s; cudaStreamCreateWithFlags(&s, cudaStreamNonBlocking); return s; }();
    static cudaEvent_t evFork = [] { cudaEvent_t e; cudaEventCreateWithFlags(&e, cudaEventDisableTiming); return e; }();
    static cudaEvent_t evCSR  = [] { cudaEvent_t e; cudaEventCreateWithFlags(&e, cudaEventDisableTiming); return e; }();
    static cudaEvent_t evG1   = [] { cudaEvent_t e; cudaEventCreateWithFlags(&e, cudaEventDisableTiming); return e; }();
    static cudaEvent_t evHi   = [] { cudaEvent_t e; cudaEventCreateWithFlags(&e, cudaEventDisableTiming); return e; }();

    cudaFuncSetAttribute(gemm1_mma_kernel, cudaFuncAttributeMaxDynamicSharedMemorySize,
                         GEMM1_SMEM);

    // ---- fork: CSR chain + w2 split on stream B, shadowed by gemm1 ----
    cudaEventRecord(evFork, 0);
    cudaStreamWaitEvent(sB, evFork, 0);

    void* degp = nullptr;
    cudaGetSymbolAddress(&degp, g_deg);
    cudaMemsetAsync(degp, 0, NN * sizeof(int), sB);
    hist_kernel<<<(EE + 255) / 256, 256, 0, sB>>>(dst);
    scanA_kernel<<<SCAN_BLOCKS, 1024, 0, sB>>>();
    scanB_kernel<<<1, 64, 0, sB>>>();
    scanC_kernel<<<SCAN_BLOCKS, 1024, 0, sB>>>();
    scatter_kernel<<<(EE + 255) / 256, 256, 0, sB>>>(src, dst);
    split_w2_kernel<<<(HC1 * C2 / 4 + 255) / 256, 256, 0, sB>>>(W2);
    cudaEventRecord(evCSR, sB);

    // ---- main stream: splits + gemm1 ----
    split_x_kernel<<<(NN * IN_DIM / 4 + 255) / 256, 256>>>(x);
    split_w_kernel<<<(IN_DIM * HC1 / 4 + 255) / 256, 256>>>(W1);
    {
        dim3 grid((NN + 127) / 128, HC1 / 128);
        gemm1_mma_kernel<<<grid, 256, GEMM1_SMEM>>>(attS1, attD1);
    }
    cudaEventRecord(evG1, 0);

    // ---- layer 1 agg + layer 2 gemm, pipelined in node halves ----
    cudaStreamWaitEvent(0, evCSR, 0);
    agg1_kernel<<<(NHALF * 32 + 255) / 256, 256>>>(b1, 0, NHALF);
    gemm2_mma_kernel<<<NHALF / 128, 256>>>(attS2, attD2, 0, NHALF);

    cudaStreamWaitEvent(sB, evG1, 0);
    agg1_kernel<<<((NN - NHALF) * 32 + 255) / 256, 256, 0, sB>>>(b1, NHALF, NN);
    gemm2_mma_kernel<<<(NN - NHALF + 127) / 128, 256, 0, sB>>>(attS2, attD2, NHALF, NN);
    cudaEventRecord(evHi, sB);

    // ---- join, then layer-2 agg + fused fc head ----
    cudaStreamWaitEvent(0, evHi, 0);
    agg2_kernel<<<(NN * 32 + 255) / 256, 256>>>(b2, fcW, fcb, out);
}

// round 8
// speedup vs baseline: 3.3221x; 1.4961x over previous
#include <cuda_runtime.h>
#include <cuda_bf16.h>
#include <cuda_fp16.h>
#include <cstdint>

// Problem constants (fixed by the dataset)
#define NN      50000
#define EE      800000
#define IN_DIM  256
#define HEADS   8
#define C1      64
#define HC1     512          // HEADS*C1
#define C2      32
#define OUT_DIM 40
#define NEG_SLOPE 0.2f

#define SCAN_BLOCKS 49       // 49 * 1024 >= NN
#define NHALF 25088          // 196 * 128, split point for layer pipelining

// ---------------- scratch (device globals; no cudaMalloc allowed) ------------
__device__ __half g_xl1h[(size_t)NN * HC1];   // x @ W1  (fp16)
__device__ __half g_h1h [(size_t)NN * HC1];   // layer-1 output, relu (fp16)
__device__ __nv_bfloat16 g_xhi[(size_t)NN * IN_DIM];
__device__ __nv_bfloat16 g_xlo[(size_t)NN * IN_DIM];
__device__ __nv_bfloat16 g_whi[(size_t)IN_DIM * HC1];
__device__ __nv_bfloat16 g_wlo[(size_t)IN_DIM * HC1];
__device__ __nv_bfloat16 g_w2hi[HC1 * C2];
__device__ __nv_bfloat16 g_w2lo[HC1 * C2];
__device__ float g_as1[NN * HEADS];
__device__ float g_ad1[NN * HEADS];
__device__ float g_xl2[(size_t)NN * C2];
__device__ float g_as2[NN], g_ad2[NN];
__device__ int   g_deg[NN];
__device__ int   g_incl[SCAN_BLOCKS * 1024];
__device__ int   g_bsum[SCAN_BLOCKS];
__device__ int   g_boff[SCAN_BLOCKS];
__device__ int   g_rowptr[NN + 1];
__device__ int   g_cursor[NN];
__device__ int   g_csrc[EE];

__device__ __forceinline__ float lrelu(float x) { return x > 0.f ? x : NEG_SLOPE * x; }

// ========================= PTX helpers =========================
__device__ __forceinline__ uint32_t smem_u32(const void* p) {
    uint32_t a;
    asm("{ .reg .u64 t; cvta.to.shared.u64 t, %1; cvt.u32.u64 %0, t; }" : "=r"(a) : "l"(p));
    return a;
}
__device__ __forceinline__ void ldsm_x4(uint32_t addr, uint32_t& r0, uint32_t& r1,
                                        uint32_t& r2, uint32_t& r3) {
    asm volatile("ldmatrix.sync.aligned.m8n8.x4.shared.b16 {%0,%1,%2,%3}, [%4];"
                 : "=r"(r0), "=r"(r1), "=r"(r2), "=r"(r3) : "r"(addr));
}
__device__ __forceinline__ void ldsm_x4_trans(uint32_t addr, uint32_t& r0, uint32_t& r1,
                                              uint32_t& r2, uint32_t& r3) {
    asm volatile("ldmatrix.sync.aligned.m8n8.x4.trans.shared.b16 {%0,%1,%2,%3}, [%4];"
                 : "=r"(r0), "=r"(r1), "=r"(r2), "=r"(r3) : "r"(addr));
}
__device__ __forceinline__ void mma16816(float* d, const uint32_t* a, const uint32_t* b) {
    asm volatile(
        "mma.sync.aligned.m16n8k16.row.col.f32.bf16.bf16.f32 "
        "{%0,%1,%2,%3},{%4,%5,%6,%7},{%8,%9},{%0,%1,%2,%3};"
        : "+f"(d[0]), "+f"(d[1]), "+f"(d[2]), "+f"(d[3])
        : "r"(a[0]), "r"(a[1]), "r"(a[2]), "r"(a[3]), "r"(b[0]), "r"(b[1]));
}
__device__ __forceinline__ uint32_t pack2(__nv_bfloat16 x, __nv_bfloat16 y) {
    uint32_t lo = __bfloat16_as_ushort(x);
    uint32_t hi = __bfloat16_as_ushort(y);
    return lo | (hi << 16);
}
__device__ __forceinline__ void cp16(uint32_t dst, const void* src, uint32_t sz) {
    asm volatile("cp.async.cg.shared.global [%0], [%1], 16, %2;"
                 :: "r"(dst), "l"(src), "r"(sz) : "memory");
}
__device__ __forceinline__ void cvt_store(float4 v, __nv_bfloat16* hi, __nv_bfloat16* lo) {
    __nv_bfloat16 h0 = __float2bfloat16_rn(v.x), h1 = __float2bfloat16_rn(v.y);
    __nv_bfloat16 h2 = __float2bfloat16_rn(v.z), h3 = __float2bfloat16_rn(v.w);
    uint2 hv, lv;
    hv.x = pack2(h0, h1); hv.y = pack2(h2, h3);
    lv.x = pack2(__float2bfloat16_rn(v.x - __bfloat162float(h0)),
                 __float2bfloat16_rn(v.y - __bfloat162float(h1)));
    lv.y = pack2(__float2bfloat16_rn(v.z - __bfloat162float(h2)),
                 __float2bfloat16_rn(v.w - __bfloat162float(h3)));
    *(uint2*)hi = hv; *(uint2*)lo = lv;
}
// unpack 8 fp16 (one uint4) to 8 floats
__device__ __forceinline__ void unpack8(uint4 v, float* f) {
    float2 t;
    t = __half22float2(*(__half2*)&v.x); f[0] = t.x; f[1] = t.y;
    t = __half22float2(*(__half2*)&v.y); f[2] = t.x; f[3] = t.y;
    t = __half22float2(*(__half2*)&v.z); f[4] = t.x; f[5] = t.y;
    t = __half22float2(*(__half2*)&v.w); f[6] = t.x; f[7] = t.y;
}
// convert 8 fp16 (one uint4) to 8 bf16 hi + 8 bf16 lo in smem
__device__ __forceinline__ void cvt8_h2b(uint4 v, __nv_bfloat16* hi, __nv_bfloat16* lo) {
    uint32_t uu[4] = { v.x, v.y, v.z, v.w };
    uint32_t* ho = (uint32_t*)hi;
    uint32_t* lo32 = (uint32_t*)lo;
#pragma unroll
    for (int i = 0; i < 4; i++) {
        float2 f = __half22float2(*(__half2*)&uu[i]);
        __nv_bfloat16 b0 = __float2bfloat16_rn(f.x), b1 = __float2bfloat16_rn(f.y);
        ho[i] = pack2(b0, b1);
        lo32[i] = pack2(__float2bfloat16_rn(f.x - __bfloat162float(b0)),
                        __float2bfloat16_rn(f.y - __bfloat162float(b1)));
    }
}

// ===================== split: fp32 -> bf16 hi/lo ==============================
__global__ void split_x_kernel(const float* __restrict__ x) {
    int i = blockIdx.x * blockDim.x + threadIdx.x;
    if (i >= NN * IN_DIM / 4) return;
    cvt_store(((const float4*)x)[i], g_xhi + i * 4, g_xlo + i * 4);
}
__global__ void split_w_kernel(const float* __restrict__ w) {
    int i = blockIdx.x * blockDim.x + threadIdx.x;
    if (i >= IN_DIM * HC1 / 4) return;
    cvt_store(((const float4*)w)[i], g_whi + i * 4, g_wlo + i * 4);
}
__global__ void split_w2_kernel(const float* __restrict__ w) {
    int i = blockIdx.x * blockDim.x + threadIdx.x;
    if (i >= HC1 * C2 / 4) return;
    cvt_store(((const float4*)w)[i], g_w2hi + i * 4, g_w2lo + i * 4);
}

// ======== GEMM1: xl1 = x @ W1, bf16 3-split, cp.async double-buffered ========
#define ASTR 40     // bf16 per A smem row (32 + 8 pad)
#define BSTR 136    // bf16 per B smem row (128 + 8 pad)
#define OFF_AHI 0
#define OFF_ALO 10240
#define OFF_BHI 20480
#define OFF_BLO 29184
#define STAGE   37888
#define GEMM1_SMEM (2 * STAGE)

__global__ void __launch_bounds__(256, 2) gemm1_mma_kernel(const float* __restrict__ attS1,
                                                           const float* __restrict__ attD1) {
    extern __shared__ __align__(16) char smem[];
    const uint32_t sbase = smem_u32(smem);
    const int tid = threadIdx.x, wid = tid >> 5, lane = tid & 31;
    const int warpM = (wid & 3) * 32;
    const int warpN = (wid >> 2) * 64;
    const int mBase = blockIdx.x * 128;
    const int nBase = blockIdx.y * 128;

    float acc[2][8][4];
#pragma unroll
    for (int mi = 0; mi < 2; mi++)
#pragma unroll
        for (int ni = 0; ni < 8; ni++)
#pragma unroll
            for (int q = 0; q < 4; q++) acc[mi][ni][q] = 0.f;

    auto load_stage = [&](int ch, int buf) {
        const int k0 = ch * 32;
        const uint32_t sb = sbase + buf * STAGE;
#pragma unroll
        for (int it = 0; it < 2; it++) {
            int chunk = it * 256 + tid;
            int r = chunk >> 2, c = (chunk & 3) * 8;
            int gr = mBase + r;
            uint32_t sz = (gr < NN) ? 16u : 0u;
            int grc = gr < NN ? gr : NN - 1;
            uint32_t so = (uint32_t)(r * ASTR + c) * 2;
            cp16(sb + OFF_AHI + so, &g_xhi[(size_t)grc * IN_DIM + k0 + c], sz);
            cp16(sb + OFF_ALO + so, &g_xlo[(size_t)grc * IN_DIM + k0 + c], sz);
        }
#pragma unroll
        for (int it = 0; it < 2; it++) {
            int chunk = it * 256 + tid;
            int r = chunk >> 4, c = (chunk & 15) * 8;
            uint32_t so = (uint32_t)(r * BSTR + c) * 2;
            cp16(sb + OFF_BHI + so, &g_whi[(size_t)(k0 + r) * HC1 + nBase + c], 16);
            cp16(sb + OFF_BLO + so, &g_wlo[(size_t)(k0 + r) * HC1 + nBase + c], 16);
        }
        asm volatile("cp.async.commit_group;" ::: "memory");
    };

    load_stage(0, 0);
    for (int ch = 0; ch < 8; ch++) {
        const int buf = ch & 1;
        if (ch + 1 < 8) {
            load_stage(ch + 1, buf ^ 1);
            asm volatile("cp.async.wait_group 1;" ::: "memory");
        } else {
            asm volatile("cp.async.wait_group 0;" ::: "memory");
        }
        __syncthreads();
        const uint32_t sb = sbase + buf * STAGE;
#pragma unroll
        for (int ks = 0; ks < 2; ks++) {
            uint32_t ah[2][4], al[2][4];
#pragma unroll
            for (int mi = 0; mi < 2; mi++) {
                int row = warpM + mi * 16 + (lane & 15);
                int col = ks * 16 + (lane >> 4) * 8;
                uint32_t off = (uint32_t)(row * ASTR + col) * 2;
                ldsm_x4(sb + OFF_AHI + off, ah[mi][0], ah[mi][1], ah[mi][2], ah[mi][3]);
                ldsm_x4(sb + OFF_ALO + off, al[mi][0], al[mi][1], al[mi][2], al[mi][3]);
            }
            uint32_t bh[8][2], bl[8][2];
#pragma unroll
            for (int np = 0; np < 4; np++) {
                int krow = ks * 16 + (lane & 15);
                int col = warpN + np * 16 + (lane >> 4) * 8;
                uint32_t off = (uint32_t)(krow * BSTR + col) * 2;
                ldsm_x4_trans(sb + OFF_BHI + off, bh[np * 2][0], bh[np * 2][1],
                              bh[np * 2 + 1][0], bh[np * 2 + 1][1]);
                ldsm_x4_trans(sb + OFF_BLO + off, bl[np * 2][0], bl[np * 2][1],
                              bl[np * 2 + 1][0], bl[np * 2 + 1][1]);
            }
#pragma unroll
            for (int mi = 0; mi < 2; mi++)
#pragma unroll
                for (int ni = 0; ni < 8; ni++) {
                    mma16816(acc[mi][ni], ah[mi], bh[ni]);
                    mma16816(acc[mi][ni], ah[mi], bl[ni]);
                    mma16816(acc[mi][ni], al[mi], bh[ni]);
                }
        }
        __syncthreads();
    }

    // ---- epilogue 1: store xl1 (fp16) ----
#pragma unroll
    for (int mi = 0; mi < 2; mi++) {
#pragma unroll
        for (int ni = 0; ni < 8; ni++) {
            int row0 = mBase + warpM + mi * 16 + (lane >> 2);
            int col = nBase + warpN + ni * 8 + (lane & 3) * 2;
            if (row0 < NN)
                *(__half2*)(&g_xl1h[(size_t)row0 * HC1 + col]) =
                    __floats2half2_rn(acc[mi][ni][0], acc[mi][ni][1]);
            int row1 = row0 + 8;
            if (row1 < NN)
                *(__half2*)(&g_xl1h[(size_t)row1 * HC1 + col]) =
                    __floats2half2_rn(acc[mi][ni][2], acc[mi][ni][3]);
        }
    }

    // ---- epilogue 2: fused a_src / a_dst (warp owns one complete head) ----
    {
        const int h = blockIdx.y * 2 + (wid >> 2);
        float sS[8][2], sD[8][2];
        int cb = h * C1 + (lane & 3) * 2;
#pragma unroll
        for (int ni = 0; ni < 8; ni++) {
            sS[ni][0] = __ldg(&attS1[cb + ni * 8]);
            sS[ni][1] = __ldg(&attS1[cb + ni * 8 + 1]);
            sD[ni][0] = __ldg(&attD1[cb + ni * 8]);
            sD[ni][1] = __ldg(&attD1[cb + ni * 8 + 1]);
        }
#pragma unroll
        for (int mi = 0; mi < 2; mi++) {
            float rs0 = 0.f, rs1 = 0.f, rd0 = 0.f, rd1 = 0.f;
#pragma unroll
            for (int ni = 0; ni < 8; ni++) {
                rs0 = fmaf(acc[mi][ni][0], sS[ni][0], fmaf(acc[mi][ni][1], sS[ni][1], rs0));
                rd0 = fmaf(acc[mi][ni][0], sD[ni][0], fmaf(acc[mi][ni][1], sD[ni][1], rd0));
                rs1 = fmaf(acc[mi][ni][2], sS[ni][0], fmaf(acc[mi][ni][3], sS[ni][1], rs1));
                rd1 = fmaf(acc[mi][ni][2], sD[ni][0], fmaf(acc[mi][ni][3], sD[ni][1], rd1));
            }
#pragma unroll
            for (int off = 1; off <= 2; off <<= 1) {
                rs0 += __shfl_xor_sync(0xffffffffu, rs0, off);
                rd0 += __shfl_xor_sync(0xffffffffu, rd0, off);
                rs1 += __shfl_xor_sync(0xffffffffu, rs1, off);
                rd1 += __shfl_xor_sync(0xffffffffu, rd1, off);
            }
            if ((lane & 3) == 0) {
                int row0 = mBase + warpM + mi * 16 + (lane >> 2);
                if (row0 < NN) { g_as1[row0 * 8 + h] = rs0; g_ad1[row0 * 8 + h] = rd0; }
                int row1 = row0 + 8;
                if (row1 < NN) { g_as1[row1 * 8 + h] = rs1; g_ad1[row1 * 8 + h] = rd1; }
            }
        }
    }
}

// ---------------------------- CSR construction -------------------------------
__global__ void hist_kernel(const int* __restrict__ dst) {
    int e = blockIdx.x * blockDim.x + threadIdx.x;
    if (e < EE) atomicAdd(&g_deg[dst[e]], 1);
}
__global__ void scanA_kernel() {
    __shared__ int sh[1024];
    int i = blockIdx.x * 1024 + threadIdx.x;
    int v = (i < NN) ? g_deg[i] : 0;
    sh[threadIdx.x] = v;
    __syncthreads();
#pragma unroll
    for (int off = 1; off < 1024; off <<= 1) {
        int t = (threadIdx.x >= off) ? sh[threadIdx.x - off] : 0;
        __syncthreads();
        sh[threadIdx.x] += t;
        __syncthreads();
    }
    g_incl[i] = sh[threadIdx.x];
    if (threadIdx.x == 1023) g_bsum[blockIdx.x] = sh[1023];
}
__global__ void scanB_kernel() {   // 1 block, 64 threads
    __shared__ int sh[64];
    int t = threadIdx.x;
    int v = (t < SCAN_BLOCKS) ? g_bsum[t] : 0;
    sh[t] = v;
    __syncthreads();
#pragma unroll
    for (int off = 1; off < 64; off <<= 1) {
        int u = (t >= off) ? sh[t - off] : 0;
        __syncthreads();
        sh[t] += u;
        __syncthreads();
    }
    if (t < SCAN_BLOCKS) g_boff[t] = sh[t] - v;   // exclusive
}
__global__ void scanC_kernel() {
    int i = blockIdx.x * 1024 + threadIdx.x;
    if (i < NN) {
        int ex = g_boff[blockIdx.x] + g_incl[i] - g_deg[i];
        g_rowptr[i] = ex;
        g_cursor[i] = ex;
    }
    if (i == 0) g_rowptr[NN] = EE;
}
__global__ void scatter_kernel(const int* __restrict__ src, const int* __restrict__ dst) {
    int e = blockIdx.x * blockDim.x + threadIdx.x;
    if (e >= EE) return;
    int d = dst[e];
    int pos = atomicAdd(&g_cursor[d], 1);
    g_csrc[pos] = src[e];
}

// ---- layer-1 fused softmax+aggregation: warp per node, all heads (fp16 in) ---
__global__ void agg1_kernel(const float* __restrict__ b1, int nodeBeg, int nodeEnd) {
    int w = nodeBeg + ((blockIdx.x * blockDim.x + threadIdx.x) >> 5);
    int lane = threadIdx.x & 31;
    if (w >= nodeEnd) return;
    const int h = lane >> 2;
    const int e4 = lane & 3;
    const int idx8 = w * 8 + h;
    const float ad = g_ad1[idx8];
    const float pself = __expf(lrelu(g_as1[idx8] + ad));

    float acc[16];
    {
        const uint4* xr = (const uint4*)(g_xl1h + (size_t)w * HC1 + lane * 16);
        uint4 v0 = xr[0], v1 = xr[1];
        unpack8(v0, acc); unpack8(v1, acc + 8);
#pragma unroll
        for (int i = 0; i < 16; i++) acc[i] *= pself;
    }
    float dacc = 0.f;

    const int beg = g_rowptr[w], end = g_rowptr[w + 1];
    for (int j0 = beg; j0 < end; j0 += 4) {
        int j = j0 + e4;
        bool valid = j < end;
        int s_l = valid ? g_csrc[j] : 0;
        float p_l = 0.f;
        if (valid) p_l = __expf(lrelu(__ldg(&g_as1[s_l * 8 + h]) + ad));
        dacc += p_l;
        int cnt = end - j0;
        int qb = lane & 28;
#pragma unroll
        for (int t = 0; t < 4; t++) {
            if (t < cnt) {
                float p = __shfl_sync(0xffffffffu, p_l, qb | t);
                int   s = __shfl_sync(0xffffffffu, s_l, qb | t);
                const uint4* sr = (const uint4*)(g_xl1h + (size_t)s * HC1 + lane * 16);
                uint4 u0 = sr[0], u1 = sr[1];
                float bq[16];
                unpack8(u0, bq); unpack8(u1, bq + 8);
#pragma unroll
                for (int i = 0; i < 16; i++) acc[i] = fmaf(p, bq[i], acc[i]);
            }
        }
    }
    dacc += __shfl_xor_sync(0xffffffffu, dacc, 1);
    dacc += __shfl_xor_sync(0xffffffffu, dacc, 2);
    float inv = 1.f / (dacc + pself + 1e-16f);

    float bv[16];
    {
        const float4* bb = (const float4*)(b1 + lane * 16);
        float4 t0 = bb[0], t1 = bb[1], t2 = bb[2], t3 = bb[3];
        bv[0] = t0.x; bv[1] = t0.y; bv[2]  = t0.z; bv[3]  = t0.w;
        bv[4] = t1.x; bv[5] = t1.y; bv[6]  = t1.z; bv[7]  = t1.w;
        bv[8] = t2.x; bv[9] = t2.y; bv[10] = t2.z; bv[11] = t2.w;
        bv[12] = t3.x; bv[13] = t3.y; bv[14] = t3.z; bv[15] = t3.w;
    }
    uint32_t r[8];
#pragma unroll
    for (int i = 0; i < 8; i++) {
        float f0 = fmaxf(fmaf(acc[2 * i],     inv, bv[2 * i]),     0.f);
        float f1 = fmaxf(fmaf(acc[2 * i + 1], inv, bv[2 * i + 1]), 0.f);
        __half2 hh = __floats2half2_rn(f0, f1);
        r[i] = *(uint32_t*)&hh;
    }
    uint4* hw = (uint4*)(g_h1h + (size_t)w * HC1 + lane * 16);
    hw[0] = make_uint4(r[0], r[1], r[2], r[3]);
    hw[1] = make_uint4(r[4], r[5], r[6], r[7]);
}

// ==== GEMM2 on tensor cores: xl2 = h1 @ W2 (rows [nodeBeg,nodeEnd)) ==========
#define A2STR 40
#define B2STR 40
__global__ void __launch_bounds__(256) gemm2_mma_kernel(const float* __restrict__ attS2,
                                                        const float* __restrict__ attD2,
                                                        int nodeBeg, int nodeEnd) {
    __shared__ __align__(16) __nv_bfloat16 sAhi[128 * A2STR], sAlo[128 * A2STR];
    __shared__ __align__(16) __nv_bfloat16 sBhi[32 * B2STR],  sBlo[32 * B2STR];
    const int tid = threadIdx.x, wid = tid >> 5, lane = tid & 31;
    const int mBase = nodeBeg + blockIdx.x * 128;
    const int warpM = wid * 16;

    const int ar = tid >> 1, ak = (tid & 1) * 16;
    int grow = mBase + ar; if (grow >= nodeEnd) grow = nodeEnd - 1;
    const __half* abase = g_h1h + (size_t)grow * HC1 + ak;
    const bool bhi_role = tid < 128;
    const int bk = (tid & 127) >> 2, bseg = (tid & 3) * 8;
    const __nv_bfloat16* bsrc = (bhi_role ? g_w2hi : g_w2lo) + bk * C2 + bseg;

    float acc[4][4];
#pragma unroll
    for (int ni = 0; ni < 4; ni++)
#pragma unroll
        for (int q = 0; q < 4; q++) acc[ni][q] = 0.f;

    uint4 ra0 = *(const uint4*)(abase);      // 8 fp16
    uint4 ra1 = *(const uint4*)(abase + 8);  // 8 fp16
    uint4 rb = *(const uint4*)bsrc;

    const uint32_t sAhiB = smem_u32(sAhi), sAloB = smem_u32(sAlo);
    const uint32_t sBhiB = smem_u32(sBhi), sBloB = smem_u32(sBlo);

    for (int ch = 0; ch < 16; ch++) {
        __nv_bfloat16* ah = &sAhi[ar * A2STR + ak];
        __nv_bfloat16* al = &sAlo[ar * A2STR + ak];
        cvt8_h2b(ra0, ah + 0, al + 0);
        cvt8_h2b(ra1, ah + 8, al + 8);
        __nv_bfloat16* bdst = (bhi_role ? sBhi : sBlo) + bk * B2STR + bseg;
        *(uint4*)bdst = rb;
        __syncthreads();
        if (ch < 15) {
            const __half* an = abase + (ch + 1) * 32;
            ra0 = *(const uint4*)(an);
            ra1 = *(const uint4*)(an + 8);
            rb = *(const uint4*)(bsrc + (size_t)(ch + 1) * 32 * C2);
        }
#pragma unroll
        for (int ks = 0; ks < 2; ks++) {
            uint32_t ah4[4], al4[4];
            int row = warpM + (lane & 15);
            int col = ks * 16 + (lane >> 4) * 8;
            uint32_t offA = (uint32_t)(row * A2STR + col) * 2;
            ldsm_x4(sAhiB + offA, ah4[0], ah4[1], ah4[2], ah4[3]);
            ldsm_x4(sAloB + offA, al4[0], al4[1], al4[2], al4[3]);
            uint32_t bh[4][2], bl[4][2];
            int krow = ks * 16 + (lane & 15);
#pragma unroll
            for (int np = 0; np < 2; np++) {
                int bcol = np * 16 + (lane >> 4) * 8;
                uint32_t offB = (uint32_t)(krow * B2STR + bcol) * 2;
                ldsm_x4_trans(sBhiB + offB, bh[np * 2][0], bh[np * 2][1],
                              bh[np * 2 + 1][0], bh[np * 2 + 1][1]);
                ldsm_x4_trans(sBloB + offB, bl[np * 2][0], bl[np * 2][1],
                              bl[np * 2 + 1][0], bl[np * 2 + 1][1]);
            }
#pragma unroll
            for (int ni = 0; ni < 4; ni++) {
                mma16816(acc[ni], ah4, bh[ni]);
                mma16816(acc[ni], ah4, bl[ni]);
                mma16816(acc[ni], al4, bh[ni]);
            }
        }
        __syncthreads();
    }

    int row0 = mBase + warpM + (lane >> 2);
    int row1 = row0 + 8;
    float rs0 = 0.f, rd0 = 0.f, rs1 = 0.f, rd1 = 0.f;
#pragma unroll
    for (int ni = 0; ni < 4; ni++) {
        int col = ni * 8 + (lane & 3) * 2;
        if (row0 < nodeEnd)
            *(float2*)(&g_xl2[(size_t)row0 * C2 + col]) = make_float2(acc[ni][0], acc[ni][1]);
        if (row1 < nodeEnd)
            *(float2*)(&g_xl2[(size_t)row1 * C2 + col]) = make_float2(acc[ni][2], acc[ni][3]);
        float s0 = __ldg(&attS2[col]), s1 = __ldg(&attS2[col + 1]);
        float d0 = __ldg(&attD2[col]), d1 = __ldg(&attD2[col + 1]);
        rs0 = fmaf(acc[ni][0], s0, fmaf(acc[ni][1], s1, rs0));
        rd0 = fmaf(acc[ni][0], d0, fmaf(acc[ni][1], d1, rd0));
        rs1 = fmaf(acc[ni][2], s0, fmaf(acc[ni][3], s1, rs1));
        rd1 = fmaf(acc[ni][2], d0, fmaf(acc[ni][3], d1, rd1));
    }
#pragma unroll
    for (int off = 1; off <= 2; off <<= 1) {
        rs0 += __shfl_xor_sync(0xffffffffu, rs0, off);
        rd0 += __shfl_xor_sync(0xffffffffu, rd0, off);
        rs1 += __shfl_xor_sync(0xffffffffu, rs1, off);
        rd1 += __shfl_xor_sync(0xffffffffu, rd1, off);
    }
    if ((lane & 3) == 0) {
        if (row0 < nodeEnd) { g_as2[row0] = rs0; g_ad2[row0] = rd0; }
        if (row1 < nodeEnd) { g_as2[row1] = rs1; g_ad2[row1] = rd1; }
    }
}

// ---- layer-2 fused softmax+aggregation + fc head: warp per node --------------
__global__ void __launch_bounds__(256) agg2_kernel(const float* __restrict__ b2,
                                                   const float* __restrict__ fcW,
                                                   const float* __restrict__ fcb,
                                                   float* __restrict__ out) {
    __shared__ float fs[C2 * OUT_DIM];
    __shared__ float fb[OUT_DIM];
    for (int i = threadIdx.x; i < C2 * OUT_DIM; i += 256) fs[i] = fcW[i];
    if (threadIdx.x < OUT_DIM) fb[threadIdx.x] = fcb[threadIdx.x];
    __syncthreads();

    int w = (blockIdx.x * blockDim.x + threadIdx.x) >> 5;
    int lane = threadIdx.x & 31;
    if (w >= NN) return;
    float ad = g_ad2[w];
    float pself = __expf(lrelu(g_as2[w] + ad));
    float acc = pself * g_xl2[(size_t)w * C2 + lane];
    float dacc = 0.f;
    int beg = g_rowptr[w], end = g_rowptr[w + 1];
    for (int j0 = beg; j0 < end; j0 += 32) {
        int j = j0 + lane;
        bool valid = j < end;
        int s_l = valid ? g_csrc[j] : 0;
        float p_l = 0.f;
        if (valid) p_l = __expf(lrelu(__ldg(&g_as2[s_l]) + ad));
        dacc += p_l;
        int cnt = end - j0;
        if (cnt > 32) cnt = 32;
        for (int t = 0; t < cnt; t++) {
            float p = __shfl_sync(0xffffffffu, p_l, t);
            int   s = __shfl_sync(0xffffffffu, s_l, t);
            acc = fmaf(p, g_xl2[(size_t)s * C2 + lane], acc);
        }
    }
#pragma unroll
    for (int off = 16; off; off >>= 1) dacc += __shfl_xor_sync(0xffffffffu, dacc, off);
    float inv = 1.f / (dacc + pself + 1e-16f);
    float emb = fmaxf(fmaf(acc, inv, b2[lane]), 0.f);
    out[(size_t)w * C2 + lane] = emb;

    float l1 = fb[lane];
    float l2 = (lane < OUT_DIM - 32) ? fb[32 + lane] : 0.f;
#pragma unroll
    for (int c = 0; c < C2; c++) {
        float e = __shfl_sync(0xffffffffu, emb, c);
        l1 = fmaf(e, fs[c * OUT_DIM + lane], l1);
        if (lane < OUT_DIM - 32) l2 = fmaf(e, fs[c * OUT_DIM + 32 + lane], l2);
    }
    float* lg = out + (size_t)NN * C2 + (size_t)w * OUT_DIM;
    lg[lane] = l1;
    if (lane < OUT_DIM - 32) lg[32 + lane] = l2;
}

// ------------------------------------------------------------------------------
extern "C" void kernel_launch(void* const* d_in, const int* in_sizes, int n_in,
                              void* d_out, int out_size) {
    const float* x     = (const float*)d_in[0];
    const int*   ei    = (const int*)  d_in[1];
    const float* W1    = (const float*)d_in[2];
    const float* attS1 = (const float*)d_in[3];
    const float* attD1 = (const float*)d_in[4];
    const float* b1    = (const float*)d_in[5];
    const float* W2    = (const float*)d_in[6];
    const float* attS2 = (const float*)d_in[7];
    const float* attD2 = (const float*)d_in[8];
    const float* b2    = (const float*)d_in[9];
    const float* fcW   = (const float*)d_in[10];
    const float* fcb   = (const float*)d_in[11];
    float* out = (float*)d_out;

    const int* src = ei;
    const int* dst = ei + EE;

    // fixed auxiliary stream + events (created once; same captured DAG each call)
    static cudaStream_t sB = [] { cudaStream_t s; cudaStreamCreateWithFlags(&s, cudaStreamNonBlocking); return s; }();
    static cudaEvent_t evFork = [] { cudaEvent_t e; cudaEventCreateWithFlags(&e, cudaEventDisableTiming); return e; }();
    static cudaEvent_t evCSR  = [] { cudaEvent_t e; cudaEventCreateWithFlags(&e, cudaEventDisableTiming); return e; }();
    static cudaEvent_t evG1   = [] { cudaEvent_t e; cudaEventCreateWithFlags(&e, cudaEventDisableTiming); return e; }();
    static cudaEvent_t evHi   = [] { cudaEvent_t e; cudaEventCreateWithFlags(&e, cudaEventDisableTiming); return e; }();

    cudaFuncSetAttribute(gemm1_mma_kernel, cudaFuncAttributeMaxDynamicSharedMemorySize,
                         GEMM1_SMEM);

    // ---- fork: CSR chain + w2 split on stream B, shadowed by gemm1 ----
    cudaEventRecord(evFork, 0);
    cudaStreamWaitEvent(sB, evFork, 0);

    void* degp = nullptr;
    cudaGetSymbolAddress(&degp, g_deg);
    cudaMemsetAsync(degp, 0, NN * sizeof(int), sB);
    hist_kernel<<<(EE + 255) / 256, 256, 0, sB>>>(dst);
    scanA_kernel<<<SCAN_BLOCKS, 1024, 0, sB>>>();
    scanB_kernel<<<1, 64, 0, sB>>>();
    scanC_kernel<<<SCAN_BLOCKS, 1024, 0, sB>>>();
    scatter_kernel<<<(EE + 255) / 256, 256, 0, sB>>>(src, dst);
    split_w2_kernel<<<(HC1 * C2 / 4 + 255) / 256, 256, 0, sB>>>(W2);
    cudaEventRecord(evCSR, sB);

    // ---- main stream: splits + gemm1 ----
    split_x_kernel<<<(NN * IN_DIM / 4 + 255) / 256, 256>>>(x);
    split_w_kernel<<<(IN_DIM * HC1 / 4 + 255) / 256, 256>>>(W1);
    {
        dim3 grid((NN + 127) / 128, HC1 / 128);
        gemm1_mma_kernel<<<grid, 256, GEMM1_SMEM>>>(attS1, attD1);
    }
    cudaEventRecord(evG1, 0);

    // ---- layer 1 agg + layer 2 gemm, pipelined in node halves ----
    cudaStreamWaitEvent(0, evCSR, 0);
    agg1_kernel<<<(NHALF * 32 + 255) / 256, 256>>>(b1, 0, NHALF);
    gemm2_mma_kernel<<<NHALF / 128, 256>>>(attS2, attD2, 0, NHALF);

    cudaStreamWaitEvent(sB, evG1, 0);
    agg1_kernel<<<((NN - NHALF) * 32 + 255) / 256, 256, 0, sB>>>(b1, NHALF, NN);
    gemm2_mma_kernel<<<(NN - NHALF + 127) / 128, 256, 0, sB>>>(attS2, attD2, NHALF, NN);
    cudaEventRecord(evHi, sB);

    // ---- join, then layer-2 agg + fused fc head ----
    cudaStreamWaitEvent(0, evHi, 0);
    agg2_kernel<<<(NN * 32 + 255) / 256, 256>>>(b2, fcW, fcb, out);
}

// round 9
// speedup vs baseline: 3.7625x; 1.1326x over previous
#include <cuda_runtime.h>
#include <cuda_bf16.h>
#include <cuda_fp16.h>
#include <cstdint>

// Problem constants (fixed by the dataset)
#define NN      50000
#define EE      800000
#define IN_DIM  256
#define HEADS   8
#define C1      64
#define HC1     512          // HEADS*C1
#define C2      32
#define OUT_DIM 40
#define NEG_SLOPE 0.2f

#define SCAN_BLOCKS 49       // 49 * 1024 >= NN
#define NHALF 25088          // 196 * 128, split point for layer pipelining

// ---------------- scratch (device globals; no cudaMalloc allowed) ------------
__device__ __half g_xl1h[(size_t)NN * HC1];   // x @ W1  (fp16)
__device__ __half g_h1h [(size_t)NN * HC1];   // layer-1 output, relu (fp16)
__device__ __half g_xh  [(size_t)NN * IN_DIM];   // x in fp16
__device__ __half g_w1hi[(size_t)IN_DIM * HC1];  // W1 fp16 hi
__device__ __half g_w1lo[(size_t)IN_DIM * HC1];  // W1 fp16 residual
__device__ __half g_w2hi[HC1 * C2];
__device__ __half g_w2lo[HC1 * C2];
__device__ float g_as1[NN * HEADS];
__device__ float g_ad1[NN * HEADS];
__device__ float g_xl2[(size_t)NN * C2];
__device__ float g_as2[NN], g_ad2[NN];
__device__ int   g_deg[NN];
__device__ int   g_incl[SCAN_BLOCKS * 1024];
__device__ int   g_bsum[SCAN_BLOCKS];
__device__ int   g_boff[SCAN_BLOCKS];
__device__ int   g_rowptr[NN + 1];
__device__ int   g_cursor[NN];
__device__ int   g_csrc[EE];

__device__ __forceinline__ float lrelu(float x) { return x > 0.f ? x : NEG_SLOPE * x; }

// ========================= PTX helpers =========================
__device__ __forceinline__ uint32_t smem_u32(const void* p) {
    uint32_t a;
    asm("{ .reg .u64 t; cvta.to.shared.u64 t, %1; cvt.u32.u64 %0, t; }" : "=r"(a) : "l"(p));
    return a;
}
__device__ __forceinline__ void ldsm_x4(uint32_t addr, uint32_t& r0, uint32_t& r1,
                                        uint32_t& r2, uint32_t& r3) {
    asm volatile("ldmatrix.sync.aligned.m8n8.x4.shared.b16 {%0,%1,%2,%3}, [%4];"
                 : "=r"(r0), "=r"(r1), "=r"(r2), "=r"(r3) : "r"(addr));
}
__device__ __forceinline__ void ldsm_x4_trans(uint32_t addr, uint32_t& r0, uint32_t& r1,
                                              uint32_t& r2, uint32_t& r3) {
    asm volatile("ldmatrix.sync.aligned.m8n8.x4.trans.shared.b16 {%0,%1,%2,%3}, [%4];"
                 : "=r"(r0), "=r"(r1), "=r"(r2), "=r"(r3) : "r"(addr));
}
__device__ __forceinline__ void mma_f16(float* d, const uint32_t* a, const uint32_t* b) {
    asm volatile(
        "mma.sync.aligned.m16n8k16.row.col.f32.f16.f16.f32 "
        "{%0,%1,%2,%3},{%4,%5,%6,%7},{%8,%9},{%0,%1,%2,%3};"
        : "+f"(d[0]), "+f"(d[1]), "+f"(d[2]), "+f"(d[3])
        : "r"(a[0]), "r"(a[1]), "r"(a[2]), "r"(a[3]), "r"(b[0]), "r"(b[1]));
}
__device__ __forceinline__ void cp16(uint32_t dst, const void* src, uint32_t sz) {
    asm volatile("cp.async.cg.shared.global [%0], [%1], 16, %2;"
                 :: "r"(dst), "l"(src), "r"(sz) : "memory");
}
// unpack 8 fp16 (one uint4) to 8 floats
__device__ __forceinline__ void unpack8(uint4 v, float* f) {
    float2 t;
    t = __half22float2(*(__half2*)&v.x); f[0] = t.x; f[1] = t.y;
    t = __half22float2(*(__half2*)&v.y); f[2] = t.x; f[3] = t.y;
    t = __half22float2(*(__half2*)&v.z); f[4] = t.x; f[5] = t.y;
    t = __half22float2(*(__half2*)&v.w); f[6] = t.x; f[7] = t.y;
}

// ===================== input prep kernels =====================================
__global__ void split_x_kernel(const float* __restrict__ x) {
    int i = blockIdx.x * blockDim.x + threadIdx.x;
    if (i >= NN * IN_DIM / 4) return;
    float4 v = ((const float4*)x)[i];
    __half2 a = __floats2half2_rn(v.x, v.y);
    __half2 b = __floats2half2_rn(v.z, v.w);
    ((uint2*)g_xh)[i] = make_uint2(*(uint32_t*)&a, *(uint32_t*)&b);
}
__device__ __forceinline__ void split_hl(float4 v, __half* hi, __half* lo) {
    __half h0 = __float2half_rn(v.x), h1 = __float2half_rn(v.y);
    __half h2 = __float2half_rn(v.z), h3 = __float2half_rn(v.w);
    __half l0 = __float2half_rn(v.x - __half2float(h0));
    __half l1 = __float2half_rn(v.y - __half2float(h1));
    __half l2 = __float2half_rn(v.z - __half2float(h2));
    __half l3 = __float2half_rn(v.w - __half2float(h3));
    __half2 p0 = __halves2half2(h0, h1), p1 = __halves2half2(h2, h3);
    __half2 q0 = __halves2half2(l0, l1), q1 = __halves2half2(l2, l3);
    *(uint2*)hi = make_uint2(*(uint32_t*)&p0, *(uint32_t*)&p1);
    *(uint2*)lo = make_uint2(*(uint32_t*)&q0, *(uint32_t*)&q1);
}
__global__ void split_w_kernel(const float* __restrict__ w) {
    int i = blockIdx.x * blockDim.x + threadIdx.x;
    if (i >= IN_DIM * HC1 / 4) return;
    split_hl(((const float4*)w)[i], g_w1hi + i * 4, g_w1lo + i * 4);
}
__global__ void split_w2_kernel(const float* __restrict__ w) {
    int i = blockIdx.x * blockDim.x + threadIdx.x;
    if (i >= HC1 * C2 / 4) return;
    split_hl(((const float4*)w)[i], g_w2hi + i * 4, g_w2lo + i * 4);
}

// ======== GEMM1: xl1 = x @ W1, fp16 A + fp16 hi/lo B, 2 MMAs per step ========
#define ASTR 40     // fp16 per A smem row (32 + 8 pad)
#define BSTR 136    // fp16 per B smem row (128 + 8 pad)
#define OFF_A   0
#define OFF_BHI 10240
#define OFF_BLO 18944
#define STAGE   27648
#define GEMM1_SMEM (2 * STAGE)

__global__ void __launch_bounds__(256, 2) gemm1_mma_kernel(const float* __restrict__ attS1,
                                                           const float* __restrict__ attD1) {
    extern __shared__ __align__(16) char smem[];
    const uint32_t sbase = smem_u32(smem);
    const int tid = threadIdx.x, wid = tid >> 5, lane = tid & 31;
    const int warpM = (wid & 3) * 32;
    const int warpN = (wid >> 2) * 64;
    const int mBase = blockIdx.x * 128;
    const int nBase = blockIdx.y * 128;

    float acc[2][8][4];
#pragma unroll
    for (int mi = 0; mi < 2; mi++)
#pragma unroll
        for (int ni = 0; ni < 8; ni++)
#pragma unroll
            for (int q = 0; q < 4; q++) acc[mi][ni][q] = 0.f;

    auto load_stage = [&](int ch, int buf) {
        const int k0 = ch * 32;
        const uint32_t sb = sbase + buf * STAGE;
        // A: 128 rows x 32 k fp16 = 512 x 16B chunks... actually 128*64B = 512 chunks/16B? 128*4=512
#pragma unroll
        for (int it = 0; it < 2; it++) {
            int chunk = it * 256 + tid;          // 512 chunks
            int r = chunk >> 2, c = (chunk & 3) * 8;
            int gr = mBase + r;
            uint32_t sz = (gr < NN) ? 16u : 0u;
            int grc = gr < NN ? gr : NN - 1;
            uint32_t so = (uint32_t)(r * ASTR + c) * 2;
            cp16(sb + OFF_A + so, &g_xh[(size_t)grc * IN_DIM + k0 + c], sz);
        }
        // B: 32 k-rows x 128 n fp16 per buffer = 512 chunks each
#pragma unroll
        for (int it = 0; it < 2; it++) {
            int chunk = it * 256 + tid;
            int r = chunk >> 4, c = (chunk & 15) * 8;
            uint32_t so = (uint32_t)(r * BSTR + c) * 2;
            cp16(sb + OFF_BHI + so, &g_w1hi[(size_t)(k0 + r) * HC1 + nBase + c], 16);
            cp16(sb + OFF_BLO + so, &g_w1lo[(size_t)(k0 + r) * HC1 + nBase + c], 16);
        }
        asm volatile("cp.async.commit_group;" ::: "memory");
    };

    load_stage(0, 0);
    for (int ch = 0; ch < 8; ch++) {
        const int buf = ch & 1;
        if (ch + 1 < 8) {
            load_stage(ch + 1, buf ^ 1);
            asm volatile("cp.async.wait_group 1;" ::: "memory");
        } else {
            asm volatile("cp.async.wait_group 0;" ::: "memory");
        }
        __syncthreads();
        const uint32_t sb = sbase + buf * STAGE;
#pragma unroll
        for (int ks = 0; ks < 2; ks++) {
            uint32_t av[2][4];
#pragma unroll
            for (int mi = 0; mi < 2; mi++) {
                int row = warpM + mi * 16 + (lane & 15);
                int col = ks * 16 + (lane >> 4) * 8;
                uint32_t off = (uint32_t)(row * ASTR + col) * 2;
                ldsm_x4(sb + OFF_A + off, av[mi][0], av[mi][1], av[mi][2], av[mi][3]);
            }
            uint32_t bh[8][2], bl[8][2];
#pragma unroll
            for (int np = 0; np < 4; np++) {
                int krow = ks * 16 + (lane & 15);
                int col = warpN + np * 16 + (lane >> 4) * 8;
                uint32_t off = (uint32_t)(krow * BSTR + col) * 2;
                ldsm_x4_trans(sb + OFF_BHI + off, bh[np * 2][0], bh[np * 2][1],
                              bh[np * 2 + 1][0], bh[np * 2 + 1][1]);
                ldsm_x4_trans(sb + OFF_BLO + off, bl[np * 2][0], bl[np * 2][1],
                              bl[np * 2 + 1][0], bl[np * 2 + 1][1]);
            }
#pragma unroll
            for (int mi = 0; mi < 2; mi++)
#pragma unroll
                for (int ni = 0; ni < 8; ni++) {
                    mma_f16(acc[mi][ni], av[mi], bh[ni]);
                    mma_f16(acc[mi][ni], av[mi], bl[ni]);
                }
        }
        __syncthreads();
    }

    // ---- epilogue 1: store xl1 (fp16) ----
#pragma unroll
    for (int mi = 0; mi < 2; mi++) {
#pragma unroll
        for (int ni = 0; ni < 8; ni++) {
            int row0 = mBase + warpM + mi * 16 + (lane >> 2);
            int col = nBase + warpN + ni * 8 + (lane & 3) * 2;
            if (row0 < NN)
                *(__half2*)(&g_xl1h[(size_t)row0 * HC1 + col]) =
                    __floats2half2_rn(acc[mi][ni][0], acc[mi][ni][1]);
            int row1 = row0 + 8;
            if (row1 < NN)
                *(__half2*)(&g_xl1h[(size_t)row1 * HC1 + col]) =
                    __floats2half2_rn(acc[mi][ni][2], acc[mi][ni][3]);
        }
    }

    // ---- epilogue 2: fused a_src / a_dst (warp owns one complete head) ----
    {
        const int h = blockIdx.y * 2 + (wid >> 2);
        float sS[8][2], sD[8][2];
        int cb = h * C1 + (lane & 3) * 2;
#pragma unroll
        for (int ni = 0; ni < 8; ni++) {
            sS[ni][0] = __ldg(&attS1[cb + ni * 8]);
            sS[ni][1] = __ldg(&attS1[cb + ni * 8 + 1]);
            sD[ni][0] = __ldg(&attD1[cb + ni * 8]);
            sD[ni][1] = __ldg(&attD1[cb + ni * 8 + 1]);
        }
#pragma unroll
        for (int mi = 0; mi < 2; mi++) {
            float rs0 = 0.f, rs1 = 0.f, rd0 = 0.f, rd1 = 0.f;
#pragma unroll
            for (int ni = 0; ni < 8; ni++) {
                rs0 = fmaf(acc[mi][ni][0], sS[ni][0], fmaf(acc[mi][ni][1], sS[ni][1], rs0));
                rd0 = fmaf(acc[mi][ni][0], sD[ni][0], fmaf(acc[mi][ni][1], sD[ni][1], rd0));
                rs1 = fmaf(acc[mi][ni][2], sS[ni][0], fmaf(acc[mi][ni][3], sS[ni][1], rs1));
                rd1 = fmaf(acc[mi][ni][2], sD[ni][0], fmaf(acc[mi][ni][3], sD[ni][1], rd1));
            }
#pragma unroll
            for (int off = 1; off <= 2; off <<= 1) {
                rs0 += __shfl_xor_sync(0xffffffffu, rs0, off);
                rd0 += __shfl_xor_sync(0xffffffffu, rd0, off);
                rs1 += __shfl_xor_sync(0xffffffffu, rs1, off);
                rd1 += __shfl_xor_sync(0xffffffffu, rd1, off);
            }
            if ((lane & 3) == 0) {
                int row0 = mBase + warpM + mi * 16 + (lane >> 2);
                if (row0 < NN) { g_as1[row0 * 8 + h] = rs0; g_ad1[row0 * 8 + h] = rd0; }
                int row1 = row0 + 8;
                if (row1 < NN) { g_as1[row1 * 8 + h] = rs1; g_ad1[row1 * 8 + h] = rd1; }
            }
        }
    }
}

// ---------------------------- CSR construction -------------------------------
__global__ void hist_kernel(const int* __restrict__ dst) {
    int e = blockIdx.x * blockDim.x + threadIdx.x;
    if (e < EE) atomicAdd(&g_deg[dst[e]], 1);
}
__global__ void scanA_kernel() {
    __shared__ int sh[1024];
    int i = blockIdx.x * 1024 + threadIdx.x;
    int v = (i < NN) ? g_deg[i] : 0;
    sh[threadIdx.x] = v;
    __syncthreads();
#pragma unroll
    for (int off = 1; off < 1024; off <<= 1) {
        int t = (threadIdx.x >= off) ? sh[threadIdx.x - off] : 0;
        __syncthreads();
        sh[threadIdx.x] += t;
        __syncthreads();
    }
    g_incl[i] = sh[threadIdx.x];
    if (threadIdx.x == 1023) g_bsum[blockIdx.x] = sh[1023];
}
__global__ void scanB_kernel() {   // 1 block, 64 threads
    __shared__ int sh[64];
    int t = threadIdx.x;
    int v = (t < SCAN_BLOCKS) ? g_bsum[t] : 0;
    sh[t] = v;
    __syncthreads();
#pragma unroll
    for (int off = 1; off < 64; off <<= 1) {
        int u = (t >= off) ? sh[t - off] : 0;
        __syncthreads();
        sh[t] += u;
        __syncthreads();
    }
    if (t < SCAN_BLOCKS) g_boff[t] = sh[t] - v;   // exclusive
}
__global__ void scanC_kernel() {
    int i = blockIdx.x * 1024 + threadIdx.x;
    if (i < NN) {
        int ex = g_boff[blockIdx.x] + g_incl[i] - g_deg[i];
        g_rowptr[i] = ex;
        g_cursor[i] = ex;
    }
    if (i == 0) g_rowptr[NN] = EE;
}
__global__ void scatter_kernel(const int* __restrict__ src, const int* __restrict__ dst) {
    int e = blockIdx.x * blockDim.x + threadIdx.x;
    if (e >= EE) return;
    int d = dst[e];
    int pos = atomicAdd(&g_cursor[d], 1);
    g_csrc[pos] = src[e];
}

// ---- layer-1 fused softmax+aggregation: warp per node, all heads (fp16 in) ---
__global__ void agg1_kernel(const float* __restrict__ b1, int nodeBeg, int nodeEnd) {
    int w = nodeBeg + ((blockIdx.x * blockDim.x + threadIdx.x) >> 5);
    int lane = threadIdx.x & 31;
    if (w >= nodeEnd) return;
    const int h = lane >> 2;
    const int e4 = lane & 3;
    const int idx8 = w * 8 + h;
    const float ad = g_ad1[idx8];
    const float pself = __expf(lrelu(g_as1[idx8] + ad));

    float acc[16];
    {
        const uint4* xr = (const uint4*)(g_xl1h + (size_t)w * HC1 + lane * 16);
        uint4 v0 = xr[0], v1 = xr[1];
        unpack8(v0, acc); unpack8(v1, acc + 8);
#pragma unroll
        for (int i = 0; i < 16; i++) acc[i] *= pself;
    }
    float dacc = 0.f;

    const int beg = g_rowptr[w], end = g_rowptr[w + 1];
    for (int j0 = beg; j0 < end; j0 += 4) {
        int j = j0 + e4;
        bool valid = j < end;
        int s_l = valid ? g_csrc[j] : 0;
        float p_l = 0.f;
        if (valid) p_l = __expf(lrelu(__ldg(&g_as1[s_l * 8 + h]) + ad));
        dacc += p_l;
        int cnt = end - j0;
        int qb = lane & 28;
#pragma unroll
        for (int t = 0; t < 4; t++) {
            if (t < cnt) {
                float p = __shfl_sync(0xffffffffu, p_l, qb | t);
                int   s = __shfl_sync(0xffffffffu, s_l, qb | t);
                const uint4* sr = (const uint4*)(g_xl1h + (size_t)s * HC1 + lane * 16);
                uint4 u0 = sr[0], u1 = sr[1];
                float bq[16];
                unpack8(u0, bq); unpack8(u1, bq + 8);
#pragma unroll
                for (int i = 0; i < 16; i++) acc[i] = fmaf(p, bq[i], acc[i]);
            }
        }
    }
    dacc += __shfl_xor_sync(0xffffffffu, dacc, 1);
    dacc += __shfl_xor_sync(0xffffffffu, dacc, 2);
    float inv = 1.f / (dacc + pself + 1e-16f);

    float bv[16];
    {
        const float4* bb = (const float4*)(b1 + lane * 16);
        float4 t0 = bb[0], t1 = bb[1], t2 = bb[2], t3 = bb[3];
        bv[0] = t0.x; bv[1] = t0.y; bv[2]  = t0.z; bv[3]  = t0.w;
        bv[4] = t1.x; bv[5] = t1.y; bv[6]  = t1.z; bv[7]  = t1.w;
        bv[8] = t2.x; bv[9] = t2.y; bv[10] = t2.z; bv[11] = t2.w;
        bv[12] = t3.x; bv[13] = t3.y; bv[14] = t3.z; bv[15] = t3.w;
    }
    uint32_t r[8];
#pragma unroll
    for (int i = 0; i < 8; i++) {
        float f0 = fmaxf(fmaf(acc[2 * i],     inv, bv[2 * i]),     0.f);
        float f1 = fmaxf(fmaf(acc[2 * i + 1], inv, bv[2 * i + 1]), 0.f);
        __half2 hh = __floats2half2_rn(f0, f1);
        r[i] = *(uint32_t*)&hh;
    }
    uint4* hw = (uint4*)(g_h1h + (size_t)w * HC1 + lane * 16);
    hw[0] = make_uint4(r[0], r[1], r[2], r[3]);
    hw[1] = make_uint4(r[4], r[5], r[6], r[7]);
}

// ==== GEMM2: xl2 = h1 @ W2 (rows [nodeBeg,nodeEnd)), fp16 A + fp16 hi/lo B ===
#define A2STR 40
#define B2STR 40
__global__ void __launch_bounds__(256) gemm2_mma_kernel(const float* __restrict__ attS2,
                                                        const float* __restrict__ attD2,
                                                        int nodeBeg, int nodeEnd) {
    __shared__ __align__(16) __half sA[128 * A2STR];
    __shared__ __align__(16) __half sBhi[32 * B2STR], sBlo[32 * B2STR];
    const int tid = threadIdx.x, wid = tid >> 5, lane = tid & 31;
    const int mBase = nodeBeg + blockIdx.x * 128;
    const int warpM = wid * 16;

    const int ar = tid >> 1, ak = (tid & 1) * 16;
    int grow = mBase + ar; if (grow >= nodeEnd) grow = nodeEnd - 1;
    const __half* abase = g_h1h + (size_t)grow * HC1 + ak;
    const bool bhi_role = tid < 128;
    const int bk = (tid & 127) >> 2, bseg = (tid & 3) * 8;
    const __half* bsrc = (bhi_role ? g_w2hi : g_w2lo) + bk * C2 + bseg;

    float acc[4][4];
#pragma unroll
    for (int ni = 0; ni < 4; ni++)
#pragma unroll
        for (int q = 0; q < 4; q++) acc[ni][q] = 0.f;

    uint4 ra0 = *(const uint4*)(abase);      // 8 fp16
    uint4 ra1 = *(const uint4*)(abase + 8);  // 8 fp16
    uint4 rb = *(const uint4*)bsrc;

    const uint32_t sAB = smem_u32(sA);
    const uint32_t sBhiB = smem_u32(sBhi), sBloB = smem_u32(sBlo);

    for (int ch = 0; ch < 16; ch++) {
        *(uint4*)(&sA[ar * A2STR + ak])     = ra0;
        *(uint4*)(&sA[ar * A2STR + ak + 8]) = ra1;
        __half* bdst = (bhi_role ? sBhi : sBlo) + bk * B2STR + bseg;
        *(uint4*)bdst = rb;
        __syncthreads();
        if (ch < 15) {
            const __half* an = abase + (ch + 1) * 32;
            ra0 = *(const uint4*)(an);
            ra1 = *(const uint4*)(an + 8);
            rb = *(const uint4*)(bsrc + (size_t)(ch + 1) * 32 * C2);
        }
#pragma unroll
        for (int ks = 0; ks < 2; ks++) {
            uint32_t av[4];
            int row = warpM + (lane & 15);
            int col = ks * 16 + (lane >> 4) * 8;
            uint32_t offA = (uint32_t)(row * A2STR + col) * 2;
            ldsm_x4(sAB + offA, av[0], av[1], av[2], av[3]);
            uint32_t bh[4][2], bl[4][2];
            int krow = ks * 16 + (lane & 15);
#pragma unroll
            for (int np = 0; np < 2; np++) {
                int bcol = np * 16 + (lane >> 4) * 8;
                uint32_t offB = (uint32_t)(krow * B2STR + bcol) * 2;
                ldsm_x4_trans(sBhiB + offB, bh[np * 2][0], bh[np * 2][1],
                              bh[np * 2 + 1][0], bh[np * 2 + 1][1]);
                ldsm_x4_trans(sBloB + offB, bl[np * 2][0], bl[np * 2][1],
                              bl[np * 2 + 1][0], bl[np * 2 + 1][1]);
            }
#pragma unroll
            for (int ni = 0; ni < 4; ni++) {
                mma_f16(acc[ni], av, bh[ni]);
                mma_f16(acc[ni], av, bl[ni]);
            }
        }
        __syncthreads();
    }

    int row0 = mBase + warpM + (lane >> 2);
    int row1 = row0 + 8;
    float rs0 = 0.f, rd0 = 0.f, rs1 = 0.f, rd1 = 0.f;
#pragma unroll
    for (int ni = 0; ni < 4; ni++) {
        int col = ni * 8 + (lane & 3) * 2;
        if (row0 < nodeEnd)
            *(float2*)(&g_xl2[(size_t)row0 * C2 + col]) = make_float2(acc[ni][0], acc[ni][1]);
        if (row1 < nodeEnd)
            *(float2*)(&g_xl2[(size_t)row1 * C2 + col]) = make_float2(acc[ni][2], acc[ni][3]);
        float s0 = __ldg(&attS2[col]), s1 = __ldg(&attS2[col + 1]);
        float d0 = __ldg(&attD2[col]), d1 = __ldg(&attD2[col + 1]);
        rs0 = fmaf(acc[ni][0], s0, fmaf(acc[ni][1], s1, rs0));
        rd0 = fmaf(acc[ni][0], d0, fmaf(acc[ni][1], d1, rd0));
        rs1 = fmaf(acc[ni][2], s0, fmaf(acc[ni][3], s1, rs1));
        rd1 = fmaf(acc[ni][2], d0, fmaf(acc[ni][3], d1, rd1));
    }
#pragma unroll
    for (int off = 1; off <= 2; off <<= 1) {
        rs0 += __shfl_xor_sync(0xffffffffu, rs0, off);
        rd0 += __shfl_xor_sync(0xffffffffu, rd0, off);
        rs1 += __shfl_xor_sync(0xffffffffu, rs1, off);
        rd1 += __shfl_xor_sync(0xffffffffu, rd1, off);
    }
    if ((lane & 3) == 0) {
        if (row0 < nodeEnd) { g_as2[row0] = rs0; g_ad2[row0] = rd0; }
        if (row1 < nodeEnd) { g_as2[row1] = rs1; g_ad2[row1] = rd1; }
    }
}

// ---- layer-2 fused softmax+aggregation + fc head: warp per node --------------
__global__ void __launch_bounds__(256) agg2_kernel(const float* __restrict__ b2,
                                                   const float* __restrict__ fcW,
                                                   const float* __restrict__ fcb,
                                                   float* __restrict__ out) {
    __shared__ float fs[C2 * OUT_DIM];
    __shared__ float fb[OUT_DIM];
    for (int i = threadIdx.x; i < C2 * OUT_DIM; i += 256) fs[i] = fcW[i];
    if (threadIdx.x < OUT_DIM) fb[threadIdx.x] = fcb[threadIdx.x];
    __syncthreads();

    int w = (blockIdx.x * blockDim.x + threadIdx.x) >> 5;
    int lane = threadIdx.x & 31;
    if (w >= NN) return;
    float ad = g_ad2[w];
    float pself = __expf(lrelu(g_as2[w] + ad));
    float acc = pself * g_xl2[(size_t)w * C2 + lane];
    float dacc = 0.f;
    int beg = g_rowptr[w], end = g_rowptr[w + 1];
    for (int j0 = beg; j0 < end; j0 += 32) {
        int j = j0 + lane;
        bool valid = j < end;
        int s_l = valid ? g_csrc[j] : 0;
        float p_l = 0.f;
        if (valid) p_l = __expf(lrelu(__ldg(&g_as2[s_l]) + ad));
        dacc += p_l;
        int cnt = end - j0;
        if (cnt > 32) cnt = 32;
        for (int t = 0; t < cnt; t++) {
            float p = __shfl_sync(0xffffffffu, p_l, t);
            int   s = __shfl_sync(0xffffffffu, s_l, t);
            acc = fmaf(p, g_xl2[(size_t)s * C2 + lane], acc);
        }
    }
#pragma unroll
    for (int off = 16; off; off >>= 1) dacc += __shfl_xor_sync(0xffffffffu, dacc, off);
    float inv = 1.f / (dacc + pself + 1e-16f);
    float emb = fmaxf(fmaf(acc, inv, b2[lane]), 0.f);
    out[(size_t)w * C2 + lane] = emb;

    float l1 = fb[lane];
    float l2 = (lane < OUT_DIM - 32) ? fb[32 + lane] : 0.f;
#pragma unroll
    for (int c = 0; c < C2; c++) {
        float e = __shfl_sync(0xffffffffu, emb, c);
        l1 = fmaf(e, fs[c * OUT_DIM + lane], l1);
        if (lane < OUT_DIM - 32) l2 = fmaf(e, fs[c * OUT_DIM + 32 + lane], l2);
    }
    float* lg = out + (size_t)NN * C2 + (size_t)w * OUT_DIM;
    lg[lane] = l1;
    if (lane < OUT_DIM - 32) lg[32 + lane] = l2;
}

// ------------------------------------------------------------------------------
extern "C" void kernel_launch(void* const* d_in, const int* in_sizes, int n_in,
                              void* d_out, int out_size) {
    const float* x     = (const float*)d_in[0];
    const int*   ei    = (const int*)  d_in[1];
    const float* W1    = (const float*)d_in[2];
    const float* attS1 = (const float*)d_in[3];
    const float* attD1 = (const float*)d_in[4];
    const float* b1    = (const float*)d_in[5];
    const float* W2    = (const float*)d_in[6];
    const float* attS2 = (const float*)d_in[7];
    const float* attD2 = (const float*)d_in[8];
    const float* b2    = (const float*)d_in[9];
    const float* fcW   = (const float*)d_in[10];
    const float* fcb   = (const float*)d_in[11];
    float* out = (float*)d_out;

    const int* src = ei;
    const int* dst = ei + EE;

    // fixed auxiliary stream + events (created once; same captured DAG each call)
    static cudaStream_t sB = [] { cudaStream_t s; cudaStreamCreateWithFlags(&s, cudaStreamNonBlocking); return s; }();
    static cudaEvent_t evFork = [] { cudaEvent_t e; cudaEventCreateWithFlags(&e, cudaEventDisableTiming); return e; }();
    static cudaEvent_t evCSR  = [] { cudaEvent_t e; cudaEventCreateWithFlags(&e, cudaEventDisableTiming); return e; }();
    static cudaEvent_t evG1   = [] { cudaEvent_t e; cudaEventCreateWithFlags(&e, cudaEventDisableTiming); return e; }();
    static cudaEvent_t evHi   = [] { cudaEvent_t e; cudaEventCreateWithFlags(&e, cudaEventDisableTiming); return e; }();

    cudaFuncSetAttribute(gemm1_mma_kernel, cudaFuncAttributeMaxDynamicSharedMemorySize,
                         GEMM1_SMEM);

    // ---- fork: CSR chain + w2 split on stream B, shadowed by gemm1 ----
    cudaEventRecord(evFork, 0);
    cudaStreamWaitEvent(sB, evFork, 0);

    void* degp = nullptr;
    cudaGetSymbolAddress(&degp, g_deg);
    cudaMemsetAsync(degp, 0, NN * sizeof(int), sB);
    hist_kernel<<<(EE + 255) / 256, 256, 0, sB>>>(dst);
    scanA_kernel<<<SCAN_BLOCKS, 1024, 0, sB>>>();
    scanB_kernel<<<1, 64, 0, sB>>>();
    scanC_kernel<<<SCAN_BLOCKS, 1024, 0, sB>>>();
    scatter_kernel<<<(EE + 255) / 256, 256, 0, sB>>>(src, dst);
    split_w2_kernel<<<(HC1 * C2 / 4 + 255) / 256, 256, 0, sB>>>(W2);
    cudaEventRecord(evCSR, sB);

    // ---- main stream: splits + gemm1 ----
    split_x_kernel<<<(NN * IN_DIM / 4 + 255) / 256, 256>>>(x);
    split_w_kernel<<<(IN_DIM * HC1 / 4 + 255) / 256, 256>>>(W1);
    {
        dim3 grid((NN + 127) / 128, HC1 / 128);
        gemm1_mma_kernel<<<grid, 256, GEMM1_SMEM>>>(attS1, attD1);
    }
    cudaEventRecord(evG1, 0);

    // ---- layer 1 agg + layer 2 gemm, pipelined in node halves ----
    cudaStreamWaitEvent(0, evCSR, 0);
    agg1_kernel<<<(NHALF * 32 + 255) / 256, 256>>>(b1, 0, NHALF);
    gemm2_mma_kernel<<<NHALF / 128, 256>>>(attS2, attD2, 0, NHALF);

    cudaStreamWaitEvent(sB, evG1, 0);
    agg1_kernel<<<((NN - NHALF) * 32 + 255) / 256, 256, 0, sB>>>(b1, NHALF, NN);
    gemm2_mma_kernel<<<(NN - NHALF + 127) / 128, 256, 0, sB>>>(attS2, attD2, NHALF, NN);
    cudaEventRecord(evHi, sB);

    // ---- join, then layer-2 agg + fused fc head ----
    cudaStreamWaitEvent(0, evHi, 0);
    agg2_kernel<<<(NN * 32 + 255) / 256, 256>>>(b2, fcW, fcb, out);
}

// round 10
// speedup vs baseline: 4.1377x; 1.0997x over previous
#include <cuda_runtime.h>
#include <cuda_bf16.h>
#include <cuda_fp16.h>
#include <cstdint>

// Problem constants (fixed by the dataset)
#define NN      50000
#define EE      800000
#define IN_DIM  256
#define HEADS   8
#define C1      64
#define HC1     512          // HEADS*C1
#define C2      32
#define OUT_DIM 40
#define NEG_SLOPE 0.2f

#define SCAN_BLOCKS 49       // 49 * 1024 >= NN
#define NHALF 25088          // 196 * 128, split point for layer pipelining

// ---------------- scratch (device globals; no cudaMalloc allowed) ------------
__device__ __half g_xl1h[(size_t)NN * HC1];   // x @ W1  (fp16)
__device__ __half g_h1h [(size_t)NN * HC1];   // layer-1 output, relu (fp16)
__device__ __half g_xh  [(size_t)NN * IN_DIM];   // x in fp16
__device__ __half g_w1h [(size_t)IN_DIM * HC1];  // W1 fp16
__device__ __half g_w2hi[HC1 * C2];
__device__ __half g_w2lo[HC1 * C2];
__device__ __half g_xl2h[(size_t)NN * C2];    // layer-2 pre-act (fp16)
__device__ float g_as1[NN * HEADS];
__device__ float g_ad1[NN * HEADS];
__device__ float g_as2[NN], g_ad2[NN];
__device__ int   g_deg[NN];
__device__ int   g_incl[SCAN_BLOCKS * 1024];
__device__ int   g_bsum[SCAN_BLOCKS];
__device__ int   g_boff[SCAN_BLOCKS];
__device__ int   g_rowptr[NN + 1];
__device__ int   g_cursor[NN];
__device__ int   g_csrc[EE];

__device__ __forceinline__ float lrelu(float x) { return x > 0.f ? x : NEG_SLOPE * x; }

// ========================= PTX helpers =========================
__device__ __forceinline__ uint32_t smem_u32(const void* p) {
    uint32_t a;
    asm("{ .reg .u64 t; cvta.to.shared.u64 t, %1; cvt.u32.u64 %0, t; }" : "=r"(a) : "l"(p));
    return a;
}
__device__ __forceinline__ void ldsm_x4(uint32_t addr, uint32_t& r0, uint32_t& r1,
                                        uint32_t& r2, uint32_t& r3) {
    asm volatile("ldmatrix.sync.aligned.m8n8.x4.shared.b16 {%0,%1,%2,%3}, [%4];"
                 : "=r"(r0), "=r"(r1), "=r"(r2), "=r"(r3) : "r"(addr));
}
__device__ __forceinline__ void ldsm_x4_trans(uint32_t addr, uint32_t& r0, uint32_t& r1,
                                              uint32_t& r2, uint32_t& r3) {
    asm volatile("ldmatrix.sync.aligned.m8n8.x4.trans.shared.b16 {%0,%1,%2,%3}, [%4];"
                 : "=r"(r0), "=r"(r1), "=r"(r2), "=r"(r3) : "r"(addr));
}
__device__ __forceinline__ void mma_f16(float* d, const uint32_t* a, const uint32_t* b) {
    asm volatile(
        "mma.sync.aligned.m16n8k16.row.col.f32.f16.f16.f32 "
        "{%0,%1,%2,%3},{%4,%5,%6,%7},{%8,%9},{%0,%1,%2,%3};"
        : "+f"(d[0]), "+f"(d[1]), "+f"(d[2]), "+f"(d[3])
        : "r"(a[0]), "r"(a[1]), "r"(a[2]), "r"(a[3]), "r"(b[0]), "r"(b[1]));
}
__device__ __forceinline__ void cp16(uint32_t dst, const void* src, uint32_t sz) {
    asm volatile("cp.async.cg.shared.global [%0], [%1], 16, %2;"
                 :: "r"(dst), "l"(src), "r"(sz) : "memory");
}
// unpack 8 fp16 (one uint4) to 8 floats
__device__ __forceinline__ void unpack8(uint4 v, float* f) {
    float2 t;
    t = __half22float2(*(__half2*)&v.x); f[0] = t.x; f[1] = t.y;
    t = __half22float2(*(__half2*)&v.y); f[2] = t.x; f[3] = t.y;
    t = __half22float2(*(__half2*)&v.z); f[4] = t.x; f[5] = t.y;
    t = __half22float2(*(__half2*)&v.w); f[6] = t.x; f[7] = t.y;
}

// ===================== input prep kernels =====================================
__global__ void split_x_kernel(const float* __restrict__ x) {
    int i = blockIdx.x * blockDim.x + threadIdx.x;
    if (i >= NN * IN_DIM / 4) return;
    float4 v = ((const float4*)x)[i];
    __half2 a = __floats2half2_rn(v.x, v.y);
    __half2 b = __floats2half2_rn(v.z, v.w);
    ((uint2*)g_xh)[i] = make_uint2(*(uint32_t*)&a, *(uint32_t*)&b);
}
__global__ void split_w_kernel(const float* __restrict__ w) {
    int i = blockIdx.x * blockDim.x + threadIdx.x;
    if (i >= IN_DIM * HC1 / 4) return;
    float4 v = ((const float4*)w)[i];
    __half2 a = __floats2half2_rn(v.x, v.y);
    __half2 b = __floats2half2_rn(v.z, v.w);
    ((uint2*)g_w1h)[i] = make_uint2(*(uint32_t*)&a, *(uint32_t*)&b);
}
__global__ void split_w2_kernel(const float* __restrict__ w) {
    int i = blockIdx.x * blockDim.x + threadIdx.x;
    if (i >= HC1 * C2 / 4) return;
    float4 v = ((const float4*)w)[i];
    __half h0 = __float2half_rn(v.x), h1 = __float2half_rn(v.y);
    __half h2 = __float2half_rn(v.z), h3 = __float2half_rn(v.w);
    __half l0 = __float2half_rn(v.x - __half2float(h0));
    __half l1 = __float2half_rn(v.y - __half2float(h1));
    __half l2 = __float2half_rn(v.z - __half2float(h2));
    __half l3 = __float2half_rn(v.w - __half2float(h3));
    __half2 p0 = __halves2half2(h0, h1), p1 = __halves2half2(h2, h3);
    __half2 q0 = __halves2half2(l0, l1), q1 = __halves2half2(l2, l3);
    ((uint2*)g_w2hi)[i] = make_uint2(*(uint32_t*)&p0, *(uint32_t*)&p1);
    ((uint2*)g_w2lo)[i] = make_uint2(*(uint32_t*)&q0, *(uint32_t*)&q1);
}

// ======== GEMM1: xl1 = x @ W1, pure fp16, cp.async double-buffered ===========
#define ASTR 40     // fp16 per A smem row (32 + 8 pad)
#define BSTR 136    // fp16 per B smem row (128 + 8 pad)
#define OFF_A   0
#define OFF_B   10240
#define STAGE   18944
#define GEMM1_SMEM (2 * STAGE)

__global__ void __launch_bounds__(256, 2) gemm1_mma_kernel(const float* __restrict__ attS1,
                                                           const float* __restrict__ attD1) {
    extern __shared__ __align__(16) char smem[];
    const uint32_t sbase = smem_u32(smem);
    const int tid = threadIdx.x, wid = tid >> 5, lane = tid & 31;
    const int warpM = (wid & 3) * 32;
    const int warpN = (wid >> 2) * 64;
    const int mBase = blockIdx.x * 128;
    const int nBase = blockIdx.y * 128;

    float acc[2][8][4];
#pragma unroll
    for (int mi = 0; mi < 2; mi++)
#pragma unroll
        for (int ni = 0; ni < 8; ni++)
#pragma unroll
            for (int q = 0; q < 4; q++) acc[mi][ni][q] = 0.f;

    auto load_stage = [&](int ch, int buf) {
        const int k0 = ch * 32;
        const uint32_t sb = sbase + buf * STAGE;
#pragma unroll
        for (int it = 0; it < 2; it++) {
            int chunk = it * 256 + tid;          // 512 chunks (A)
            int r = chunk >> 2, c = (chunk & 3) * 8;
            int gr = mBase + r;
            uint32_t sz = (gr < NN) ? 16u : 0u;
            int grc = gr < NN ? gr : NN - 1;
            uint32_t so = (uint32_t)(r * ASTR + c) * 2;
            cp16(sb + OFF_A + so, &g_xh[(size_t)grc * IN_DIM + k0 + c], sz);
        }
#pragma unroll
        for (int it = 0; it < 2; it++) {
            int chunk = it * 256 + tid;          // 512 chunks (B)
            int r = chunk >> 4, c = (chunk & 15) * 8;
            uint32_t so = (uint32_t)(r * BSTR + c) * 2;
            cp16(sb + OFF_B + so, &g_w1h[(size_t)(k0 + r) * HC1 + nBase + c], 16);
        }
        asm volatile("cp.async.commit_group;" ::: "memory");
    };

    load_stage(0, 0);
    for (int ch = 0; ch < 8; ch++) {
        const int buf = ch & 1;
        if (ch + 1 < 8) {
            load_stage(ch + 1, buf ^ 1);
            asm volatile("cp.async.wait_group 1;" ::: "memory");
        } else {
            asm volatile("cp.async.wait_group 0;" ::: "memory");
        }
        __syncthreads();
        const uint32_t sb = sbase + buf * STAGE;
#pragma unroll
        for (int ks = 0; ks < 2; ks++) {
            uint32_t av[2][4];
#pragma unroll
            for (int mi = 0; mi < 2; mi++) {
                int row = warpM + mi * 16 + (lane & 15);
                int col = ks * 16 + (lane >> 4) * 8;
                uint32_t off = (uint32_t)(row * ASTR + col) * 2;
                ldsm_x4(sb + OFF_A + off, av[mi][0], av[mi][1], av[mi][2], av[mi][3]);
            }
            uint32_t bv[8][2];
#pragma unroll
            for (int np = 0; np < 4; np++) {
                int krow = ks * 16 + (lane & 15);
                int col = warpN + np * 16 + (lane >> 4) * 8;
                uint32_t off = (uint32_t)(krow * BSTR + col) * 2;
                ldsm_x4_trans(sb + OFF_B + off, bv[np * 2][0], bv[np * 2][1],
                              bv[np * 2 + 1][0], bv[np * 2 + 1][1]);
            }
#pragma unroll
            for (int mi = 0; mi < 2; mi++)
#pragma unroll
                for (int ni = 0; ni < 8; ni++)
                    mma_f16(acc[mi][ni], av[mi], bv[ni]);
        }
        __syncthreads();
    }

    // ---- epilogue 1: store xl1 (fp16) ----
#pragma unroll
    for (int mi = 0; mi < 2; mi++) {
#pragma unroll
        for (int ni = 0; ni < 8; ni++) {
            int row0 = mBase + warpM + mi * 16 + (lane >> 2);
            int col = nBase + warpN + ni * 8 + (lane & 3) * 2;
            if (row0 < NN)
                *(__half2*)(&g_xl1h[(size_t)row0 * HC1 + col]) =
                    __floats2half2_rn(acc[mi][ni][0], acc[mi][ni][1]);
            int row1 = row0 + 8;
            if (row1 < NN)
                *(__half2*)(&g_xl1h[(size_t)row1 * HC1 + col]) =
                    __floats2half2_rn(acc[mi][ni][2], acc[mi][ni][3]);
        }
    }

    // ---- epilogue 2: fused a_src / a_dst (warp owns one complete head) ----
    {
        const int h = blockIdx.y * 2 + (wid >> 2);
        float sS[8][2], sD[8][2];
        int cb = h * C1 + (lane & 3) * 2;
#pragma unroll
        for (int ni = 0; ni < 8; ni++) {
            sS[ni][0] = __ldg(&attS1[cb + ni * 8]);
            sS[ni][1] = __ldg(&attS1[cb + ni * 8 + 1]);
            sD[ni][0] = __ldg(&attD1[cb + ni * 8]);
            sD[ni][1] = __ldg(&attD1[cb + ni * 8 + 1]);
        }
#pragma unroll
        for (int mi = 0; mi < 2; mi++) {
            float rs0 = 0.f, rs1 = 0.f, rd0 = 0.f, rd1 = 0.f;
#pragma unroll
            for (int ni = 0; ni < 8; ni++) {
                rs0 = fmaf(acc[mi][ni][0], sS[ni][0], fmaf(acc[mi][ni][1], sS[ni][1], rs0));
                rd0 = fmaf(acc[mi][ni][0], sD[ni][0], fmaf(acc[mi][ni][1], sD[ni][1], rd0));
                rs1 = fmaf(acc[mi][ni][2], sS[ni][0], fmaf(acc[mi][ni][3], sS[ni][1], rs1));
                rd1 = fmaf(acc[mi][ni][2], sD[ni][0], fmaf(acc[mi][ni][3], sD[ni][1], rd1));
            }
#pragma unroll
            for (int off = 1; off <= 2; off <<= 1) {
                rs0 += __shfl_xor_sync(0xffffffffu, rs0, off);
                rd0 += __shfl_xor_sync(0xffffffffu, rd0, off);
                rs1 += __shfl_xor_sync(0xffffffffu, rs1, off);
                rd1 += __shfl_xor_sync(0xffffffffu, rd1, off);
            }
            if ((lane & 3) == 0) {
                int row0 = mBase + warpM + mi * 16 + (lane >> 2);
                if (row0 < NN) { g_as1[row0 * 8 + h] = rs0; g_ad1[row0 * 8 + h] = rd0; }
                int row1 = row0 + 8;
                if (row1 < NN) { g_as1[row1 * 8 + h] = rs1; g_ad1[row1 * 8 + h] = rd1; }
            }
        }
    }
}

// ---------------------------- CSR construction -------------------------------
__global__ void hist_kernel(const int* __restrict__ dst) {
    int e = blockIdx.x * blockDim.x + threadIdx.x;
    if (e < EE) atomicAdd(&g_deg[dst[e]], 1);
}
__global__ void scanA_kernel() {
    __shared__ int sh[1024];
    int i = blockIdx.x * 1024 + threadIdx.x;
    int v = (i < NN) ? g_deg[i] : 0;
    sh[threadIdx.x] = v;
    __syncthreads();
#pragma unroll
    for (int off = 1; off < 1024; off <<= 1) {
        int t = (threadIdx.x >= off) ? sh[threadIdx.x - off] : 0;
        __syncthreads();
        sh[threadIdx.x] += t;
        __syncthreads();
    }
    g_incl[i] = sh[threadIdx.x];
    if (threadIdx.x == 1023) g_bsum[blockIdx.x] = sh[1023];
}
__global__ void scanB_kernel() {   // 1 block, 64 threads
    __shared__ int sh[64];
    int t = threadIdx.x;
    int v = (t < SCAN_BLOCKS) ? g_bsum[t] : 0;
    sh[t] = v;
    __syncthreads();
#pragma unroll
    for (int off = 1; off < 64; off <<= 1) {
        int u = (t >= off) ? sh[t - off] : 0;
        __syncthreads();
        sh[t] += u;
        __syncthreads();
    }
    if (t < SCAN_BLOCKS) g_boff[t] = sh[t] - v;   // exclusive
}
__global__ void scanC_kernel() {
    int i = blockIdx.x * 1024 + threadIdx.x;
    if (i < NN) {
        int ex = g_boff[blockIdx.x] + g_incl[i] - g_deg[i];
        g_rowptr[i] = ex;
        g_cursor[i] = ex;
    }
    if (i == 0) g_rowptr[NN] = EE;
}
__global__ void scatter_kernel(const int* __restrict__ src, const int* __restrict__ dst) {
    int e = blockIdx.x * blockDim.x + threadIdx.x;
    if (e >= EE) return;
    int d = dst[e];
    int pos = atomicAdd(&g_cursor[d], 1);
    g_csrc[pos] = src[e];
}

// ---- layer-1 fused softmax+aggregation: warp per node, all heads (fp16 in) ---
__global__ void agg1_kernel(const float* __restrict__ b1, int nodeBeg, int nodeEnd) {
    int w = nodeBeg + ((blockIdx.x * blockDim.x + threadIdx.x) >> 5);
    int lane = threadIdx.x & 31;
    if (w >= nodeEnd) return;
    const int h = lane >> 2;
    const int e4 = lane & 3;
    const int idx8 = w * 8 + h;
    const float ad = g_ad1[idx8];
    const float pself = __expf(lrelu(g_as1[idx8] + ad));

    float acc[16];
    {
        const uint4* xr = (const uint4*)(g_xl1h + (size_t)w * HC1 + lane * 16);
        uint4 v0 = xr[0], v1 = xr[1];
        unpack8(v0, acc); unpack8(v1, acc + 8);
#pragma unroll
        for (int i = 0; i < 16; i++) acc[i] *= pself;
    }
    float dacc = 0.f;

    const int beg = g_rowptr[w], end = g_rowptr[w + 1];
    for (int j0 = beg; j0 < end; j0 += 4) {
        int j = j0 + e4;
        bool valid = j < end;
        int s_l = valid ? g_csrc[j] : 0;
        float p_l = 0.f;
        if (valid) p_l = __expf(lrelu(__ldg(&g_as1[s_l * 8 + h]) + ad));
        dacc += p_l;
        int cnt = end - j0;
        int qb = lane & 28;
#pragma unroll
        for (int t = 0; t < 4; t++) {
            if (t < cnt) {
                float p = __shfl_sync(0xffffffffu, p_l, qb | t);
                int   s = __shfl_sync(0xffffffffu, s_l, qb | t);
                const uint4* sr = (const uint4*)(g_xl1h + (size_t)s * HC1 + lane * 16);
                uint4 u0 = sr[0], u1 = sr[1];
                float bq[16];
                unpack8(u0, bq); unpack8(u1, bq + 8);
#pragma unroll
                for (int i = 0; i < 16; i++) acc[i] = fmaf(p, bq[i], acc[i]);
            }
        }
    }
    dacc += __shfl_xor_sync(0xffffffffu, dacc, 1);
    dacc += __shfl_xor_sync(0xffffffffu, dacc, 2);
    float inv = 1.f / (dacc + pself + 1e-16f);

    float bv[16];
    {
        const float4* bb = (const float4*)(b1 + lane * 16);
        float4 t0 = bb[0], t1 = bb[1], t2 = bb[2], t3 = bb[3];
        bv[0] = t0.x; bv[1] = t0.y; bv[2]  = t0.z; bv[3]  = t0.w;
        bv[4] = t1.x; bv[5] = t1.y; bv[6]  = t1.z; bv[7]  = t1.w;
        bv[8] = t2.x; bv[9] = t2.y; bv[10] = t2.z; bv[11] = t2.w;
        bv[12] = t3.x; bv[13] = t3.y; bv[14] = t3.z; bv[15] = t3.w;
    }
    uint32_t r[8];
#pragma unroll
    for (int i = 0; i < 8; i++) {
        float f0 = fmaxf(fmaf(acc[2 * i],     inv, bv[2 * i]),     0.f);
        float f1 = fmaxf(fmaf(acc[2 * i + 1], inv, bv[2 * i + 1]), 0.f);
        __half2 hh = __floats2half2_rn(f0, f1);
        r[i] = *(uint32_t*)&hh;
    }
    uint4* hw = (uint4*)(g_h1h + (size_t)w * HC1 + lane * 16);
    hw[0] = make_uint4(r[0], r[1], r[2], r[3]);
    hw[1] = make_uint4(r[4], r[5], r[6], r[7]);
}

// ==== GEMM2: xl2 = h1 @ W2 (rows [nodeBeg,nodeEnd)), fp16 A + fp16 hi/lo B ===
#define A2STR 40
#define B2STR 40
__global__ void __launch_bounds__(256) gemm2_mma_kernel(const float* __restrict__ attS2,
                                                        const float* __restrict__ attD2,
                                                        int nodeBeg, int nodeEnd) {
    __shared__ __align__(16) __half sA[128 * A2STR];
    __shared__ __align__(16) __half sBhi[32 * B2STR], sBlo[32 * B2STR];
    const int tid = threadIdx.x, wid = tid >> 5, lane = tid & 31;
    const int mBase = nodeBeg + blockIdx.x * 128;
    const int warpM = wid * 16;

    const int ar = tid >> 1, ak = (tid & 1) * 16;
    int grow = mBase + ar; if (grow >= nodeEnd) grow = nodeEnd - 1;
    const __half* abase = g_h1h + (size_t)grow * HC1 + ak;
    const bool bhi_role = tid < 128;
    const int bk = (tid & 127) >> 2, bseg = (tid & 3) * 8;
    const __half* bsrc = (bhi_role ? g_w2hi : g_w2lo) + bk * C2 + bseg;

    float acc[4][4];
#pragma unroll
    for (int ni = 0; ni < 4; ni++)
#pragma unroll
        for (int q = 0; q < 4; q++) acc[ni][q] = 0.f;

    uint4 ra0 = *(const uint4*)(abase);      // 8 fp16
    uint4 ra1 = *(const uint4*)(abase + 8);  // 8 fp16
    uint4 rb = *(const uint4*)bsrc;

    const uint32_t sAB = smem_u32(sA);
    const uint32_t sBhiB = smem_u32(sBhi), sBloB = smem_u32(sBlo);

    for (int ch = 0; ch < 16; ch++) {
        *(uint4*)(&sA[ar * A2STR + ak])     = ra0;
        *(uint4*)(&sA[ar * A2STR + ak + 8]) = ra1;
        __half* bdst = (bhi_role ? sBhi : sBlo) + bk * B2STR + bseg;
        *(uint4*)bdst = rb;
        __syncthreads();
        if (ch < 15) {
            const __half* an = abase + (ch + 1) * 32;
            ra0 = *(const uint4*)(an);
            ra1 = *(const uint4*)(an + 8);
            rb = *(const uint4*)(bsrc + (size_t)(ch + 1) * 32 * C2);
        }
#pragma unroll
        for (int ks = 0; ks < 2; ks++) {
            uint32_t av[4];
            int row = warpM + (lane & 15);
            int col = ks * 16 + (lane >> 4) * 8;
            uint32_t offA = (uint32_t)(row * A2STR + col) * 2;
            ldsm_x4(sAB + offA, av[0], av[1], av[2], av[3]);
            uint32_t bh[4][2], bl[4][2];
            int krow = ks * 16 + (lane & 15);
#pragma unroll
            for (int np = 0; np < 2; np++) {
                int bcol = np * 16 + (lane >> 4) * 8;
                uint32_t offB = (uint32_t)(krow * B2STR + bcol) * 2;
                ldsm_x4_trans(sBhiB + offB, bh[np * 2][0], bh[np * 2][1],
                              bh[np * 2 + 1][0], bh[np * 2 + 1][1]);
                ldsm_x4_trans(sBloB + offB, bl[np * 2][0], bl[np * 2][1],
                              bl[np * 2 + 1][0], bl[np * 2 + 1][1]);
            }
#pragma unroll
            for (int ni = 0; ni < 4; ni++) {
                mma_f16(acc[ni], av, bh[ni]);
                mma_f16(acc[ni], av, bl[ni]);
            }
        }
        __syncthreads();
    }

    int row0 = mBase + warpM + (lane >> 2);
    int row1 = row0 + 8;
    float rs0 = 0.f, rd0 = 0.f, rs1 = 0.f, rd1 = 0.f;
#pragma unroll
    for (int ni = 0; ni < 4; ni++) {
        int col = ni * 8 + (lane & 3) * 2;
        if (row0 < nodeEnd)
            *(__half2*)(&g_xl2h[(size_t)row0 * C2 + col]) =
                __floats2half2_rn(acc[ni][0], acc[ni][1]);
        if (row1 < nodeEnd)
            *(__half2*)(&g_xl2h[(size_t)row1 * C2 + col]) =
                __floats2half2_rn(acc[ni][2], acc[ni][3]);
        float s0 = __ldg(&attS2[col]), s1 = __ldg(&attS2[col + 1]);
        float d0 = __ldg(&attD2[col]), d1 = __ldg(&attD2[col + 1]);
        rs0 = fmaf(acc[ni][0], s0, fmaf(acc[ni][1], s1, rs0));
        rd0 = fmaf(acc[ni][0], d0, fmaf(acc[ni][1], d1, rd0));
        rs1 = fmaf(acc[ni][2], s0, fmaf(acc[ni][3], s1, rs1));
        rd1 = fmaf(acc[ni][2], d0, fmaf(acc[ni][3], d1, rd1));
    }
#pragma unroll
    for (int off = 1; off <= 2; off <<= 1) {
        rs0 += __shfl_xor_sync(0xffffffffu, rs0, off);
        rd0 += __shfl_xor_sync(0xffffffffu, rd0, off);
        rs1 += __shfl_xor_sync(0xffffffffu, rs1, off);
        rd1 += __shfl_xor_sync(0xffffffffu, rd1, off);
    }
    if ((lane & 3) == 0) {
        if (row0 < nodeEnd) { g_as2[row0] = rs0; g_ad2[row0] = rd0; }
        if (row1 < nodeEnd) { g_as2[row1] = rs1; g_ad2[row1] = rd1; }
    }
}

// ---- layer-2 fused softmax+aggregation + fc head: warp per node --------------
__global__ void __launch_bounds__(256) agg2_kernel(const float* __restrict__ b2,
                                                   const float* __restrict__ fcW,
                                                   const float* __restrict__ fcb,
                                                   float* __restrict__ out) {
    __shared__ float fs[C2 * OUT_DIM];
    __shared__ float fb[OUT_DIM];
    for (int i = threadIdx.x; i < C2 * OUT_DIM; i += 256) fs[i] = fcW[i];
    if (threadIdx.x < OUT_DIM) fb[threadIdx.x] = fcb[threadIdx.x];
    __syncthreads();

    int w = (blockIdx.x * blockDim.x + threadIdx.x) >> 5;
    int lane = threadIdx.x & 31;
    if (w >= NN) return;
    float ad = g_ad2[w];
    float pself = __expf(lrelu(g_as2[w] + ad));
    float acc = pself * __half2float(g_xl2h[(size_t)w * C2 + lane]);
    float dacc = 0.f;
    int beg = g_rowptr[w], end = g_rowptr[w + 1];
    for (int j0 = beg; j0 < end; j0 += 32) {
        int j = j0 + lane;
        bool valid = j < end;
        int s_l = valid ? g_csrc[j] : 0;
        float p_l = 0.f;
        if (valid) p_l = __expf(lrelu(__ldg(&g_as2[s_l]) + ad));
        dacc += p_l;
        int cnt = end - j0;
        if (cnt > 32) cnt = 32;
        for (int t = 0; t < cnt; t++) {
            float p = __shfl_sync(0xffffffffu, p_l, t);
            int   s = __shfl_sync(0xffffffffu, s_l, t);
            acc = fmaf(p, __half2float(g_xl2h[(size_t)s * C2 + lane]), acc);
        }
    }
#pragma unroll
    for (int off = 16; off; off >>= 1) dacc += __shfl_xor_sync(0xffffffffu, dacc, off);
    float inv = 1.f / (dacc + pself + 1e-16f);
    float emb = fmaxf(fmaf(acc, inv, b2[lane]), 0.f);
    out[(size_t)w * C2 + lane] = emb;

    float l1 = fb[lane];
    float l2 = (lane < OUT_DIM - 32) ? fb[32 + lane] : 0.f;
#pragma unroll
    for (int c = 0; c < C2; c++) {
        float e = __shfl_sync(0xffffffffu, emb, c);
        l1 = fmaf(e, fs[c * OUT_DIM + lane], l1);
        if (lane < OUT_DIM - 32) l2 = fmaf(e, fs[c * OUT_DIM + 32 + lane], l2);
    }
    float* lg = out + (size_t)NN * C2 + (size_t)w * OUT_DIM;
    lg[lane] = l1;
    if (lane < OUT_DIM - 32) lg[32 + lane] = l2;
}

// ------------------------------------------------------------------------------
extern "C" void kernel_launch(void* const* d_in, const int* in_sizes, int n_in,
                              void* d_out, int out_size) {
    const float* x     = (const float*)d_in[0];
    const int*   ei    = (const int*)  d_in[1];
    const float* W1    = (const float*)d_in[2];
    const float* attS1 = (const float*)d_in[3];
    const float* attD1 = (const float*)d_in[4];
    const float* b1    = (const float*)d_in[5];
    const float* W2    = (const float*)d_in[6];
    const float* attS2 = (const float*)d_in[7];
    const float* attD2 = (const float*)d_in[8];
    const float* b2    = (const float*)d_in[9];
    const float* fcW   = (const float*)d_in[10];
    const float* fcb   = (const float*)d_in[11];
    float* out = (float*)d_out;

    const int* src = ei;
    const int* dst = ei + EE;

    // fixed auxiliary stream + events (created once; same captured DAG each call)
    static cudaStream_t sB = [] { cudaStream_t s; cudaStreamCreateWithFlags(&s, cudaStreamNonBlocking); return s; }();
    static cudaEvent_t evFork = [] { cudaEvent_t e; cudaEventCreateWithFlags(&e, cudaEventDisableTiming); return e; }();
    static cudaEvent_t evCSR  = [] { cudaEvent_t e; cudaEventCreateWithFlags(&e, cudaEventDisableTiming); return e; }();
    static cudaEvent_t evG1   = [] { cudaEvent_t e; cudaEventCreateWithFlags(&e, cudaEventDisableTiming); return e; }();
    static cudaEvent_t evHi   = [] { cudaEvent_t e; cudaEventCreateWithFlags(&e, cudaEventDisableTiming); return e; }();

    cudaFuncSetAttribute(gemm1_mma_kernel, cudaFuncAttributeMaxDynamicSharedMemorySize,
                         GEMM1_SMEM);

    // ---- fork: CSR chain + w2 split on stream B, shadowed by gemm1 ----
    cudaEventRecord(evFork, 0);
    cudaStreamWaitEvent(sB, evFork, 0);

    void* degp = nullptr;
    cudaGetSymbolAddress(&degp, g_deg);
    cudaMemsetAsync(degp, 0, NN * sizeof(int), sB);
    hist_kernel<<<(EE + 255) / 256, 256, 0, sB>>>(dst);
    scanA_kernel<<<SCAN_BLOCKS, 1024, 0, sB>>>();
    scanB_kernel<<<1, 64, 0, sB>>>();
    scanC_kernel<<<SCAN_BLOCKS, 1024, 0, sB>>>();
    scatter_kernel<<<(EE + 255) / 256, 256, 0, sB>>>(src, dst);
    split_w2_kernel<<<(HC1 * C2 / 4 + 255) / 256, 256, 0, sB>>>(W2);
    cudaEventRecord(evCSR, sB);

    // ---- main stream: splits + gemm1 ----
    split_x_kernel<<<(NN * IN_DIM / 4 + 255) / 256, 256>>>(x);
    split_w_kernel<<<(IN_DIM * HC1 / 4 + 255) / 256, 256>>>(W1);
    {
        dim3 grid((NN + 127) / 128, HC1 / 128);
        gemm1_mma_kernel<<<grid, 256, GEMM1_SMEM>>>(attS1, attD1);
    }
    cudaEventRecord(evG1, 0);

    // ---- layer 1 agg + layer 2 gemm, pipelined in node halves ----
    cudaStreamWaitEvent(0, evCSR, 0);
    agg1_kernel<<<(NHALF * 32 + 255) / 256, 256>>>(b1, 0, NHALF);
    gemm2_mma_kernel<<<NHALF / 128, 256>>>(attS2, attD2, 0, NHALF);

    cudaStreamWaitEvent(sB, evG1, 0);
    agg1_kernel<<<((NN - NHALF) * 32 + 255) / 256, 256, 0, sB>>>(b1, NHALF, NN);
    gemm2_mma_kernel<<<(NN - NHALF + 127) / 128, 256, 0, sB>>>(attS2, attD2, NHALF, NN);
    cudaEventRecord(evHi, sB);

    // ---- join, then layer-2 agg + fused fc head ----
    cudaStreamWaitEvent(0, evHi, 0);
    agg2_kernel<<<(NN * 32 + 255) / 256, 256>>>(b2, fcW, fcb, out);
}

// round 11
// speedup vs baseline: 4.2143x; 1.0185x over previous
#include <cuda_runtime.h>
#include <cuda_bf16.h>
#include <cuda_fp16.h>
#include <cstdint>

// Problem constants (fixed by the dataset)
#define NN      50000
#define EE      800000
#define IN_DIM  256
#define HEADS   8
#define C1      64
#define HC1     512          // HEADS*C1
#define C2      32
#define OUT_DIM 40
#define NEG_SLOPE 0.2f

#define SCAN_BLOCKS 49       // 49 * 1024 >= NN
#define NHALF 25088          // 196 * 128, split point for layer pipelining

// ---------------- scratch (device globals; no cudaMalloc allowed) ------------
__device__ __half g_xl1h[(size_t)NN * HC1];   // x @ W1  (fp16)
__device__ __half g_h1h [(size_t)NN * HC1];   // layer-1 output, relu (fp16)
__device__ __half g_xh  [(size_t)NN * IN_DIM];   // x in fp16
__device__ __half g_w1h [(size_t)IN_DIM * HC1];  // W1 fp16
__device__ __half g_w2hi[HC1 * C2];
__device__ __half g_w2lo[HC1 * C2];
__device__ __half g_xl2h[(size_t)NN * C2];    // layer-2 pre-act (fp16)
__device__ float g_as1[NN * HEADS];
__device__ float g_ad1[NN * HEADS];
__device__ float g_as2[NN], g_ad2[NN];
__device__ int   g_deg[NN];
__device__ int   g_incl[SCAN_BLOCKS * 1024];
__device__ int   g_bsum[SCAN_BLOCKS];
__device__ int   g_boff[SCAN_BLOCKS];
__device__ int   g_rowptr[NN + 1];
__device__ int   g_cursor[NN];
__device__ int   g_csrc[EE];

__device__ __forceinline__ float lrelu(float x) { return x > 0.f ? x : NEG_SLOPE * x; }

// ========================= PTX helpers =========================
__device__ __forceinline__ uint32_t smem_u32(const void* p) {
    uint32_t a;
    asm("{ .reg .u64 t; cvta.to.shared.u64 t, %1; cvt.u32.u64 %0, t; }" : "=r"(a) : "l"(p));
    return a;
}
__device__ __forceinline__ void ldsm_x4(uint32_t addr, uint32_t& r0, uint32_t& r1,
                                        uint32_t& r2, uint32_t& r3) {
    asm volatile("ldmatrix.sync.aligned.m8n8.x4.shared.b16 {%0,%1,%2,%3}, [%4];"
                 : "=r"(r0), "=r"(r1), "=r"(r2), "=r"(r3) : "r"(addr));
}
__device__ __forceinline__ void ldsm_x4_trans(uint32_t addr, uint32_t& r0, uint32_t& r1,
                                              uint32_t& r2, uint32_t& r3) {
    asm volatile("ldmatrix.sync.aligned.m8n8.x4.trans.shared.b16 {%0,%1,%2,%3}, [%4];"
                 : "=r"(r0), "=r"(r1), "=r"(r2), "=r"(r3) : "r"(addr));
}
__device__ __forceinline__ void mma_f16(float* d, const uint32_t* a, const uint32_t* b) {
    asm volatile(
        "mma.sync.aligned.m16n8k16.row.col.f32.f16.f16.f32 "
        "{%0,%1,%2,%3},{%4,%5,%6,%7},{%8,%9},{%0,%1,%2,%3};"
        : "+f"(d[0]), "+f"(d[1]), "+f"(d[2]), "+f"(d[3])
        : "r"(a[0]), "r"(a[1]), "r"(a[2]), "r"(a[3]), "r"(b[0]), "r"(b[1]));
}
__device__ __forceinline__ void cp16(uint32_t dst, const void* src, uint32_t sz) {
    asm volatile("cp.async.cg.shared.global [%0], [%1], 16, %2;"
                 :: "r"(dst), "l"(src), "r"(sz) : "memory");
}
// unpack 8 fp16 (one uint4) to 8 floats
__device__ __forceinline__ void unpack8(uint4 v, float* f) {
    float2 t;
    t = __half22float2(*(__half2*)&v.x); f[0] = t.x; f[1] = t.y;
    t = __half22float2(*(__half2*)&v.y); f[2] = t.x; f[3] = t.y;
    t = __half22float2(*(__half2*)&v.z); f[4] = t.x; f[5] = t.y;
    t = __half22float2(*(__half2*)&v.w); f[6] = t.x; f[7] = t.y;
}

// ===================== input prep kernels =====================================
// merged fp32 -> fp16 conversion for x and W1
#define NXC (NN * IN_DIM / 4)
#define NWC (IN_DIM * HC1 / 4)
__global__ void split_xw_kernel(const float* __restrict__ x, const float* __restrict__ w) {
    int i = blockIdx.x * blockDim.x + threadIdx.x;
    if (i < NXC) {
        float4 v = ((const float4*)x)[i];
        __half2 a = __floats2half2_rn(v.x, v.y);
        __half2 b = __floats2half2_rn(v.z, v.w);
        ((uint2*)g_xh)[i] = make_uint2(*(uint32_t*)&a, *(uint32_t*)&b);
    } else if (i < NXC + NWC) {
        int k = i - NXC;
        float4 v = ((const float4*)w)[k];
        __half2 a = __floats2half2_rn(v.x, v.y);
        __half2 b = __floats2half2_rn(v.z, v.w);
        ((uint2*)g_w1h)[k] = make_uint2(*(uint32_t*)&a, *(uint32_t*)&b);
    }
}
__global__ void split_w2_kernel(const float* __restrict__ w) {
    int i = blockIdx.x * blockDim.x + threadIdx.x;
    if (i >= HC1 * C2 / 4) return;
    float4 v = ((const float4*)w)[i];
    __half h0 = __float2half_rn(v.x), h1 = __float2half_rn(v.y);
    __half h2 = __float2half_rn(v.z), h3 = __float2half_rn(v.w);
    __half l0 = __float2half_rn(v.x - __half2float(h0));
    __half l1 = __float2half_rn(v.y - __half2float(h1));
    __half l2 = __float2half_rn(v.z - __half2float(h2));
    __half l3 = __float2half_rn(v.w - __half2float(h3));
    __half2 p0 = __halves2half2(h0, h1), p1 = __halves2half2(h2, h3);
    __half2 q0 = __halves2half2(l0, l1), q1 = __halves2half2(l2, l3);
    ((uint2*)g_w2hi)[i] = make_uint2(*(uint32_t*)&p0, *(uint32_t*)&p1);
    ((uint2*)g_w2lo)[i] = make_uint2(*(uint32_t*)&q0, *(uint32_t*)&q1);
}

// ======== GEMM1: xl1 = x @ W1, pure fp16, cp.async 3-stage pipeline ==========
#define ASTR 40     // fp16 per A smem row (32 + 8 pad)
#define BSTR 136    // fp16 per B smem row (128 + 8 pad)
#define OFF_A   0
#define OFF_B   10240
#define STAGE   18944
#define GEMM1_SMEM (3 * STAGE)

__global__ void __launch_bounds__(256, 2) gemm1_mma_kernel(const float* __restrict__ attS1,
                                                           const float* __restrict__ attD1) {
    extern __shared__ __align__(16) char smem[];
    const uint32_t sbase = smem_u32(smem);
    const int tid = threadIdx.x, wid = tid >> 5, lane = tid & 31;
    const int warpM = (wid & 3) * 32;
    const int warpN = (wid >> 2) * 64;
    const int mBase = blockIdx.x * 128;
    const int nBase = blockIdx.y * 128;

    float acc[2][8][4];
#pragma unroll
    for (int mi = 0; mi < 2; mi++)
#pragma unroll
        for (int ni = 0; ni < 8; ni++)
#pragma unroll
            for (int q = 0; q < 4; q++) acc[mi][ni][q] = 0.f;

    auto load_stage = [&](int ch, int buf) {
        const int k0 = ch * 32;
        const uint32_t sb = sbase + buf * STAGE;
#pragma unroll
        for (int it = 0; it < 2; it++) {
            int chunk = it * 256 + tid;          // 512 chunks (A)
            int r = chunk >> 2, c = (chunk & 3) * 8;
            int gr = mBase + r;
            uint32_t sz = (gr < NN) ? 16u : 0u;
            int grc = gr < NN ? gr : NN - 1;
            uint32_t so = (uint32_t)(r * ASTR + c) * 2;
            cp16(sb + OFF_A + so, &g_xh[(size_t)grc * IN_DIM + k0 + c], sz);
        }
#pragma unroll
        for (int it = 0; it < 2; it++) {
            int chunk = it * 256 + tid;          // 512 chunks (B)
            int r = chunk >> 4, c = (chunk & 15) * 8;
            uint32_t so = (uint32_t)(r * BSTR + c) * 2;
            cp16(sb + OFF_B + so, &g_w1h[(size_t)(k0 + r) * HC1 + nBase + c], 16);
        }
        asm volatile("cp.async.commit_group;" ::: "memory");
    };

    load_stage(0, 0);
    load_stage(1, 1);
    for (int ch = 0; ch < 8; ch++) {
        if (ch < 7) {
            asm volatile("cp.async.wait_group 1;" ::: "memory");
        } else {
            asm volatile("cp.async.wait_group 0;" ::: "memory");
        }
        __syncthreads();
        if (ch + 2 < 8) load_stage(ch + 2, (ch + 2) % 3);
        const uint32_t sb = sbase + (ch % 3) * STAGE;
#pragma unroll
        for (int ks = 0; ks < 2; ks++) {
            uint32_t av[2][4];
#pragma unroll
            for (int mi = 0; mi < 2; mi++) {
                int row = warpM + mi * 16 + (lane & 15);
                int col = ks * 16 + (lane >> 4) * 8;
                uint32_t off = (uint32_t)(row * ASTR + col) * 2;
                ldsm_x4(sb + OFF_A + off, av[mi][0], av[mi][1], av[mi][2], av[mi][3]);
            }
            uint32_t bv[8][2];
#pragma unroll
            for (int np = 0; np < 4; np++) {
                int krow = ks * 16 + (lane & 15);
                int col = warpN + np * 16 + (lane >> 4) * 8;
                uint32_t off = (uint32_t)(krow * BSTR + col) * 2;
                ldsm_x4_trans(sb + OFF_B + off, bv[np * 2][0], bv[np * 2][1],
                              bv[np * 2 + 1][0], bv[np * 2 + 1][1]);
            }
#pragma unroll
            for (int mi = 0; mi < 2; mi++)
#pragma unroll
                for (int ni = 0; ni < 8; ni++)
                    mma_f16(acc[mi][ni], av[mi], bv[ni]);
        }
    }

    // ---- epilogue 1: store xl1 (fp16) ----
#pragma unroll
    for (int mi = 0; mi < 2; mi++) {
#pragma unroll
        for (int ni = 0; ni < 8; ni++) {
            int row0 = mBase + warpM + mi * 16 + (lane >> 2);
            int col = nBase + warpN + ni * 8 + (lane & 3) * 2;
            if (row0 < NN)
                *(__half2*)(&g_xl1h[(size_t)row0 * HC1 + col]) =
                    __floats2half2_rn(acc[mi][ni][0], acc[mi][ni][1]);
            int row1 = row0 + 8;
            if (row1 < NN)
                *(__half2*)(&g_xl1h[(size_t)row1 * HC1 + col]) =
                    __floats2half2_rn(acc[mi][ni][2], acc[mi][ni][3]);
        }
    }

    // ---- epilogue 2: fused a_src / a_dst (warp owns one complete head) ----
    {
        const int h = blockIdx.y * 2 + (wid >> 2);
        float sS[8][2], sD[8][2];
        int cb = h * C1 + (lane & 3) * 2;
#pragma unroll
        for (int ni = 0; ni < 8; ni++) {
            sS[ni][0] = __ldg(&attS1[cb + ni * 8]);
            sS[ni][1] = __ldg(&attS1[cb + ni * 8 + 1]);
            sD[ni][0] = __ldg(&attD1[cb + ni * 8]);
            sD[ni][1] = __ldg(&attD1[cb + ni * 8 + 1]);
        }
#pragma unroll
        for (int mi = 0; mi < 2; mi++) {
            float rs0 = 0.f, rs1 = 0.f, rd0 = 0.f, rd1 = 0.f;
#pragma unroll
            for (int ni = 0; ni < 8; ni++) {
                rs0 = fmaf(acc[mi][ni][0], sS[ni][0], fmaf(acc[mi][ni][1], sS[ni][1], rs0));
                rd0 = fmaf(acc[mi][ni][0], sD[ni][0], fmaf(acc[mi][ni][1], sD[ni][1], rd0));
                rs1 = fmaf(acc[mi][ni][2], sS[ni][0], fmaf(acc[mi][ni][3], sS[ni][1], rs1));
                rd1 = fmaf(acc[mi][ni][2], sD[ni][0], fmaf(acc[mi][ni][3], sD[ni][1], rd1));
            }
#pragma unroll
            for (int off = 1; off <= 2; off <<= 1) {
                rs0 += __shfl_xor_sync(0xffffffffu, rs0, off);
                rd0 += __shfl_xor_sync(0xffffffffu, rd0, off);
                rs1 += __shfl_xor_sync(0xffffffffu, rs1, off);
                rd1 += __shfl_xor_sync(0xffffffffu, rd1, off);
            }
            if ((lane & 3) == 0) {
                int row0 = mBase + warpM + mi * 16 + (lane >> 2);
                if (row0 < NN) { g_as1[row0 * 8 + h] = rs0; g_ad1[row0 * 8 + h] = rd0; }
                int row1 = row0 + 8;
                if (row1 < NN) { g_as1[row1 * 8 + h] = rs1; g_ad1[row1 * 8 + h] = rd1; }
            }
        }
    }
}

// ---------------------------- CSR construction -------------------------------
__global__ void hist_kernel(const int* __restrict__ dst) {
    int e = blockIdx.x * blockDim.x + threadIdx.x;
    if (e < EE) atomicAdd(&g_deg[dst[e]], 1);
}
__global__ void scanA_kernel() {
    __shared__ int sh[1024];
    int i = blockIdx.x * 1024 + threadIdx.x;
    int v = (i < NN) ? g_deg[i] : 0;
    sh[threadIdx.x] = v;
    __syncthreads();
#pragma unroll
    for (int off = 1; off < 1024; off <<= 1) {
        int t = (threadIdx.x >= off) ? sh[threadIdx.x - off] : 0;
        __syncthreads();
        sh[threadIdx.x] += t;
        __syncthreads();
    }
    g_incl[i] = sh[threadIdx.x];
    if (threadIdx.x == 1023) g_bsum[blockIdx.x] = sh[1023];
}
__global__ void scanB_kernel() {   // 1 block, 64 threads
    __shared__ int sh[64];
    int t = threadIdx.x;
    int v = (t < SCAN_BLOCKS) ? g_bsum[t] : 0;
    sh[t] = v;
    __syncthreads();
#pragma unroll
    for (int off = 1; off < 64; off <<= 1) {
        int u = (t >= off) ? sh[t - off] : 0;
        __syncthreads();
        sh[t] += u;
        __syncthreads();
    }
    if (t < SCAN_BLOCKS) g_boff[t] = sh[t] - v;   // exclusive
}
__global__ void scanC_kernel() {
    int i = blockIdx.x * 1024 + threadIdx.x;
    if (i < NN) {
        int ex = g_boff[blockIdx.x] + g_incl[i] - g_deg[i];
        g_rowptr[i] = ex;
        g_cursor[i] = ex;
    }
    if (i == 0) g_rowptr[NN] = EE;
}
__global__ void scatter_kernel(const int* __restrict__ src, const int* __restrict__ dst) {
    int e = blockIdx.x * blockDim.x + threadIdx.x;
    if (e >= EE) return;
    int d = dst[e];
    int pos = atomicAdd(&g_cursor[d], 1);
    g_csrc[pos] = src[e];
}

// ---- layer-1 fused softmax+aggregation: warp per node, prefetched batches ----
__global__ void agg1_kernel(const float* __restrict__ b1, int nodeBeg, int nodeEnd) {
    int w = nodeBeg + ((blockIdx.x * blockDim.x + threadIdx.x) >> 5);
    int lane = threadIdx.x & 31;
    if (w >= nodeEnd) return;
    const int h = lane >> 2;
    const int e4 = lane & 3;
    const int idx8 = w * 8 + h;
    const float ad = g_ad1[idx8];
    const float pself = __expf(lrelu(g_as1[idx8] + ad));

    float acc[16];
    {
        const uint4* xr = (const uint4*)(g_xl1h + (size_t)w * HC1 + lane * 16);
        uint4 v0 = xr[0], v1 = xr[1];
        unpack8(v0, acc); unpack8(v1, acc + 8);
#pragma unroll
        for (int i = 0; i < 16; i++) acc[i] *= pself;
    }
    float dacc = 0.f;

    const int beg = g_rowptr[w], end = g_rowptr[w + 1];
    const int qb = lane & 28;

    // software-pipelined: prefetch next batch's (src, as1) before current FMAs
    int s_cur = 0; float a_cur = 0.f;
    {
        int j = beg + e4;
        if (j < end) { s_cur = g_csrc[j]; a_cur = __ldg(&g_as1[s_cur * 8 + h]); }
    }
    for (int j0 = beg; j0 < end; j0 += 4) {
        int s_nxt = 0; float a_nxt = 0.f;
        int jn = j0 + 4 + e4;
        if (jn < end) { s_nxt = g_csrc[jn]; a_nxt = __ldg(&g_as1[s_nxt * 8 + h]); }

        bool valid = (j0 + e4) < end;
        float p_l = valid ? __expf(lrelu(a_cur + ad)) : 0.f;
        dacc += p_l;
        int cnt = end - j0;
#pragma unroll
        for (int t = 0; t < 4; t++) {
            if (t < cnt) {
                float p = __shfl_sync(0xffffffffu, p_l, qb | t);
                int   s = __shfl_sync(0xffffffffu, s_cur, qb | t);
                const uint4* sr = (const uint4*)(g_xl1h + (size_t)s * HC1 + lane * 16);
                uint4 u0 = sr[0], u1 = sr[1];
                float bq[16];
                unpack8(u0, bq); unpack8(u1, bq + 8);
#pragma unroll
                for (int i = 0; i < 16; i++) acc[i] = fmaf(p, bq[i], acc[i]);
            }
        }
        s_cur = s_nxt; a_cur = a_nxt;
    }
    dacc += __shfl_xor_sync(0xffffffffu, dacc, 1);
    dacc += __shfl_xor_sync(0xffffffffu, dacc, 2);
    float inv = 1.f / (dacc + pself + 1e-16f);

    float bv[16];
    {
        const float4* bb = (const float4*)(b1 + lane * 16);
        float4 t0 = bb[0], t1 = bb[1], t2 = bb[2], t3 = bb[3];
        bv[0] = t0.x; bv[1] = t0.y; bv[2]  = t0.z; bv[3]  = t0.w;
        bv[4] = t1.x; bv[5] = t1.y; bv[6]  = t1.z; bv[7]  = t1.w;
        bv[8] = t2.x; bv[9] = t2.y; bv[10] = t2.z; bv[11] = t2.w;
        bv[12] = t3.x; bv[13] = t3.y; bv[14] = t3.z; bv[15] = t3.w;
    }
    uint32_t r[8];
#pragma unroll
    for (int i = 0; i < 8; i++) {
        float f0 = fmaxf(fmaf(acc[2 * i],     inv, bv[2 * i]),     0.f);
        float f1 = fmaxf(fmaf(acc[2 * i + 1], inv, bv[2 * i + 1]), 0.f);
        __half2 hh = __floats2half2_rn(f0, f1);
        r[i] = *(uint32_t*)&hh;
    }
    uint4* hw = (uint4*)(g_h1h + (size_t)w * HC1 + lane * 16);
    hw[0] = make_uint4(r[0], r[1], r[2], r[3]);
    hw[1] = make_uint4(r[4], r[5], r[6], r[7]);
}

// ==== GEMM2: xl2 = h1 @ W2 (rows [nodeBeg,nodeEnd)), fp16 A + fp16 hi/lo B ===
#define A2STR 40
#define B2STR 40
__global__ void __launch_bounds__(256) gemm2_mma_kernel(const float* __restrict__ attS2,
                                                        const float* __restrict__ attD2,
                                                        int nodeBeg, int nodeEnd) {
    __shared__ __align__(16) __half sA[128 * A2STR];
    __shared__ __align__(16) __half sBhi[32 * B2STR], sBlo[32 * B2STR];
    const int tid = threadIdx.x, wid = tid >> 5, lane = tid & 31;
    const int mBase = nodeBeg + blockIdx.x * 128;
    const int warpM = wid * 16;

    const int ar = tid >> 1, ak = (tid & 1) * 16;
    int grow = mBase + ar; if (grow >= nodeEnd) grow = nodeEnd - 1;
    const __half* abase = g_h1h + (size_t)grow * HC1 + ak;
    const bool bhi_role = tid < 128;
    const int bk = (tid & 127) >> 2, bseg = (tid & 3) * 8;
    const __half* bsrc = (bhi_role ? g_w2hi : g_w2lo) + bk * C2 + bseg;

    float acc[4][4];
#pragma unroll
    for (int ni = 0; ni < 4; ni++)
#pragma unroll
        for (int q = 0; q < 4; q++) acc[ni][q] = 0.f;

    uint4 ra0 = *(const uint4*)(abase);      // 8 fp16
    uint4 ra1 = *(const uint4*)(abase + 8);  // 8 fp16
    uint4 rb = *(const uint4*)bsrc;

    const uint32_t sAB = smem_u32(sA);
    const uint32_t sBhiB = smem_u32(sBhi), sBloB = smem_u32(sBlo);

    for (int ch = 0; ch < 16; ch++) {
        *(uint4*)(&sA[ar * A2STR + ak])     = ra0;
        *(uint4*)(&sA[ar * A2STR + ak + 8]) = ra1;
        __half* bdst = (bhi_role ? sBhi : sBlo) + bk * B2STR + bseg;
        *(uint4*)bdst = rb;
        __syncthreads();
        if (ch < 15) {
            const __half* an = abase + (ch + 1) * 32;
            ra0 = *(const uint4*)(an);
            ra1 = *(const uint4*)(an + 8);
            rb = *(const uint4*)(bsrc + (size_t)(ch + 1) * 32 * C2);
        }
#pragma unroll
        for (int ks = 0; ks < 2; ks++) {
            uint32_t av[4];
            int row = warpM + (lane & 15);
            int col = ks * 16 + (lane >> 4) * 8;
            uint32_t offA = (uint32_t)(row * A2STR + col) * 2;
            ldsm_x4(sAB + offA, av[0], av[1], av[2], av[3]);
            uint32_t bh[4][2], bl[4][2];
            int krow = ks * 16 + (lane & 15);
#pragma unroll
            for (int np = 0; np < 2; np++) {
                int bcol = np * 16 + (lane >> 4) * 8;
                uint32_t offB = (uint32_t)(krow * B2STR + bcol) * 2;
                ldsm_x4_trans(sBhiB + offB, bh[np * 2][0], bh[np * 2][1],
                              bh[np * 2 + 1][0], bh[np * 2 + 1][1]);
                ldsm_x4_trans(sBloB + offB, bl[np * 2][0], bl[np * 2][1],
                              bl[np * 2 + 1][0], bl[np * 2 + 1][1]);
            }
#pragma unroll
            for (int ni = 0; ni < 4; ni++) {
                mma_f16(acc[ni], av, bh[ni]);
                mma_f16(acc[ni], av, bl[ni]);
            }
        }
        __syncthreads();
    }

    int row0 = mBase + warpM + (lane >> 2);
    int row1 = row0 + 8;
    float rs0 = 0.f, rd0 = 0.f, rs1 = 0.f, rd1 = 0.f;
#pragma unroll
    for (int ni = 0; ni < 4; ni++) {
        int col = ni * 8 + (lane & 3) * 2;
        if (row0 < nodeEnd)
            *(__half2*)(&g_xl2h[(size_t)row0 * C2 + col]) =
                __floats2half2_rn(acc[ni][0], acc[ni][1]);
        if (row1 < nodeEnd)
            *(__half2*)(&g_xl2h[(size_t)row1 * C2 + col]) =
                __floats2half2_rn(acc[ni][2], acc[ni][3]);
        float s0 = __ldg(&attS2[col]), s1 = __ldg(&attS2[col + 1]);
        float d0 = __ldg(&attD2[col]), d1 = __ldg(&attD2[col + 1]);
        rs0 = fmaf(acc[ni][0], s0, fmaf(acc[ni][1], s1, rs0));
        rd0 = fmaf(acc[ni][0], d0, fmaf(acc[ni][1], d1, rd0));
        rs1 = fmaf(acc[ni][2], s0, fmaf(acc[ni][3], s1, rs1));
        rd1 = fmaf(acc[ni][2], d0, fmaf(acc[ni][3], d1, rd1));
    }
#pragma unroll
    for (int off = 1; off <= 2; off <<= 1) {
        rs0 += __shfl_xor_sync(0xffffffffu, rs0, off);
        rd0 += __shfl_xor_sync(0xffffffffu, rd0, off);
        rs1 += __shfl_xor_sync(0xffffffffu, rs1, off);
        rd1 += __shfl_xor_sync(0xffffffffu, rd1, off);
    }
    if ((lane & 3) == 0) {
        if (row0 < nodeEnd) { g_as2[row0] = rs0; g_ad2[row0] = rd0; }
        if (row1 < nodeEnd) { g_as2[row1] = rs1; g_ad2[row1] = rd1; }
    }
}

// ---- layer-2 fused softmax+aggregation + fc head: warp per node --------------
__global__ void __launch_bounds__(256) agg2_kernel(const float* __restrict__ b2,
                                                   const float* __restrict__ fcW,
                                                   const float* __restrict__ fcb,
                                                   float* __restrict__ out) {
    __shared__ float fs[C2 * OUT_DIM];
    __shared__ float fb[OUT_DIM];
    for (int i = threadIdx.x; i < C2 * OUT_DIM; i += 256) fs[i] = fcW[i];
    if (threadIdx.x < OUT_DIM) fb[threadIdx.x] = fcb[threadIdx.x];
    __syncthreads();

    int w = (blockIdx.x * blockDim.x + threadIdx.x) >> 5;
    int lane = threadIdx.x & 31;
    if (w >= NN) return;
    float ad = g_ad2[w];
    float pself = __expf(lrelu(g_as2[w] + ad));
    float acc = pself * __half2float(g_xl2h[(size_t)w * C2 + lane]);
    float dacc = 0.f;
    int beg = g_rowptr[w], end = g_rowptr[w + 1];
    for (int j0 = beg; j0 < end; j0 += 32) {
        int j = j0 + lane;
        bool valid = j < end;
        int s_l = valid ? g_csrc[j] : 0;
        float p_l = 0.f;
        if (valid) p_l = __expf(lrelu(__ldg(&g_as2[s_l]) + ad));
        dacc += p_l;
        int cnt = end - j0;
        if (cnt > 32) cnt = 32;
        for (int t = 0; t < cnt; t++) {
            float p = __shfl_sync(0xffffffffu, p_l, t);
            int   s = __shfl_sync(0xffffffffu, s_l, t);
            acc = fmaf(p, __half2float(g_xl2h[(size_t)s * C2 + lane]), acc);
        }
    }
#pragma unroll
    for (int off = 16; off; off >>= 1) dacc += __shfl_xor_sync(0xffffffffu, dacc, off);
    float inv = 1.f / (dacc + pself + 1e-16f);
    float emb = fmaxf(fmaf(acc, inv, b2[lane]), 0.f);
    out[(size_t)w * C2 + lane] = emb;

    float l1 = fb[lane];
    float l2 = (lane < OUT_DIM - 32) ? fb[32 + lane] : 0.f;
#pragma unroll
    for (int c = 0; c < C2; c++) {
        float e = __shfl_sync(0xffffffffu, emb, c);
        l1 = fmaf(e, fs[c * OUT_DIM + lane], l1);
        if (lane < OUT_DIM - 32) l2 = fmaf(e, fs[c * OUT_DIM + 32 + lane], l2);
    }
    float* lg = out + (size_t)NN * C2 + (size_t)w * OUT_DIM;
    lg[lane] = l1;
    if (lane < OUT_DIM - 32) lg[32 + lane] = l2;
}

// ------------------------------------------------------------------------------
extern "C" void kernel_launch(void* const* d_in, const int* in_sizes, int n_in,
                              void* d_out, int out_size) {
    const float* x     = (const float*)d_in[0];
    const int*   ei    = (const int*)  d_in[1];
    const float* W1    = (const float*)d_in[2];
    const float* attS1 = (const float*)d_in[3];
    const float* attD1 = (const float*)d_in[4];
    const float* b1    = (const float*)d_in[5];
    const float* W2    = (const float*)d_in[6];
    const float* attS2 = (const float*)d_in[7];
    const float* attD2 = (const float*)d_in[8];
    const float* b2    = (const float*)d_in[9];
    const float* fcW   = (const float*)d_in[10];
    const float* fcb   = (const float*)d_in[11];
    float* out = (float*)d_out;

    const int* src = ei;
    const int* dst = ei + EE;

    // fixed auxiliary stream + events (created once; same captured DAG each call)
    static cudaStream_t sB = [] { cudaStream_t s; cudaStreamCreateWithFlags(&s, cudaStreamNonBlocking); return s; }();
    static cudaEvent_t evFork = [] { cudaEvent_t e; cudaEventCreateWithFlags(&e, cudaEventDisableTiming); return e; }();
    static cudaEvent_t evCSR  = [] { cudaEvent_t e; cudaEventCreateWithFlags(&e, cudaEventDisableTiming); return e; }();
    static cudaEvent_t evG1   = [] { cudaEvent_t e; cudaEventCreateWithFlags(&e, cudaEventDisableTiming); return e; }();
    static cudaEvent_t evHi   = [] { cudaEvent_t e; cudaEventCreateWithFlags(&e, cudaEventDisableTiming); return e; }();

    cudaFuncSetAttribute(gemm1_mma_kernel, cudaFuncAttributeMaxDynamicSharedMemorySize,
                         GEMM1_SMEM);

    // ---- fork: CSR chain + w2 split on stream B, shadowed by gemm1 ----
    cudaEventRecord(evFork, 0);
    cudaStreamWaitEvent(sB, evFork, 0);

    void* degp = nullptr;
    cudaGetSymbolAddress(&degp, g_deg);
    cudaMemsetAsync(degp, 0, NN * sizeof(int), sB);
    hist_kernel<<<(EE + 255) / 256, 256, 0, sB>>>(dst);
    scanA_kernel<<<SCAN_BLOCKS, 1024, 0, sB>>>();
    scanB_kernel<<<1, 64, 0, sB>>>();
    scanC_kernel<<<SCAN_BLOCKS, 1024, 0, sB>>>();
    scatter_kernel<<<(EE + 255) / 256, 256, 0, sB>>>(src, dst);
    split_w2_kernel<<<(HC1 * C2 / 4 + 255) / 256, 256, 0, sB>>>(W2);
    cudaEventRecord(evCSR, sB);

    // ---- main stream: merged split + gemm1 ----
    split_xw_kernel<<<(NXC + NWC + 255) / 256, 256>>>(x, W1);
    {
        dim3 grid((NN + 127) / 128, HC1 / 128);
        gemm1_mma_kernel<<<grid, 256, GEMM1_SMEM>>>(attS1, attD1);
    }
    cudaEventRecord(evG1, 0);

    // ---- layer 1 agg + layer 2 gemm, pipelined in node halves ----
    cudaStreamWaitEvent(0, evCSR, 0);
    agg1_kernel<<<(NHALF * 32 + 255) / 256, 256>>>(b1, 0, NHALF);
    gemm2_mma_kernel<<<NHALF / 128, 256>>>(attS2, attD2, 0, NHALF);

    cudaStreamWaitEvent(sB, evG1, 0);
    agg1_kernel<<<((NN - NHALF) * 32 + 255) / 256, 256, 0, sB>>>(b1, NHALF, NN);
    gemm2_mma_kernel<<<(NN - NHALF + 127) / 128, 256, 0, sB>>>(attS2, attD2, NHALF, NN);
    cudaEventRecord(evHi, sB);

    // ---- join, then layer-2 agg + fused fc head ----
    cudaStreamWaitEvent(0, evHi, 0);
    agg2_kernel<<<(NN * 32 + 255) / 256, 256>>>(b2, fcW, fcb, out);
}